// round 5
// baseline (speedup 1.0000x reference)
#include <cuda_runtime.h>
#include <math.h>
#include <cstdint>

#define BB 4
#define CC 128
#define NNp 4096
#define TW 132
typedef unsigned long long ull;
typedef unsigned int uint32;

__device__ float g_x1[BB*CC*NNp];
__device__ float g_xf[BB*CC*NNp];
__device__ float g_XH[BB*NNp*CC];     // [b][n][c] hi (tf32-exact)
__device__ float g_XL[BB*NNp*CC];     // [b][n][c] lo (tf32-exact)
__device__ float g_sq[BB*NNp];
__device__ int   g_idx[BB*NNp*9];
__device__ float g_PC[4*BB*NNp*CC];   // [slot][b][n][o]
__device__ float g_h[BB*NNp*3*CC];    // [b][n][j][o]
__device__ float g_W4[4*CC*CC];
__device__ float g_Wl2[CC*3*CC];
__device__ float g_g0[BB*CC];
__device__ float g_g2[BB*CC];

// ===================== f32x2 GEMM helpers (non-KNN kernels) =================
__device__ __forceinline__ ull pack2(float a){
    ull r; unsigned ai=__float_as_uint(a);
    asm("mov.b64 %0, {%1, %2};" : "=l"(r) : "r"(ai), "r"(ai));
    return r;
}
__device__ __forceinline__ void fma2(ull &d, ull a, ull b){
    asm("fma.rn.f32x2 %0, %1, %2, %0;" : "+l"(d) : "l"(a), "l"(b));
}
__device__ __forceinline__ float2 unp(ull v){ union{ull u; float2 f;}c; c.u=v; return c.f; }

__device__ __forceinline__ void micro_step(const float* As, const float* Bs,
                                           int k, int r0, int c0, ull acc[8][4]){
    const float* ar = As + k*TW; const float* br = Bs + k*TW;
    float4 a0 = *(const float4*)(ar+r0);
    float4 a1 = *(const float4*)(ar+r0+64);
    ulonglong2 b0 = *(const ulonglong2*)(br+c0);
    ulonglong2 b1 = *(const ulonglong2*)(br+c0+64);
    ull av[8]={pack2(a0.x),pack2(a0.y),pack2(a0.z),pack2(a0.w),
               pack2(a1.x),pack2(a1.y),pack2(a1.z),pack2(a1.w)};
    ull bv[4]={b0.x,b0.y,b1.x,b1.y};
#pragma unroll
    for (int i=0;i<8;i++)
#pragma unroll
        for (int j=0;j<4;j++) fma2(acc[i][j], av[i], bv[j]);
}

// ===================== mma.sync helpers =====================================
__device__ __forceinline__ uint32 smem_u32(const void* p){
    uint32 a;
    asm("{ .reg .u64 t; cvta.to.shared.u64 t, %1; cvt.u32.u64 %0, t; }" : "=r"(a) : "l"(p));
    return a;
}
__device__ __forceinline__ void cpa16(uint32 dst, const void* src){
    asm volatile("cp.async.ca.shared.global [%0], [%1], 16;" :: "r"(dst), "l"(src));
}
#define CP_COMMIT() asm volatile("cp.async.commit_group;" ::: "memory")
#define CP_WAIT0()  asm volatile("cp.async.wait_group 0;" ::: "memory")

__device__ __forceinline__ void mma8(float* d, const uint32* a, uint32 b0, uint32 b1){
    asm volatile("mma.sync.aligned.m16n8k8.row.col.f32.tf32.tf32.f32 "
        "{%0,%1,%2,%3},{%4,%5,%6,%7},{%8,%9},{%0,%1,%2,%3};"
        : "+f"(d[0]),"+f"(d[1]),"+f"(d[2]),"+f"(d[3])
        : "r"(a[0]),"r"(a[1]),"r"(a[2]),"r"(a[3]), "r"(b0),"r"(b1));
}
// swizzled word offset for row-major [row][128] tile, conflict-free frag loads
__device__ __forceinline__ int swz(int r, int k){
    return (r<<7) + (k ^ ((r&7)<<2));
}

// ===================== weight prep ==========================================
__global__ void prep_kernel(const float* __restrict__ wl1, const float* __restrict__ wl2){
    for (int i = blockIdx.x*256 + threadIdx.x; i < 4*CC*CC; i += gridDim.x*256){
        int slot=i>>14, rem=i&16383, o=rem>>7, c=rem&127;
        float v;
        if (slot==0){
            v=0.f;
#pragma unroll
            for (int w=0;w<3;w++) v += wl1[(o*256+c)*3+w] + wl1[(o*256+128+c)*3+w];
        } else v = wl1[(o*256+128+c)*3+(slot-1)];
        g_W4[i]=v;
    }
    for (int i = blockIdx.x*256 + threadIdx.x; i < CC*3*CC; i += gridDim.x*256){
        int p=i/384, k=i%384, w=k>>7, o=k&127;
        g_Wl2[i] = wl2[(p*128+o)*3+w];
    }
}

// ===================== pointwise conv =======================================
__global__ void __launch_bounds__(256) pw_gemm(const float* __restrict__ X,
        const float* __restrict__ W, const float* __restrict__ bias,
        const float* __restrict__ sc, const float* __restrict__ tr_,
        float* __restrict__ out){
    __shared__ float As[16*TW], Bs[16*TW];
    int b=blockIdx.y, n0=blockIdx.x*128, tid=threadIdx.x;
    const float* Xb = X + (size_t)b*CC*NNp;
    int tr=tid>>4, tc=tid&15, r0=tr*4, c0=tc*4;
    ull acc[8][4];
#pragma unroll
    for(int i=0;i<8;i++)
#pragma unroll
        for(int j=0;j<4;j++) acc[i][j]=0ULL;
    for (int kk=0; kk<128; kk+=16){
        for (int i=tid;i<512;i+=256){
            int m=i>>2, k4=(i&3)*4;
            float4 v = *(const float4*)(W + m*128 + kk + k4);
            As[(k4+0)*TW+m]=v.x; As[(k4+1)*TW+m]=v.y; As[(k4+2)*TW+m]=v.z; As[(k4+3)*TW+m]=v.w;
        }
        for (int i=tid;i<512;i+=256){
            int k=i>>5, n4=(i&31)*4;
            *(float4*)&Bs[k*TW+n4] = *(const float4*)(Xb + (size_t)(kk+k)*NNp + n0 + n4);
        }
        __syncthreads();
#pragma unroll
        for (int k=0;k<16;k++) micro_step(As,Bs,k,r0,c0,acc);
        __syncthreads();
    }
#pragma unroll
    for (int i=0;i<8;i++){
        int row = (i<4)? r0+i : r0+60+i;
        float bb=bias[row], ss=sc[row], tt=tr_[row];
        float* orow = out + ((size_t)b*CC+row)*NNp + n0;
#pragma unroll
        for (int j=0;j<4;j++){
            int cj = (j<2)? c0+2*j : c0+60+2*j;
            float2 v=unp(acc[i][j]);
            float2 o; o.x=fmaxf(ss*(v.x+bb)+tt,0.f); o.y=fmaxf(ss*(v.y+bb)+tt,0.f);
            *(float2*)(orow+cj)=o;
        }
    }
}

__global__ void sq_kernel(const float* __restrict__ XF, float* __restrict__ SQ){
    int n=blockIdx.x*256+threadIdx.x, b=blockIdx.y;
    const float* p = XF + (size_t)b*CC*NNp + n;
    float s=0.f;
#pragma unroll 8
    for (int c=0;c<128;c++){ float v=p[(size_t)c*NNp]; s+=v*v; }
    SQ[b*NNp+n]=s;
}

// ===================== transpose + tf32 hi/lo split =========================
__global__ void split_kernel(const float* __restrict__ XF,
        float* __restrict__ XH, float* __restrict__ XL){
    __shared__ float t[32][33];
    int b = blockIdx.z, c0 = blockIdx.y*32, n0 = blockIdx.x*32;
    int tx = threadIdx.x, ty = threadIdx.y;  // 32 x 8
    const float* src = XF + ((size_t)b*CC + c0)*NNp + n0;
#pragma unroll
    for (int j=0;j<4;j++) t[ty*4+j][tx] = src[(size_t)(ty*4+j)*NNp + tx];
    __syncthreads();
#pragma unroll
    for (int j=0;j<4;j++){
        int n = ty*4+j;
        float v = t[tx][n];
        float hi = __uint_as_float(__float_as_uint(v) & 0xffffe000u);
        float lo = v - hi;
        lo = __uint_as_float(__float_as_uint(lo) & 0xffffe000u);  // tf32-exact
        size_t o = ((size_t)b*NNp + n0 + n)*CC + c0 + tx;
        XH[o] = hi; XL[o] = lo;
    }
}

// ===================== mma.sync fused Gram + top-9 KNN ======================
// smem(float): Qh[16384] Ql[16384] Cb[16384] sqs[128]  = 197120 B
#define INS(L, val, jg) do{ \
  if ((val)>tv##L[8] || ((val)==tv##L[8] && (jg)<ti##L[8])){ \
    tv##L[8]=(val); ti##L[8]=(jg); \
    _Pragma("unroll") for (int p_=8;p_>0;--p_){ \
      bool sw_=(tv##L[p_]>tv##L[p_-1])||(tv##L[p_]==tv##L[p_-1]&&ti##L[p_]<ti##L[p_-1]); \
      if (sw_){ float fv_=tv##L[p_];tv##L[p_]=tv##L[p_-1];tv##L[p_-1]=fv_; \
               int iv_=ti##L[p_];ti##L[p_]=ti##L[p_-1];ti##L[p_-1]=iv_; } } } }while(0)

#define PASS(QB) do{ \
  _Pragma("unroll") for (int ks=0;ks<16;ks++){ \
    uint32 afr[2][4]; \
    _Pragma("unroll") for (int mt=0;mt<2;mt++){ \
      int r0_ = mg*32 + mt*16 + gID; \
      int kk_ = ks*8 + tig; \
      afr[mt][0]=__float_as_uint((QB)[swz(r0_,kk_)]); \
      afr[mt][1]=__float_as_uint((QB)[swz(r0_+8,kk_)]); \
      afr[mt][2]=__float_as_uint((QB)[swz(r0_,kk_+4)]); \
      afr[mt][3]=__float_as_uint((QB)[swz(r0_+8,kk_+4)]); } \
    _Pragma("unroll") for (int t=0;t<8;t++){ \
      int rc_ = ng*64 + t*8 + gID; \
      int kk_ = ks*8 + tig; \
      uint32 b0_=__float_as_uint(Cb[swz(rc_,kk_)]); \
      uint32 b1_=__float_as_uint(Cb[swz(rc_,kk_+4)]); \
      mma8(acc[0][t], afr[0], b0_, b1_); \
      mma8(acc[1][t], afr[1], b0_, b1_); } } }while(0)

extern __shared__ float kms[];
__global__ void __launch_bounds__(256,1) knn_mma(
        const float* __restrict__ XH, const float* __restrict__ XL,
        const float* __restrict__ SQ, int* __restrict__ IDX){
    float* Qh = kms;
    float* Ql = kms + 16384;
    float* Cb = kms + 32768;
    float* sqs= kms + 49152;
    uint32 smb = smem_u32(kms);
    int tid=threadIdx.x, lane=tid&31, wid=tid>>5;
    int b=blockIdx.y, q0=blockIdx.x*128;
    int mg=wid>>1, ng=wid&1, gID=lane>>2, tig=lane&3;
    const float* XHb = XH + (size_t)b*NNp*CC;
    const float* XLb = XL + (size_t)b*NNp*CC;

    // load Q hi+lo (swizzled)
#pragma unroll
    for (int j=0;j<16;j++){
        int idx = tid + 256*j;
        int r = idx>>5, k4 = (idx&31)*4;
        int w = swz(r, k4);
        cpa16(smb + (uint32)w*4u,         XHb + (size_t)(q0+r)*CC + k4);
        cpa16(smb + 65536u + (uint32)w*4u, XLb + (size_t)(q0+r)*CC + k4);
    }
    CP_COMMIT();

    float acc[2][8][4];
#pragma unroll
    for (int mt=0;mt<2;mt++)
#pragma unroll
        for (int t=0;t<8;t++)
#pragma unroll
            for (int c=0;c<4;c++) acc[mt][t][c]=0.f;

    const float NEGINF = __int_as_float(0xff800000);
    float tv0[9],tv1[9],tv2[9],tv3[9]; int ti0[9],ti1[9],ti2[9],ti3[9];
#pragma unroll
    for (int k=0;k<9;k++){
        tv0[k]=tv1[k]=tv2[k]=tv3[k]=NEGINF;
        ti0[k]=ti1[k]=ti2[k]=ti3[k]=0x7fffffff;
    }

    for (int ct=0; ct<32; ct++){
        __syncthreads();   // prior tile's pass3/selection done with Cb/sqs
        // load Ch + sq tile
#pragma unroll
        for (int j=0;j<16;j++){
            int idx = tid + 256*j;
            int r = idx>>5, k4 = (idx&31)*4;
            cpa16(smb + 131072u + (uint32)swz(r,k4)*4u,
                  XHb + (size_t)(ct*128+r)*CC + k4);
        }
        if (tid < 32)
            *(float4*)(sqs + tid*4) = *(const float4*)(SQ + (size_t)b*NNp + ct*128 + tid*4);
        CP_COMMIT(); CP_WAIT0();
        __syncthreads();

        PASS(Qh);          // hi·hi
        PASS(Ql);          // lo·hi
        __syncthreads();   // done reading Ch
        // load Cl
#pragma unroll
        for (int j=0;j<16;j++){
            int idx = tid + 256*j;
            int r = idx>>5, k4 = (idx&31)*4;
            cpa16(smb + 131072u + (uint32)swz(r,k4)*4u,
                  XLb + (size_t)(ct*128+r)*CC + k4);
        }
        CP_COMMIT(); CP_WAIT0();
        __syncthreads();

        PASS(Qh);          // hi·lo

        // selection from accumulators
#pragma unroll
        for (int mt=0;mt<2;mt++)
#pragma unroll
        for (int t=0;t<8;t++){
            float2 s2 = *(float2*)(sqs + ng*64 + t*8 + 2*tig);
            int jg = ct*128 + ng*64 + t*8 + 2*tig;
            float k0 = acc[mt][t][0] - 0.5f*s2.x;
            float k1 = acc[mt][t][1] - 0.5f*s2.y;
            float k2 = acc[mt][t][2] - 0.5f*s2.x;
            float k3 = acc[mt][t][3] - 0.5f*s2.y;
            if (mt==0){ INS(0,k0,jg); INS(0,k1,jg+1); INS(1,k2,jg); INS(1,k3,jg+1); }
            else      { INS(2,k0,jg); INS(2,k1,jg+1); INS(3,k2,jg); INS(3,k3,jg+1); }
            acc[mt][t][0]=0.f; acc[mt][t][1]=0.f; acc[mt][t][2]=0.f; acc[mt][t][3]=0.f;
        }
    }
    __syncthreads();

    // write per-thread lists: row r, slot s = ng*4+tig
    float* LV = kms;                 // 128*72 floats
    int*   LI = (int*)(kms + 9216);
#pragma unroll
    for (int l=0;l<4;l++){
        int mt=l>>1, h=l&1;
        int r = mg*32 + mt*16 + 8*h + gID;
        int base = r*72 + (ng*4+tig)*9;
        const float* tvp = (l==0)?tv0:(l==1)?tv1:(l==2)?tv2:tv3;
        const int*   tip = (l==0)?ti0:(l==1)?ti1:(l==2)?ti2:ti3;
#pragma unroll
        for (int k=0;k<9;k++){ LV[base+k]=tvp[k]; LI[base+k]=tip[k]; }
    }
    __syncthreads();
    if (tid < 128){
        int head[8]={0,0,0,0,0,0,0,0};
        const float* lv = LV + tid*72;
        const int*   li = LI + tid*72;
        int* dst = IDX + ((size_t)b*NNp + q0 + tid)*9;
#pragma unroll
        for (int k=0;k<9;k++){
            float bv = NEGINF; int bi = 0x7fffffff; int bs = 0;
#pragma unroll
            for (int s=0;s<8;s++){
                int p = head[s];
                float v = lv[s*9+p]; int ix = li[s*9+p];
                if (v>bv || (v==bv && ix<bi)){ bv=v; bi=ix; bs=s; }
            }
            head[bs]++;
            dst[k]=bi;
        }
    }
}

// ===================== per-tap GEMMs ========================================
__global__ void __launch_bounds__(256) pc_gemm(const float* __restrict__ X,
        const float* __restrict__ W4, float* __restrict__ out){
    __shared__ float As[16*TW], Bs[16*TW];
    int slot=blockIdx.z, b=blockIdx.y, n0=blockIdx.x*128, tid=threadIdx.x;
    const float* Xb = X + (size_t)b*CC*NNp;
    const float* Wd = W4 + (size_t)slot*CC*CC;
    int tr=tid>>4, tc=tid&15, r0=tr*4, c0=tc*4;
    ull acc[8][4];
#pragma unroll
    for(int i=0;i<8;i++)
#pragma unroll
        for(int j=0;j<4;j++) acc[i][j]=0ULL;
    for (int kk=0; kk<128; kk+=16){
        for (int i=tid;i<512;i+=256){
            int k=i>>5, n4=(i&31)*4;
            *(float4*)&As[k*TW+n4] = *(const float4*)(Xb + (size_t)(kk+k)*NNp + n0 + n4);
        }
        for (int i=tid;i<512;i+=256){
            int m=i>>2, k4=(i&3)*4;
            float4 v = *(const float4*)(Wd + m*128 + kk + k4);
            Bs[(k4+0)*TW+m]=v.x; Bs[(k4+1)*TW+m]=v.y; Bs[(k4+2)*TW+m]=v.z; Bs[(k4+3)*TW+m]=v.w;
        }
        __syncthreads();
#pragma unroll
        for (int k=0;k<16;k++) micro_step(As,Bs,k,r0,c0,acc);
        __syncthreads();
    }
    float* obase = out + (((size_t)slot*BB+b)*NNp + n0)*128;
#pragma unroll
    for (int i=0;i<8;i++){
        int row=(i<4)? r0+i : r0+60+i;
#pragma unroll
        for (int j=0;j<4;j++){
            int cj=(j<2)? c0+2*j : c0+60+2*j;
            *(float2*)(obase + (size_t)row*128 + cj) = unp(acc[i][j]);
        }
    }
}

// ===================== gather + edge-conv epilogue ==========================
__global__ void __launch_bounds__(256) gather_kernel(const float* __restrict__ PC,
        const int* __restrict__ IDX, const float* __restrict__ b_l1,
        const float* __restrict__ s_l1, const float* __restrict__ t_l1,
        float* __restrict__ H){
    int b=blockIdx.y;
    int o=threadIdx.x&127, sub=threadIdx.x>>7;
    float bb=b_l1[o], ss=s_l1[o], tt=t_l1[o];
    const float* P0 = PC + ((size_t)0*BB+b)*NNp*128;
    const float* P1 = PC + ((size_t)1*BB+b)*NNp*128;
    const float* P2 = PC + ((size_t)2*BB+b)*NNp*128;
    const float* P3 = PC + ((size_t)3*BB+b)*NNp*128;
    for (int it=0; it<4; it++){
        int n = blockIdx.x*8 + it*2 + sub;
        const int* id = IDX + ((size_t)b*NNp+n)*9;
        float c0v = P0[(size_t)n*128+o];
#pragma unroll
        for (int j=0;j<3;j++){
            int i0=id[3*j], i1=id[3*j+1], i2=id[3*j+2];
            float v = c0v - P1[(size_t)i0*128+o] - P2[(size_t)i1*128+o] - P3[(size_t)i2*128+o];
            H[(((size_t)b*NNp+n)*3+j)*128+o] = fmaxf(ss*(v+bb)+tt,0.f);
        }
    }
}

// ===================== global branch ========================================
__global__ void mean_kernel(const float* __restrict__ x1, float* __restrict__ g0){
    int c=blockIdx.x, b=blockIdx.y;
    const float* p = x1 + ((size_t)b*CC+c)*NNp;
    float s=0.f;
    for (int i=threadIdx.x;i<NNp;i+=256) s+=p[i];
    __shared__ float sm[8];
    for (int o=16;o;o>>=1) s+=__shfl_down_sync(~0u,s,o);
    if ((threadIdx.x&31)==0) sm[threadIdx.x>>5]=s;
    __syncthreads();
    if (threadIdx.x<8){
        s=sm[threadIdx.x];
        for (int o=4;o;o>>=1) s+=__shfl_down_sync(0xffu,s,o);
        if (threadIdx.x==0) g0[b*CC+c]=s*(1.f/NNp);
    }
}
__global__ void glob_kernel(const float* __restrict__ g0,
        const float* __restrict__ wg1,const float* __restrict__ bg1,
        const float* __restrict__ sg1,const float* __restrict__ tg1,
        const float* __restrict__ wg2,const float* __restrict__ bg2,
        const float* __restrict__ sg2,const float* __restrict__ tg2,
        float* __restrict__ g2){
    __shared__ float s0[128], s1[32];
    int b=blockIdx.x, t=threadIdx.x;
    s0[t]=g0[b*128+t]; __syncthreads();
    if (t<32){
        float a=0.f;
        for (int c=0;c<128;c++) a+=s0[c]*wg1[t*128+c];
        s1[t]=fmaxf(sg1[t]*(a+bg1[t])+tg1[t],0.f);
    }
    __syncthreads();
    float a=0.f;
    for (int i=0;i<32;i++) a+=s1[i]*wg2[t*32+i];
    g2[b*128+t]=sg2[t]*(a+bg2[t])+tg2[t];
}

// ===================== h2 GEMM + sigmoid ====================================
__global__ void __launch_bounds__(256) h2_gemm(const float* __restrict__ H,
        const float* __restrict__ Wl2, const float* __restrict__ bl2,
        const float* __restrict__ sl2, const float* __restrict__ tl2,
        const float* __restrict__ g2, float* __restrict__ out){
    __shared__ float As[16*TW], Bs[16*TW];
    int b=blockIdx.y, n0=blockIdx.x*128, tid=threadIdx.x;
    const float* Hb = H + ((size_t)b*NNp+n0)*384;
    int tr=tid>>4, tc=tid&15, r0=tr*4, c0=tc*4;
    ull acc[8][4];
#pragma unroll
    for(int i=0;i<8;i++)
#pragma unroll
        for(int j=0;j<4;j++) acc[i][j]=0ULL;
    for (int kk=0; kk<384; kk+=16){
        for (int i=tid;i<512;i+=256){
            int m=i>>2, k4=(i&3)*4;
            float4 v = *(const float4*)(Wl2 + m*384 + kk + k4);
            As[(k4+0)*TW+m]=v.x; As[(k4+1)*TW+m]=v.y; As[(k4+2)*TW+m]=v.z; As[(k4+3)*TW+m]=v.w;
        }
        for (int i=tid;i<512;i+=256){
            int n=i>>2, k4=(i&3)*4;
            float4 v = *(const float4*)(Hb + (size_t)n*384 + kk + k4);
            Bs[(k4+0)*TW+n]=v.x; Bs[(k4+1)*TW+n]=v.y; Bs[(k4+2)*TW+n]=v.z; Bs[(k4+3)*TW+n]=v.w;
        }
        __syncthreads();
#pragma unroll
        for (int k=0;k<16;k++) micro_step(As,Bs,k,r0,c0,acc);
        __syncthreads();
    }
#pragma unroll
    for (int i=0;i<8;i++){
        int p=(i<4)? r0+i : r0+60+i;
        float bb=bl2[p], ss=sl2[p], tt=tl2[p], gg=g2[b*128+p];
        float* orow = out + ((size_t)b*CC+p)*NNp + n0;
#pragma unroll
        for (int j=0;j<4;j++){
            int cj=(j<2)? c0+2*j : c0+60+2*j;
            float2 v=unp(acc[i][j]);
            float l0=fmaxf(ss*(v.x+bb)+tt,0.f);
            float l1=fmaxf(ss*(v.y+bb)+tt,0.f);
            float2 o;
            o.x = 1.f/(1.f+__expf(-(gg+l0)));
            o.y = 1.f/(1.f+__expf(-(gg+l1)));
            *(float2*)(orow+cj)=o;
        }
    }
}

extern "C" void kernel_launch(void* const* d_in, const int* in_sizes, int n_in,
                              void* d_out, int out_size){
    const float* x    = (const float*)d_in[0];
    const float* w_be = (const float*)d_in[1];
    const float* b_be = (const float*)d_in[2];
    const float* s_be = (const float*)d_in[3];
    const float* t_be = (const float*)d_in[4];
    const float* w_kn = (const float*)d_in[5];
    const float* b_kn = (const float*)d_in[6];
    const float* s_kn = (const float*)d_in[7];
    const float* t_kn = (const float*)d_in[8];
    const float* w_g1 = (const float*)d_in[9];
    const float* b_g1 = (const float*)d_in[10];
    const float* s_g1 = (const float*)d_in[11];
    const float* t_g1 = (const float*)d_in[12];
    const float* w_g2 = (const float*)d_in[13];
    const float* b_g2 = (const float*)d_in[14];
    const float* s_g2 = (const float*)d_in[15];
    const float* t_g2 = (const float*)d_in[16];
    const float* w_l1 = (const float*)d_in[17];
    const float* b_l1 = (const float*)d_in[18];
    const float* s_l1 = (const float*)d_in[19];
    const float* t_l1 = (const float*)d_in[20];
    const float* w_l2 = (const float*)d_in[21];
    const float* b_l2 = (const float*)d_in[22];
    const float* s_l2 = (const float*)d_in[23];
    const float* t_l2 = (const float*)d_in[24];
    float* out = (float*)d_out;

    float *x1, *xf, *XH, *XL, *sq, *PC, *H, *g0, *g2, *W4, *Wl2; int* idx;
    cudaGetSymbolAddress((void**)&x1, g_x1);
    cudaGetSymbolAddress((void**)&xf, g_xf);
    cudaGetSymbolAddress((void**)&XH, g_XH);
    cudaGetSymbolAddress((void**)&XL, g_XL);
    cudaGetSymbolAddress((void**)&sq, g_sq);
    cudaGetSymbolAddress((void**)&idx, g_idx);
    cudaGetSymbolAddress((void**)&PC, g_PC);
    cudaGetSymbolAddress((void**)&H, g_h);
    cudaGetSymbolAddress((void**)&W4, g_W4);
    cudaGetSymbolAddress((void**)&Wl2, g_Wl2);
    cudaGetSymbolAddress((void**)&g0, g_g0);
    cudaGetSymbolAddress((void**)&g2, g_g2);

    const int knn_smem = (3*16384 + 128) * 4;   // 197120 B
    cudaFuncSetAttribute(knn_mma, cudaFuncAttributeMaxDynamicSharedMemorySize, knn_smem);

    prep_kernel<<<256,256>>>(w_l1, w_l2);
    pw_gemm<<<dim3(32,BB),256>>>(x,  w_be, b_be, s_be, t_be, x1);
    pw_gemm<<<dim3(32,BB),256>>>(x1, w_kn, b_kn, s_kn, t_kn, xf);
    sq_kernel<<<dim3(16,BB),256>>>(xf, sq);
    split_kernel<<<dim3(128,4,BB),dim3(32,8)>>>(xf, XH, XL);
    knn_mma<<<dim3(32,BB),256,knn_smem>>>(XH, XL, sq, idx);
    pc_gemm<<<dim3(32,BB,4),256>>>(xf, W4, PC);
    gather_kernel<<<dim3(512,BB),256>>>(PC, idx, b_l1, s_l1, t_l1, H);
    mean_kernel<<<dim3(128,BB),256>>>(x1, g0);
    glob_kernel<<<BB,128>>>(g0, w_g1,b_g1,s_g1,t_g1, w_g2,b_g2,s_g2,t_g2, g2);
    h2_gemm<<<dim3(32,BB),256>>>(H, Wl2, b_l2, s_l2, t_l2, g2, out);
}

// round 6
// speedup vs baseline: 1.5347x; 1.5347x over previous
#include <cuda_runtime.h>
#include <math.h>
#include <cstdint>

#define BB 4
#define CC 128
#define NNp 4096
#define TW 132
#define KS_TW 132
typedef unsigned long long ull;
typedef unsigned int uint32;

__device__ float g_x1[BB*CC*NNp];
__device__ float g_xf[BB*CC*NNp];
__device__ float g_sq[BB*NNp];
__device__ int   g_idx[BB*NNp*9];
__device__ float g_pv[BB*NNp*32*9];   // partial top-9 values [b][n][slot][9]
__device__ int   g_pi[BB*NNp*32*9];   // partial top-9 indices
__device__ float g_PC[4*BB*NNp*CC];   // [slot][b][n][o]
__device__ float g_h[BB*NNp*3*CC];    // [b][n][j][o]
__device__ float g_W4[4*CC*CC];
__device__ float g_Wl2[CC*3*CC];
__device__ float g_g0[BB*CC];
__device__ float g_g2[BB*CC];

// ===================== f32x2 helpers ========================================
__device__ __forceinline__ ull pack2(float a){
    ull r; unsigned ai=__float_as_uint(a);
    asm("mov.b64 %0, {%1, %2};" : "=l"(r) : "r"(ai), "r"(ai));
    return r;
}
__device__ __forceinline__ void fma2(ull &d, ull a, ull b){
    asm("fma.rn.f32x2 %0, %1, %2, %0;" : "+l"(d) : "l"(a), "l"(b));
}
__device__ __forceinline__ float2 unp(ull v){ union{ull u; float2 f;}c; c.u=v; return c.f; }

__device__ __forceinline__ void micro_step(const float* As, const float* Bs,
                                           int k, int r0, int c0, ull acc[8][4]){
    const float* ar = As + k*TW; const float* br = Bs + k*TW;
    float4 a0 = *(const float4*)(ar+r0);
    float4 a1 = *(const float4*)(ar+r0+64);
    ulonglong2 b0 = *(const ulonglong2*)(br+c0);
    ulonglong2 b1 = *(const ulonglong2*)(br+c0+64);
    ull av[8]={pack2(a0.x),pack2(a0.y),pack2(a0.z),pack2(a0.w),
               pack2(a1.x),pack2(a1.y),pack2(a1.z),pack2(a1.w)};
    ull bv[4]={b0.x,b0.y,b1.x,b1.y};
#pragma unroll
    for (int i=0;i<8;i++)
#pragma unroll
        for (int j=0;j<4;j++) fma2(acc[i][j], av[i], bv[j]);
}

__device__ __forceinline__ uint32 smem_u32(const void* p){
    uint32 a;
    asm("{ .reg .u64 t; cvta.to.shared.u64 t, %1; cvt.u32.u64 %0, t; }" : "=r"(a) : "l"(p));
    return a;
}
__device__ __forceinline__ void cpa16(uint32 dst, const void* src){
    asm volatile("cp.async.ca.shared.global [%0], [%1], 16;" :: "r"(dst), "l"(src));
}
#define CP_COMMIT() asm volatile("cp.async.commit_group;" ::: "memory")
#define CP_WAIT0()  asm volatile("cp.async.wait_group 0;" ::: "memory")

// exact top-9 insert: (value desc, index asc)
#define INS1(tv, tix, val, jg) do{ \
  if ((val)>(tv)[8] || ((val)==(tv)[8] && (jg)<(tix)[8])){ \
    (tv)[8]=(val); (tix)[8]=(jg); \
    _Pragma("unroll") for (int p_=8;p_>0;--p_){ \
      bool sw_=((tv)[p_]>(tv)[p_-1])||((tv)[p_]==(tv)[p_-1]&&(tix)[p_]<(tix)[p_-1]); \
      if (sw_){ float fv_=(tv)[p_];(tv)[p_]=(tv)[p_-1];(tv)[p_-1]=fv_; \
               int iv_=(tix)[p_];(tix)[p_]=(tix)[p_-1];(tix)[p_-1]=iv_; } } } }while(0)

// ===================== weight prep ==========================================
__global__ void prep_kernel(const float* __restrict__ wl1, const float* __restrict__ wl2){
    for (int i = blockIdx.x*256 + threadIdx.x; i < 4*CC*CC; i += gridDim.x*256){
        int slot=i>>14, rem=i&16383, o=rem>>7, c=rem&127;
        float v;
        if (slot==0){
            v=0.f;
#pragma unroll
            for (int w=0;w<3;w++) v += wl1[(o*256+c)*3+w] + wl1[(o*256+128+c)*3+w];
        } else v = wl1[(o*256+128+c)*3+(slot-1)];
        g_W4[i]=v;
    }
    for (int i = blockIdx.x*256 + threadIdx.x; i < CC*3*CC; i += gridDim.x*256){
        int p=i/384, k=i%384, w=k>>7, o=k&127;
        g_Wl2[i] = wl2[(p*128+o)*3+w];
    }
}

// ===================== pointwise conv =======================================
__global__ void __launch_bounds__(256) pw_gemm(const float* __restrict__ X,
        const float* __restrict__ W, const float* __restrict__ bias,
        const float* __restrict__ sc, const float* __restrict__ tr_,
        float* __restrict__ out){
    __shared__ float As[16*TW], Bs[16*TW];
    int b=blockIdx.y, n0=blockIdx.x*128, tid=threadIdx.x;
    const float* Xb = X + (size_t)b*CC*NNp;
    int tr=tid>>4, tc=tid&15, r0=tr*4, c0=tc*4;
    ull acc[8][4];
#pragma unroll
    for(int i=0;i<8;i++)
#pragma unroll
        for(int j=0;j<4;j++) acc[i][j]=0ULL;
    for (int kk=0; kk<128; kk+=16){
        for (int i=tid;i<512;i+=256){
            int m=i>>2, k4=(i&3)*4;
            float4 v = *(const float4*)(W + m*128 + kk + k4);
            As[(k4+0)*TW+m]=v.x; As[(k4+1)*TW+m]=v.y; As[(k4+2)*TW+m]=v.z; As[(k4+3)*TW+m]=v.w;
        }
        for (int i=tid;i<512;i+=256){
            int k=i>>5, n4=(i&31)*4;
            *(float4*)&Bs[k*TW+n4] = *(const float4*)(Xb + (size_t)(kk+k)*NNp + n0 + n4);
        }
        __syncthreads();
#pragma unroll
        for (int k=0;k<16;k++) micro_step(As,Bs,k,r0,c0,acc);
        __syncthreads();
    }
#pragma unroll
    for (int i=0;i<8;i++){
        int row = (i<4)? r0+i : r0+60+i;
        float bb=bias[row], ss=sc[row], tt=tr_[row];
        float* orow = out + ((size_t)b*CC+row)*NNp + n0;
#pragma unroll
        for (int j=0;j<4;j++){
            int cj = (j<2)? c0+2*j : c0+60+2*j;
            float2 v=unp(acc[i][j]);
            float2 o; o.x=fmaxf(ss*(v.x+bb)+tt,0.f); o.y=fmaxf(ss*(v.y+bb)+tt,0.f);
            *(float2*)(orow+cj)=o;
        }
    }
}

__global__ void sq_kernel(const float* __restrict__ XF, float* __restrict__ SQ){
    int n=blockIdx.x*256+threadIdx.x, b=blockIdx.y;
    const float* p = XF + (size_t)b*CC*NNp + n;
    float s=0.f;
#pragma unroll 8
    for (int c=0;c<128;c++){ float v=p[(size_t)c*NNp]; s+=v*v; }
    SQ[b*NNp+n]=s;
}

// ===================== symmetric Gram + partial top-9 =======================
// grid (32,32,BB), tj>=ti only. 512 threads. smem: As 128*132 + Bs 128*132 + sq 256
extern __shared__ float ksm[];
__global__ void __launch_bounds__(512,1) knn_sym(const float* __restrict__ XF,
        const float* __restrict__ SQ, float* __restrict__ PV, int* __restrict__ PI){
    int ti=blockIdx.x, tj=blockIdx.y, b=blockIdx.z;
    if (tj < ti) return;
    float* As = ksm;
    float* Bs = ksm + 128*KS_TW;
    float* sqi = ksm + 2*128*KS_TW;
    float* sqj = sqi + 128;
    float* LV  = As;                       // staging overlay (post-compute)
    int*   LI  = (int*)(As + 512*9);
    uint32 smb = smem_u32(ksm);
    int tid = threadIdx.x;
    const float* Xb = XF + (size_t)b*CC*NNp;

    uint32 aB = smb, bB = smb + 128*KS_TW*4;
#pragma unroll
    for (int j=0;j<8;j++){
        int idx = tid + 512*j;
        int c = idx>>5, q4 = idx&31;
        uint32 off = (uint32)(c*KS_TW + q4*4)*4u;
        cpa16(aB + off, Xb + (size_t)c*NNp + ti*128 + q4*4);
        cpa16(bB + off, Xb + (size_t)c*NNp + tj*128 + q4*4);
    }
    if (tid < 32)      cpa16(smb + (uint32)(2*128*KS_TW + tid*4)*4u,
                             SQ + (size_t)b*NNp + ti*128 + tid*4);
    else if (tid < 64) cpa16(smb + (uint32)(2*128*KS_TW + 128 + (tid-32)*4)*4u,
                             SQ + (size_t)b*NNp + tj*128 + (tid-32)*4);
    CP_COMMIT(); CP_WAIT0();
    __syncthreads();

    // 4 rows x 8 cols per thread (cols split c0 / c0+64 for 2-phase LDS)
    int r0 = (tid>>4)*4, c0 = (tid&15)*4;
    ull acc[4][4];
#pragma unroll
    for (int i=0;i<4;i++)
#pragma unroll
        for (int j=0;j<4;j++) acc[i][j]=0ULL;
#pragma unroll 4
    for (int k=0;k<128;k++){
        const float* ar = As + k*KS_TW;
        const float* br = Bs + k*KS_TW;
        float4 a = *(const float4*)(ar + r0);
        ulonglong2 b0 = *(const ulonglong2*)(br + c0);
        ulonglong2 b1 = *(const ulonglong2*)(br + c0 + 64);
        ull av[4] = {pack2(a.x),pack2(a.y),pack2(a.z),pack2(a.w)};
        ull bv[4] = {b0.x,b0.y,b1.x,b1.y};
#pragma unroll
        for (int i=0;i<4;i++)
#pragma unroll
            for (int j=0;j<4;j++) fma2(acc[i][j], av[i], bv[j]);
    }
    __syncthreads();

    // write keys (2*dot) into Bs overlay, row-major [r][c]
#pragma unroll
    for (int i=0;i<4;i++){
        float2 v0=unp(acc[i][0]), v1=unp(acc[i][1]);
        float2 v2=unp(acc[i][2]), v3=unp(acc[i][3]);
        float4 lo = make_float4(2.f*v0.x, 2.f*v0.y, 2.f*v1.x, 2.f*v1.y);
        float4 hi = make_float4(2.f*v2.x, 2.f*v2.y, 2.f*v3.x, 2.f*v3.y);
        *(float4*)(Bs + (r0+i)*KS_TW + c0) = lo;
        *(float4*)(Bs + (r0+i)*KS_TW + c0 + 64) = hi;
    }
    __syncthreads();

    const float NEGINF = __int_as_float(0xff800000);
    int q = tid>>2, sub = tid&3;
    float tv[9]; int tix[9];
#pragma unroll
    for (int k=0;k<9;k++){ tv[k]=NEGINF; tix[k]=0x7fffffff; }
    // row direction: query = ti*128+q, candidates tj*128 + [sub*32, +32)
    {
        int cb = sub*32;
        for (int cc=0; cc<32; cc++){
            int c = cb+cc;
            float key = Bs[q*KS_TW + c] - sqj[c];
            INS1(tv, tix, key, tj*128 + c);
        }
    }
#pragma unroll
    for (int k=0;k<9;k++){ LV[tid*9+k]=tv[k]; LI[tid*9+k]=tix[k]; }
    __syncthreads();
    if (tid < 128){
        int h[4]={0,0,0,0};
        const float* lv = LV + (size_t)(tid*4)*9;
        const int*   li = LI + (size_t)(tid*4)*9;
        size_t base = (((size_t)b*NNp + ti*128 + tid)*32 + tj)*9;
#pragma unroll
        for (int k=0;k<9;k++){
            float bv=NEGINF; int bi=0x7fffffff; int bs=0;
#pragma unroll
            for (int s=0;s<4;s++){
                float v=lv[s*9+h[s]]; int ix=li[s*9+h[s]];
                if (v>bv || (v==bv && ix<bi)){ bv=v; bi=ix; bs=s; }
            }
#pragma unroll
            for (int s=0;s<4;s++) if (s==bs) h[s]++;
            PV[base+k]=bv; PI[base+k]=bi;
        }
    }
    __syncthreads();

    if (ti != tj){
        // col direction: query = tj*128+q, candidates ti*128 + [sub*32, +32)
#pragma unroll
        for (int k=0;k<9;k++){ tv[k]=NEGINF; tix[k]=0x7fffffff; }
        int rb = sub*32;
        for (int rr=0; rr<32; rr++){
            int r = rb+rr;
            float key = Bs[r*KS_TW + q] - sqi[r];
            INS1(tv, tix, key, ti*128 + r);
        }
#pragma unroll
        for (int k=0;k<9;k++){ LV[tid*9+k]=tv[k]; LI[tid*9+k]=tix[k]; }
        __syncthreads();
        if (tid < 128){
            int h[4]={0,0,0,0};
            const float* lv = LV + (size_t)(tid*4)*9;
            const int*   li = LI + (size_t)(tid*4)*9;
            size_t base = (((size_t)b*NNp + tj*128 + tid)*32 + ti)*9;
#pragma unroll
            for (int k=0;k<9;k++){
                float bv=NEGINF; int bi=0x7fffffff; int bs=0;
#pragma unroll
                for (int s=0;s<4;s++){
                    float v=lv[s*9+h[s]]; int ix=li[s*9+h[s]];
                    if (v>bv || (v==bv && ix<bi)){ bv=v; bi=ix; bs=s; }
                }
#pragma unroll
                for (int s=0;s<4;s++) if (s==bs) h[s]++;
                PV[base+k]=bv; PI[base+k]=bi;
            }
        }
    }
}

// ===================== final 32-way merge ===================================
__global__ void knn_merge(const float* __restrict__ PV, const int* __restrict__ PI,
                          int* __restrict__ IDX){
    int qg = blockIdx.x*256 + threadIdx.x;           // 0..16383
    const float* pv = PV + (size_t)qg*32*9;
    const int*   pi = PI + (size_t)qg*32*9;
    const float NEGINF = __int_as_float(0xff800000);
    int h[32];
#pragma unroll
    for (int s=0;s<32;s++) h[s]=0;
    int* dst = IDX + (size_t)qg*9;
#pragma unroll
    for (int k=0;k<9;k++){
        float bv=NEGINF; int bi=0x7fffffff; int bs=0;
#pragma unroll
        for (int s=0;s<32;s++){
            float v = pv[s*9+h[s]];
            int  ix = pi[s*9+h[s]];
            if (v>bv || (v==bv && ix<bi)){ bv=v; bi=ix; bs=s; }
        }
#pragma unroll
        for (int s=0;s<32;s++) if (s==bs) h[s]++;
        dst[k]=bi;
    }
}

// ===================== per-tap GEMMs ========================================
__global__ void __launch_bounds__(256) pc_gemm(const float* __restrict__ X,
        const float* __restrict__ W4, float* __restrict__ out){
    __shared__ float As[16*TW], Bs[16*TW];
    int slot=blockIdx.z, b=blockIdx.y, n0=blockIdx.x*128, tid=threadIdx.x;
    const float* Xb = X + (size_t)b*CC*NNp;
    const float* Wd = W4 + (size_t)slot*CC*CC;
    int tr=tid>>4, tc=tid&15, r0=tr*4, c0=tc*4;
    ull acc[8][4];
#pragma unroll
    for(int i=0;i<8;i++)
#pragma unroll
        for(int j=0;j<4;j++) acc[i][j]=0ULL;
    for (int kk=0; kk<128; kk+=16){
        for (int i=tid;i<512;i+=256){
            int k=i>>5, n4=(i&31)*4;
            *(float4*)&As[k*TW+n4] = *(const float4*)(Xb + (size_t)(kk+k)*NNp + n0 + n4);
        }
        for (int i=tid;i<512;i+=256){
            int m=i>>2, k4=(i&3)*4;
            float4 v = *(const float4*)(Wd + m*128 + kk + k4);
            Bs[(k4+0)*TW+m]=v.x; Bs[(k4+1)*TW+m]=v.y; Bs[(k4+2)*TW+m]=v.z; Bs[(k4+3)*TW+m]=v.w;
        }
        __syncthreads();
#pragma unroll
        for (int k=0;k<16;k++) micro_step(As,Bs,k,r0,c0,acc);
        __syncthreads();
    }
    float* obase = out + (((size_t)slot*BB+b)*NNp + n0)*128;
#pragma unroll
    for (int i=0;i<8;i++){
        int row=(i<4)? r0+i : r0+60+i;
#pragma unroll
        for (int j=0;j<4;j++){
            int cj=(j<2)? c0+2*j : c0+60+2*j;
            *(float2*)(obase + (size_t)row*128 + cj) = unp(acc[i][j]);
        }
    }
}

// ===================== gather + edge-conv epilogue ==========================
__global__ void __launch_bounds__(256) gather_kernel(const float* __restrict__ PC,
        const int* __restrict__ IDX, const float* __restrict__ b_l1,
        const float* __restrict__ s_l1, const float* __restrict__ t_l1,
        float* __restrict__ H){
    int b=blockIdx.y;
    int o=threadIdx.x&127, sub=threadIdx.x>>7;
    float bb=b_l1[o], ss=s_l1[o], tt=t_l1[o];
    const float* P0 = PC + ((size_t)0*BB+b)*NNp*128;
    const float* P1 = PC + ((size_t)1*BB+b)*NNp*128;
    const float* P2 = PC + ((size_t)2*BB+b)*NNp*128;
    const float* P3 = PC + ((size_t)3*BB+b)*NNp*128;
    for (int it=0; it<4; it++){
        int n = blockIdx.x*8 + it*2 + sub;
        const int* id = IDX + ((size_t)b*NNp+n)*9;
        float c0v = P0[(size_t)n*128+o];
#pragma unroll
        for (int j=0;j<3;j++){
            int i0=id[3*j], i1=id[3*j+1], i2=id[3*j+2];
            float v = c0v - P1[(size_t)i0*128+o] - P2[(size_t)i1*128+o] - P3[(size_t)i2*128+o];
            H[(((size_t)b*NNp+n)*3+j)*128+o] = fmaxf(ss*(v+bb)+tt,0.f);
        }
    }
}

// ===================== global branch ========================================
__global__ void mean_kernel(const float* __restrict__ x1, float* __restrict__ g0){
    int c=blockIdx.x, b=blockIdx.y;
    const float* p = x1 + ((size_t)b*CC+c)*NNp;
    float s=0.f;
    for (int i=threadIdx.x;i<NNp;i+=256) s+=p[i];
    __shared__ float sm[8];
    for (int o=16;o;o>>=1) s+=__shfl_down_sync(~0u,s,o);
    if ((threadIdx.x&31)==0) sm[threadIdx.x>>5]=s;
    __syncthreads();
    if (threadIdx.x<8){
        s=sm[threadIdx.x];
        for (int o=4;o;o>>=1) s+=__shfl_down_sync(0xffu,s,o);
        if (threadIdx.x==0) g0[b*CC+c]=s*(1.f/NNp);
    }
}
__global__ void glob_kernel(const float* __restrict__ g0,
        const float* __restrict__ wg1,const float* __restrict__ bg1,
        const float* __restrict__ sg1,const float* __restrict__ tg1,
        const float* __restrict__ wg2,const float* __restrict__ bg2,
        const float* __restrict__ sg2,const float* __restrict__ tg2,
        float* __restrict__ g2){
    __shared__ float s0[128], s1[32];
    int b=blockIdx.x, t=threadIdx.x;
    s0[t]=g0[b*128+t]; __syncthreads();
    if (t<32){
        float a=0.f;
        for (int c=0;c<128;c++) a+=s0[c]*wg1[t*128+c];
        s1[t]=fmaxf(sg1[t]*(a+bg1[t])+tg1[t],0.f);
    }
    __syncthreads();
    float a=0.f;
    for (int i=0;i<32;i++) a+=s1[i]*wg2[t*32+i];
    g2[b*128+t]=sg2[t]*(a+bg2[t])+tg2[t];
}

// ===================== h2 GEMM + sigmoid ====================================
__global__ void __launch_bounds__(256) h2_gemm(const float* __restrict__ H,
        const float* __restrict__ Wl2, const float* __restrict__ bl2,
        const float* __restrict__ sl2, const float* __restrict__ tl2,
        const float* __restrict__ g2, float* __restrict__ out){
    __shared__ float As[16*TW], Bs[16*TW];
    int b=blockIdx.y, n0=blockIdx.x*128, tid=threadIdx.x;
    const float* Hb = H + ((size_t)b*NNp+n0)*384;
    int tr=tid>>4, tc=tid&15, r0=tr*4, c0=tc*4;
    ull acc[8][4];
#pragma unroll
    for(int i=0;i<8;i++)
#pragma unroll
        for(int j=0;j<4;j++) acc[i][j]=0ULL;
    for (int kk=0; kk<384; kk+=16){
        for (int i=tid;i<512;i+=256){
            int m=i>>2, k4=(i&3)*4;
            float4 v = *(const float4*)(Wl2 + m*384 + kk + k4);
            As[(k4+0)*TW+m]=v.x; As[(k4+1)*TW+m]=v.y; As[(k4+2)*TW+m]=v.z; As[(k4+3)*TW+m]=v.w;
        }
        for (int i=tid;i<512;i+=256){
            int n=i>>2, k4=(i&3)*4;
            float4 v = *(const float4*)(Hb + (size_t)n*384 + kk + k4);
            Bs[(k4+0)*TW+n]=v.x; Bs[(k4+1)*TW+n]=v.y; Bs[(k4+2)*TW+n]=v.z; Bs[(k4+3)*TW+n]=v.w;
        }
        __syncthreads();
#pragma unroll
        for (int k=0;k<16;k++) micro_step(As,Bs,k,r0,c0,acc);
        __syncthreads();
    }
#pragma unroll
    for (int i=0;i<8;i++){
        int p=(i<4)? r0+i : r0+60+i;
        float bb=bl2[p], ss=sl2[p], tt=tl2[p], gg=g2[b*128+p];
        float* orow = out + ((size_t)b*CC+p)*NNp + n0;
#pragma unroll
        for (int j=0;j<4;j++){
            int cj=(j<2)? c0+2*j : c0+60+2*j;
            float2 v=unp(acc[i][j]);
            float l0=fmaxf(ss*(v.x+bb)+tt,0.f);
            float l1=fmaxf(ss*(v.y+bb)+tt,0.f);
            float2 o;
            o.x = 1.f/(1.f+__expf(-(gg+l0)));
            o.y = 1.f/(1.f+__expf(-(gg+l1)));
            *(float2*)(orow+cj)=o;
        }
    }
}

extern "C" void kernel_launch(void* const* d_in, const int* in_sizes, int n_in,
                              void* d_out, int out_size){
    const float* x    = (const float*)d_in[0];
    const float* w_be = (const float*)d_in[1];
    const float* b_be = (const float*)d_in[2];
    const float* s_be = (const float*)d_in[3];
    const float* t_be = (const float*)d_in[4];
    const float* w_kn = (const float*)d_in[5];
    const float* b_kn = (const float*)d_in[6];
    const float* s_kn = (const float*)d_in[7];
    const float* t_kn = (const float*)d_in[8];
    const float* w_g1 = (const float*)d_in[9];
    const float* b_g1 = (const float*)d_in[10];
    const float* s_g1 = (const float*)d_in[11];
    const float* t_g1 = (const float*)d_in[12];
    const float* w_g2 = (const float*)d_in[13];
    const float* b_g2 = (const float*)d_in[14];
    const float* s_g2 = (const float*)d_in[15];
    const float* t_g2 = (const float*)d_in[16];
    const float* w_l1 = (const float*)d_in[17];
    const float* b_l1 = (const float*)d_in[18];
    const float* s_l1 = (const float*)d_in[19];
    const float* t_l1 = (const float*)d_in[20];
    const float* w_l2 = (const float*)d_in[21];
    const float* b_l2 = (const float*)d_in[22];
    const float* s_l2 = (const float*)d_in[23];
    const float* t_l2 = (const float*)d_in[24];
    float* out = (float*)d_out;

    float *x1, *xf, *sq, *PC, *H, *g0, *g2, *W4, *Wl2, *pv; int *idx, *pi;
    cudaGetSymbolAddress((void**)&x1, g_x1);
    cudaGetSymbolAddress((void**)&xf, g_xf);
    cudaGetSymbolAddress((void**)&sq, g_sq);
    cudaGetSymbolAddress((void**)&idx, g_idx);
    cudaGetSymbolAddress((void**)&pv, g_pv);
    cudaGetSymbolAddress((void**)&pi, g_pi);
    cudaGetSymbolAddress((void**)&PC, g_PC);
    cudaGetSymbolAddress((void**)&H, g_h);
    cudaGetSymbolAddress((void**)&W4, g_W4);
    cudaGetSymbolAddress((void**)&Wl2, g_Wl2);
    cudaGetSymbolAddress((void**)&g0, g_g0);
    cudaGetSymbolAddress((void**)&g2, g_g2);

    const int ks_smem = (2*128*KS_TW + 256) * 4;    // 136192 B
    cudaFuncSetAttribute(knn_sym, cudaFuncAttributeMaxDynamicSharedMemorySize, ks_smem);

    prep_kernel<<<256,256>>>(w_l1, w_l2);
    pw_gemm<<<dim3(32,BB),256>>>(x,  w_be, b_be, s_be, t_be, x1);
    pw_gemm<<<dim3(32,BB),256>>>(x1, w_kn, b_kn, s_kn, t_kn, xf);
    sq_kernel<<<dim3(16,BB),256>>>(xf, sq);
    knn_sym<<<dim3(32,32,BB),512,ks_smem>>>(xf, sq, pv, pi);
    knn_merge<<<64,256>>>(pv, pi, idx);
    pc_gemm<<<dim3(32,BB,4),256>>>(xf, W4, PC);
    gather_kernel<<<dim3(512,BB),256>>>(PC, idx, b_l1, s_l1, t_l1, H);
    mean_kernel<<<dim3(128,BB),256>>>(x1, g0);
    glob_kernel<<<BB,128>>>(g0, w_g1,b_g1,s_g1,t_g1, w_g2,b_g2,s_g2,t_g2, g2);
    h2_gemm<<<dim3(32,BB),256>>>(H, Wl2, b_l2, s_l2, t_l2, g2, out);
}

// round 7
// speedup vs baseline: 1.5852x; 1.0329x over previous
#include <cuda_runtime.h>
#include <math.h>
#include <cstdint>

#define BB 4
#define CC 128
#define NNp 4096
#define TW 132
#define KS_TW 132
typedef unsigned long long ull;
typedef unsigned int uint32;

__device__ float g_x1[BB*CC*NNp];
__device__ float g_xf[BB*CC*NNp];
__device__ int   g_idx[BB*NNp*9];
__device__ float g_pv[BB*NNp*32*9];
__device__ int   g_pi[BB*NNp*32*9];
__device__ float g_PC[4*BB*NNp*CC];   // [slot][b][n][o]
__device__ float g_h[BB*NNp*3*CC];    // [b][n][j][o]
__device__ float g_W4[4*CC*CC];
__device__ float g_Wl2[CC*3*CC];
__device__ float g_g0[BB*CC];
__device__ float g_g2[BB*CC];

// ===================== f32x2 helpers ========================================
__device__ __forceinline__ ull pack2(float a){
    ull r; unsigned ai=__float_as_uint(a);
    asm("mov.b64 %0, {%1, %2};" : "=l"(r) : "r"(ai), "r"(ai));
    return r;
}
__device__ __forceinline__ void fma2(ull &d, ull a, ull b){
    asm("fma.rn.f32x2 %0, %1, %2, %0;" : "+l"(d) : "l"(a), "l"(b));
}
__device__ __forceinline__ float2 unp(ull v){ union{ull u; float2 f;}c; c.u=v; return c.f; }

__device__ __forceinline__ uint32 smem_u32(const void* p){
    uint32 a;
    asm("{ .reg .u64 t; cvta.to.shared.u64 t, %1; cvt.u32.u64 %0, t; }" : "=r"(a) : "l"(p));
    return a;
}
__device__ __forceinline__ void cpa16(uint32 dst, const void* src){
    asm volatile("cp.async.ca.shared.global [%0], [%1], 16;" :: "r"(dst), "l"(src));
}
#define CP_COMMIT() asm volatile("cp.async.commit_group;" ::: "memory")
#define CP_WAIT0()  asm volatile("cp.async.wait_group 0;" ::: "memory")

#define INS1(tv, tix, val, jg) do{ \
  if ((val)>(tv)[8] || ((val)==(tv)[8] && (jg)<(tix)[8])){ \
    (tv)[8]=(val); (tix)[8]=(jg); \
    _Pragma("unroll") for (int p_=8;p_>0;--p_){ \
      bool sw_=((tv)[p_]>(tv)[p_-1])||((tv)[p_]==(tv)[p_-1]&&(tix)[p_]<(tix)[p_-1]); \
      if (sw_){ float fv_=(tv)[p_];(tv)[p_]=(tv)[p_-1];(tv)[p_-1]=fv_; \
               int iv_=(tix)[p_];(tix)[p_]=(tix)[p_-1];(tix)[p_-1]=iv_; } } } }while(0)

// ===================== weight prep ==========================================
__global__ void prep_kernel(const float* __restrict__ wl1, const float* __restrict__ wl2){
    for (int i = blockIdx.x*256 + threadIdx.x; i < 4*CC*CC; i += gridDim.x*256){
        int slot=i>>14, rem=i&16383, o=rem>>7, c=rem&127;
        float v;
        if (slot==0){
            v=0.f;
#pragma unroll
            for (int w=0;w<3;w++) v += wl1[(o*256+c)*3+w] + wl1[(o*256+128+c)*3+w];
        } else v = wl1[(o*256+128+c)*3+(slot-1)];
        g_W4[i]=v;
    }
    for (int i = blockIdx.x*256 + threadIdx.x; i < CC*3*CC; i += gridDim.x*256){
        int p=i/384, k=i%384, w=k>>7, o=k&127;
        g_Wl2[i] = wl2[(p*128+o)*3+w];
    }
}

// ===================== pointwise conv (128 o x 64 n tiles) ==================
__global__ void __launch_bounds__(256) pw_gemm(const float* __restrict__ X,
        const float* __restrict__ W, const float* __restrict__ bias,
        const float* __restrict__ sc, const float* __restrict__ tr_,
        float* __restrict__ out){
    __shared__ float As[16*TW], Bs[16*68];
    int b=blockIdx.y, n0=blockIdx.x*64, tid=threadIdx.x;
    const float* Xb = X + (size_t)b*CC*NNp;
    int tr=tid>>4, tc=tid&15, r0=tr*4, c0=tc*2;
    ull acc[8][2];
#pragma unroll
    for(int i=0;i<8;i++){ acc[i][0]=0ULL; acc[i][1]=0ULL; }
    for (int kk=0; kk<128; kk+=16){
        for (int i=tid;i<512;i+=256){               // W[o][c] -> As[c][o]
            int m=i>>2, k4=(i&3)*4;
            float4 v = *(const float4*)(W + m*128 + kk + k4);
            As[(k4+0)*TW+m]=v.x; As[(k4+1)*TW+m]=v.y; As[(k4+2)*TW+m]=v.z; As[(k4+3)*TW+m]=v.w;
        }
        {
            int i=tid;                               // X[c][n] -> Bs[c][n] (16x64)
            int k=i>>4, n4=(i&15)*4;
            *(float4*)&Bs[k*68+n4] = *(const float4*)(Xb + (size_t)(kk+k)*NNp + n0 + n4);
        }
        __syncthreads();
#pragma unroll
        for (int k=0;k<16;k++){
            const float* ar = As + k*TW; const float* br = Bs + k*68;
            float4 a0 = *(const float4*)(ar+r0);
            float4 a1 = *(const float4*)(ar+r0+64);
            ull b0 = *(const ull*)(br+c0);
            ull b1 = *(const ull*)(br+c0+32);
            ull av[8]={pack2(a0.x),pack2(a0.y),pack2(a0.z),pack2(a0.w),
                       pack2(a1.x),pack2(a1.y),pack2(a1.z),pack2(a1.w)};
#pragma unroll
            for (int i=0;i<8;i++){ fma2(acc[i][0],av[i],b0); fma2(acc[i][1],av[i],b1); }
        }
        __syncthreads();
    }
#pragma unroll
    for (int i=0;i<8;i++){
        int row = (i<4)? r0+i : r0+60+i;
        float bb=bias[row], ss=sc[row], tt=tr_[row];
        float* orow = out + ((size_t)b*CC+row)*NNp + n0;
#pragma unroll
        for (int j=0;j<2;j++){
            int cj = c0 + j*32;
            float2 v=unp(acc[i][j]);
            float2 o; o.x=fmaxf(ss*(v.x+bb)+tt,0.f); o.y=fmaxf(ss*(v.y+bb)+tt,0.f);
            *(float2*)(orow+cj)=o;
        }
    }
}

// ===================== symmetric Gram + fused sq + partial top-9 ============
extern __shared__ float ksm[];
__global__ void __launch_bounds__(512,1) knn_sym(const float* __restrict__ XF,
        float* __restrict__ PV, int* __restrict__ PI){
    int ti=blockIdx.x, tj=blockIdx.y, b=blockIdx.z;
    if (tj < ti) return;
    float* As = ksm;
    float* Bs = ksm + 128*KS_TW;
    float* sqi = ksm + 2*128*KS_TW;
    float* sqj = sqi + 128;
    float* LV  = As;
    int*   LI  = (int*)(As + 512*9);
    uint32 smb = smem_u32(ksm);
    int tid = threadIdx.x;
    const float* Xb = XF + (size_t)b*CC*NNp;

    uint32 aB = smb, bB = smb + 128*KS_TW*4;
#pragma unroll
    for (int j=0;j<8;j++){
        int idx = tid + 512*j;
        int c = idx>>5, q4 = idx&31;
        uint32 off = (uint32)(c*KS_TW + q4*4)*4u;
        cpa16(aB + off, Xb + (size_t)c*NNp + ti*128 + q4*4);
        cpa16(bB + off, Xb + (size_t)c*NNp + tj*128 + q4*4);
    }
    CP_COMMIT(); CP_WAIT0();
    __syncthreads();

    // fused sq: sqi[q] = sum_c As[c][q]^2 (fixed c order => identical everywhere)
    if (tid < 128){
        float s=0.f;
#pragma unroll 8
        for (int c=0;c<128;c++){ float v=As[c*KS_TW+tid]; s=fmaf(v,v,s); }
        sqi[tid]=s;
    } else if (tid < 256){
        int q=tid-128; float s=0.f;
#pragma unroll 8
        for (int c=0;c<128;c++){ float v=Bs[c*KS_TW+q]; s=fmaf(v,v,s); }
        sqj[q]=s;
    }
    __syncthreads();

    int r0 = (tid>>4)*4, c0 = (tid&15)*4;
    ull acc[4][4];
#pragma unroll
    for (int i=0;i<4;i++)
#pragma unroll
        for (int j=0;j<4;j++) acc[i][j]=0ULL;
#pragma unroll 4
    for (int k=0;k<128;k++){
        const float* ar = As + k*KS_TW;
        const float* br = Bs + k*KS_TW;
        float4 a = *(const float4*)(ar + r0);
        ulonglong2 b0 = *(const ulonglong2*)(br + c0);
        ulonglong2 b1 = *(const ulonglong2*)(br + c0 + 64);
        ull av[4] = {pack2(a.x),pack2(a.y),pack2(a.z),pack2(a.w)};
        ull bv[4] = {b0.x,b0.y,b1.x,b1.y};
#pragma unroll
        for (int i=0;i<4;i++)
#pragma unroll
            for (int j=0;j<4;j++) fma2(acc[i][j], av[i], bv[j]);
    }
    __syncthreads();

#pragma unroll
    for (int i=0;i<4;i++){
        float2 v0=unp(acc[i][0]), v1=unp(acc[i][1]);
        float2 v2=unp(acc[i][2]), v3=unp(acc[i][3]);
        float4 lo = make_float4(2.f*v0.x, 2.f*v0.y, 2.f*v1.x, 2.f*v1.y);
        float4 hi = make_float4(2.f*v2.x, 2.f*v2.y, 2.f*v3.x, 2.f*v3.y);
        *(float4*)(Bs + (r0+i)*KS_TW + c0) = lo;
        *(float4*)(Bs + (r0+i)*KS_TW + c0 + 64) = hi;
    }
    __syncthreads();

    const float NEGINF = __int_as_float(0xff800000);
    int q = tid>>2, sub = tid&3;
    float tv[9]; int tix[9];
#pragma unroll
    for (int k=0;k<9;k++){ tv[k]=NEGINF; tix[k]=0x7fffffff; }
    {
        int cb = sub*32;
        for (int cc=0; cc<32; cc++){
            int c = cb+cc;
            float key = Bs[q*KS_TW + c] - sqj[c];
            INS1(tv, tix, key, tj*128 + c);
        }
    }
#pragma unroll
    for (int k=0;k<9;k++){ LV[tid*9+k]=tv[k]; LI[tid*9+k]=tix[k]; }
    __syncthreads();
    if (tid < 128){
        int h[4]={0,0,0,0};
        const float* lv = LV + (size_t)(tid*4)*9;
        const int*   li = LI + (size_t)(tid*4)*9;
        size_t base = (((size_t)b*NNp + ti*128 + tid)*32 + tj)*9;
#pragma unroll
        for (int k=0;k<9;k++){
            float bv=NEGINF; int bi=0x7fffffff; int bs=0;
#pragma unroll
            for (int s=0;s<4;s++){
                float v=lv[s*9+h[s]]; int ix=li[s*9+h[s]];
                if (v>bv || (v==bv && ix<bi)){ bv=v; bi=ix; bs=s; }
            }
#pragma unroll
            for (int s=0;s<4;s++) if (s==bs) h[s]++;
            PV[base+k]=bv; PI[base+k]=bi;
        }
    }
    __syncthreads();

    if (ti != tj){
#pragma unroll
        for (int k=0;k<9;k++){ tv[k]=NEGINF; tix[k]=0x7fffffff; }
        int rb = sub*32;
        for (int rr=0; rr<32; rr++){
            int r = rb+rr;
            float key = Bs[r*KS_TW + q] - sqi[r];
            INS1(tv, tix, key, ti*128 + r);
        }
#pragma unroll
        for (int k=0;k<9;k++){ LV[tid*9+k]=tv[k]; LI[tid*9+k]=tix[k]; }
        __syncthreads();
        if (tid < 128){
            int h[4]={0,0,0,0};
            const float* lv = LV + (size_t)(tid*4)*9;
            const int*   li = LI + (size_t)(tid*4)*9;
            size_t base = (((size_t)b*NNp + tj*128 + tid)*32 + ti)*9;
#pragma unroll
            for (int k=0;k<9;k++){
                float bv=NEGINF; int bi=0x7fffffff; int bs=0;
#pragma unroll
                for (int s=0;s<4;s++){
                    float v=lv[s*9+h[s]]; int ix=li[s*9+h[s]];
                    if (v>bv || (v==bv && ix<bi)){ bv=v; bi=ix; bs=s; }
                }
#pragma unroll
                for (int s=0;s<4;s++) if (s==bs) h[s]++;
                PV[base+k]=bv; PI[base+k]=bi;
            }
        }
    }
}

// ===================== final 32-way merge ===================================
__global__ void knn_merge(const float* __restrict__ PV, const int* __restrict__ PI,
                          int* __restrict__ IDX){
    int qg = blockIdx.x*256 + threadIdx.x;
    const float* pv = PV + (size_t)qg*32*9;
    const int*   pi = PI + (size_t)qg*32*9;
    const float NEGINF = __int_as_float(0xff800000);
    int h[32];
#pragma unroll
    for (int s=0;s<32;s++) h[s]=0;
    int* dst = IDX + (size_t)qg*9;
#pragma unroll
    for (int k=0;k<9;k++){
        float bv=NEGINF; int bi=0x7fffffff; int bs=0;
#pragma unroll
        for (int s=0;s<32;s++){
            float v = pv[s*9+h[s]];
            int  ix = pi[s*9+h[s]];
            if (v>bv || (v==bv && ix<bi)){ bv=v; bi=ix; bs=s; }
        }
#pragma unroll
        for (int s=0;s<32;s++) if (s==bs) h[s]++;
        dst[k]=bi;
    }
}

// ===================== per-tap GEMMs (2 blocks/SM) ==========================
__global__ void __launch_bounds__(256,2) pc_gemm(const float* __restrict__ X,
        const float* __restrict__ W4, float* __restrict__ out){
    __shared__ float As[16*TW], Bs[16*TW];
    int slot=blockIdx.z, b=blockIdx.y, n0=blockIdx.x*128, tid=threadIdx.x;
    const float* Xb = X + (size_t)b*CC*NNp;
    const float* Wd = W4 + (size_t)slot*CC*CC;
    int tr=tid>>4, tc=tid&15, r0=tr*4, c0=tc*4;
    ull acc[8][4];
#pragma unroll
    for(int i=0;i<8;i++)
#pragma unroll
        for(int j=0;j<4;j++) acc[i][j]=0ULL;
    for (int kk=0; kk<128; kk+=16){
        for (int i=tid;i<512;i+=256){
            int k=i>>5, n4=(i&31)*4;
            *(float4*)&As[k*TW+n4] = *(const float4*)(Xb + (size_t)(kk+k)*NNp + n0 + n4);
        }
        for (int i=tid;i<512;i+=256){
            int m=i>>2, k4=(i&3)*4;
            float4 v = *(const float4*)(Wd + m*128 + kk + k4);
            Bs[(k4+0)*TW+m]=v.x; Bs[(k4+1)*TW+m]=v.y; Bs[(k4+2)*TW+m]=v.z; Bs[(k4+3)*TW+m]=v.w;
        }
        __syncthreads();
#pragma unroll
        for (int k=0;k<16;k++){
            const float* ar = As + k*TW; const float* br = Bs + k*TW;
            float4 a0 = *(const float4*)(ar+r0);
            float4 a1 = *(const float4*)(ar+r0+64);
            ulonglong2 b0 = *(const ulonglong2*)(br+c0);
            ulonglong2 b1 = *(const ulonglong2*)(br+c0+64);
            ull av[8]={pack2(a0.x),pack2(a0.y),pack2(a0.z),pack2(a0.w),
                       pack2(a1.x),pack2(a1.y),pack2(a1.z),pack2(a1.w)};
            ull bv[4]={b0.x,b0.y,b1.x,b1.y};
#pragma unroll
            for (int i=0;i<8;i++)
#pragma unroll
                for (int j=0;j<4;j++) fma2(acc[i][j], av[i], bv[j]);
        }
        __syncthreads();
    }
    float* obase = out + (((size_t)slot*BB+b)*NNp + n0)*128;
#pragma unroll
    for (int i=0;i<8;i++){
        int row=(i<4)? r0+i : r0+60+i;
#pragma unroll
        for (int j=0;j<4;j++){
            int cj=(j<2)? c0+2*j : c0+60+2*j;
            *(float2*)(obase + (size_t)row*128 + cj) = unp(acc[i][j]);
        }
    }
}

// ===================== gather + edge-conv epilogue ==========================
__global__ void __launch_bounds__(256) gather_kernel(const float* __restrict__ PC,
        const int* __restrict__ IDX, const float* __restrict__ b_l1,
        const float* __restrict__ s_l1, const float* __restrict__ t_l1,
        float* __restrict__ H){
    int b=blockIdx.y;
    int o=threadIdx.x&127, sub=threadIdx.x>>7;
    float bb=b_l1[o], ss=s_l1[o], tt=t_l1[o];
    const float* P0 = PC + ((size_t)0*BB+b)*NNp*128;
    const float* P1 = PC + ((size_t)1*BB+b)*NNp*128;
    const float* P2 = PC + ((size_t)2*BB+b)*NNp*128;
    const float* P3 = PC + ((size_t)3*BB+b)*NNp*128;
    for (int it=0; it<4; it++){
        int n = blockIdx.x*8 + it*2 + sub;
        const int* id = IDX + ((size_t)b*NNp+n)*9;
        float c0v = P0[(size_t)n*128+o];
#pragma unroll
        for (int j=0;j<3;j++){
            int i0=id[3*j], i1=id[3*j+1], i2=id[3*j+2];
            float v = c0v - P1[(size_t)i0*128+o] - P2[(size_t)i1*128+o] - P3[(size_t)i2*128+o];
            H[(((size_t)b*NNp+n)*3+j)*128+o] = fmaxf(ss*(v+bb)+tt,0.f);
        }
    }
}

// ===================== global branch ========================================
__global__ void mean_kernel(const float* __restrict__ x1, float* __restrict__ g0){
    int c=blockIdx.x, b=blockIdx.y;
    const float* p = x1 + ((size_t)b*CC+c)*NNp;
    float s=0.f;
    for (int i=threadIdx.x;i<NNp;i+=256) s+=p[i];
    __shared__ float sm[8];
    for (int o=16;o;o>>=1) s+=__shfl_down_sync(~0u,s,o);
    if ((threadIdx.x&31)==0) sm[threadIdx.x>>5]=s;
    __syncthreads();
    if (threadIdx.x<8){
        s=sm[threadIdx.x];
        for (int o=4;o;o>>=1) s+=__shfl_down_sync(0xffu,s,o);
        if (threadIdx.x==0) g0[b*CC+c]=s*(1.f/NNp);
    }
}
__global__ void glob_kernel(const float* __restrict__ g0,
        const float* __restrict__ wg1,const float* __restrict__ bg1,
        const float* __restrict__ sg1,const float* __restrict__ tg1,
        const float* __restrict__ wg2,const float* __restrict__ bg2,
        const float* __restrict__ sg2,const float* __restrict__ tg2,
        float* __restrict__ g2){
    __shared__ float s0[128], s1[32];
    int b=blockIdx.x, t=threadIdx.x;
    s0[t]=g0[b*128+t]; __syncthreads();
    if (t<32){
        float a=0.f;
        for (int c=0;c<128;c++) a+=s0[c]*wg1[t*128+c];
        s1[t]=fmaxf(sg1[t]*(a+bg1[t])+tg1[t],0.f);
    }
    __syncthreads();
    float a=0.f;
    for (int i=0;i<32;i++) a+=s1[i]*wg2[t*32+i];
    g2[b*128+t]=sg2[t]*(a+bg2[t])+tg2[t];
}

// ===================== h2 GEMM (128 p x 64 n tiles, K=384) + sigmoid ========
__global__ void __launch_bounds__(256) h2_gemm(const float* __restrict__ H,
        const float* __restrict__ Wl2, const float* __restrict__ bl2,
        const float* __restrict__ sl2, const float* __restrict__ tl2,
        const float* __restrict__ g2, float* __restrict__ out){
    __shared__ float As[16*TW], Bs[16*68];
    int b=blockIdx.y, n0=blockIdx.x*64, tid=threadIdx.x;
    const float* Hb = H + ((size_t)b*NNp+n0)*384;
    int tr=tid>>4, tc=tid&15, r0=tr*4, c0=tc*2;
    ull acc[8][2];
#pragma unroll
    for(int i=0;i<8;i++){ acc[i][0]=0ULL; acc[i][1]=0ULL; }
    for (int kk=0; kk<384; kk+=16){
        for (int i=tid;i<512;i+=256){               // Wl2[p][k] -> As[k][p]
            int m=i>>2, k4=(i&3)*4;
            float4 v = *(const float4*)(Wl2 + m*384 + kk + k4);
            As[(k4+0)*TW+m]=v.x; As[(k4+1)*TW+m]=v.y; As[(k4+2)*TW+m]=v.z; As[(k4+3)*TW+m]=v.w;
        }
        {
            int i=tid;                               // H[n][k] -> Bs[k][n] (16x64)
            int n=i>>2, k4=(i&3)*4;
            float4 v = *(const float4*)(Hb + (size_t)n*384 + kk + k4);
            Bs[(k4+0)*68+n]=v.x; Bs[(k4+1)*68+n]=v.y; Bs[(k4+2)*68+n]=v.z; Bs[(k4+3)*68+n]=v.w;
        }
        __syncthreads();
#pragma unroll
        for (int k=0;k<16;k++){
            const float* ar = As + k*TW; const float* br = Bs + k*68;
            float4 a0 = *(const float4*)(ar+r0);
            float4 a1 = *(const float4*)(ar+r0+64);
            ull b0 = *(const ull*)(br+c0);
            ull b1 = *(const ull*)(br+c0+32);
            ull av[8]={pack2(a0.x),pack2(a0.y),pack2(a0.z),pack2(a0.w),
                       pack2(a1.x),pack2(a1.y),pack2(a1.z),pack2(a1.w)};
#pragma unroll
            for (int i=0;i<8;i++){ fma2(acc[i][0],av[i],b0); fma2(acc[i][1],av[i],b1); }
        }
        __syncthreads();
    }
#pragma unroll
    for (int i=0;i<8;i++){
        int p=(i<4)? r0+i : r0+60+i;
        float bb=bl2[p], ss=sl2[p], tt=tl2[p], gg=g2[b*128+p];
        float* orow = out + ((size_t)b*CC+p)*NNp + n0;
#pragma unroll
        for (int j=0;j<2;j++){
            int cj=c0+j*32;
            float2 v=unp(acc[i][j]);
            float l0=fmaxf(ss*(v.x+bb)+tt,0.f);
            float l1=fmaxf(ss*(v.y+bb)+tt,0.f);
            float2 o;
            o.x = 1.f/(1.f+__expf(-(gg+l0)));
            o.y = 1.f/(1.f+__expf(-(gg+l1)));
            *(float2*)(orow+cj)=o;
        }
    }
}

extern "C" void kernel_launch(void* const* d_in, const int* in_sizes, int n_in,
                              void* d_out, int out_size){
    const float* x    = (const float*)d_in[0];
    const float* w_be = (const float*)d_in[1];
    const float* b_be = (const float*)d_in[2];
    const float* s_be = (const float*)d_in[3];
    const float* t_be = (const float*)d_in[4];
    const float* w_kn = (const float*)d_in[5];
    const float* b_kn = (const float*)d_in[6];
    const float* s_kn = (const float*)d_in[7];
    const float* t_kn = (const float*)d_in[8];
    const float* w_g1 = (const float*)d_in[9];
    const float* b_g1 = (const float*)d_in[10];
    const float* s_g1 = (const float*)d_in[11];
    const float* t_g1 = (const float*)d_in[12];
    const float* w_g2 = (const float*)d_in[13];
    const float* b_g2 = (const float*)d_in[14];
    const float* s_g2 = (const float*)d_in[15];
    const float* t_g2 = (const float*)d_in[16];
    const float* w_l1 = (const float*)d_in[17];
    const float* b_l1 = (const float*)d_in[18];
    const float* s_l1 = (const float*)d_in[19];
    const float* t_l1 = (const float*)d_in[20];
    const float* w_l2 = (const float*)d_in[21];
    const float* b_l2 = (const float*)d_in[22];
    const float* s_l2 = (const float*)d_in[23];
    const float* t_l2 = (const float*)d_in[24];
    float* out = (float*)d_out;

    float *x1, *xf, *PC, *H, *g0, *g2, *W4, *Wl2, *pv; int *idx, *pi;
    cudaGetSymbolAddress((void**)&x1, g_x1);
    cudaGetSymbolAddress((void**)&xf, g_xf);
    cudaGetSymbolAddress((void**)&idx, g_idx);
    cudaGetSymbolAddress((void**)&pv, g_pv);
    cudaGetSymbolAddress((void**)&pi, g_pi);
    cudaGetSymbolAddress((void**)&PC, g_PC);
    cudaGetSymbolAddress((void**)&H, g_h);
    cudaGetSymbolAddress((void**)&W4, g_W4);
    cudaGetSymbolAddress((void**)&Wl2, g_Wl2);
    cudaGetSymbolAddress((void**)&g0, g_g0);
    cudaGetSymbolAddress((void**)&g2, g_g2);

    const int ks_smem = (2*128*KS_TW + 256) * 4;    // 136192 B
    cudaFuncSetAttribute(knn_sym, cudaFuncAttributeMaxDynamicSharedMemorySize, ks_smem);

    prep_kernel<<<256,256>>>(w_l1, w_l2);
    pw_gemm<<<dim3(64,BB),256>>>(x,  w_be, b_be, s_be, t_be, x1);
    pw_gemm<<<dim3(64,BB),256>>>(x1, w_kn, b_kn, s_kn, t_kn, xf);
    knn_sym<<<dim3(32,32,BB),512,ks_smem>>>(xf, pv, pi);   // 4th launch -> ncu
    knn_merge<<<64,256>>>(pv, pi, idx);
    pc_gemm<<<dim3(32,BB,4),256>>>(xf, W4, PC);
    gather_kernel<<<dim3(512,BB),256>>>(PC, idx, b_l1, s_l1, t_l1, H);
    mean_kernel<<<dim3(128,BB),256>>>(x1, g0);
    glob_kernel<<<BB,128>>>(g0, w_g1,b_g1,s_g1,t_g1, w_g2,b_g2,s_g2,t_g2, g2);
    h2_gemm<<<dim3(64,BB),256>>>(H, Wl2, b_l2, s_l2, t_l2, g2, out);
}

// round 9
// speedup vs baseline: 1.8372x; 1.1590x over previous
#include <cuda_runtime.h>
#include <math.h>
#include <cstdint>

#define BB 4
#define CC 128
#define NNp 4096
#define TW 132
#define KS_TW 132
typedef unsigned long long ull;
typedef unsigned int uint32;

__device__ float g_x1[BB*CC*NNp];
__device__ float g_xf[BB*CC*NNp];
__device__ float g_sq[BB*NNp];
__device__ int   g_idx[BB*NNp*9];
__device__ float g_G[(size_t)BB*NNp*NNp];   // 1 GB: raw dot products
__device__ float g_PC[4*BB*NNp*CC];   // [slot][b][n][o]
__device__ float g_h[BB*NNp*3*CC];    // [b][n][j][o]
__device__ float g_W4[4*CC*CC];
__device__ float g_Wl2[CC*3*CC];
__device__ float g_g0[BB*CC];
__device__ float g_g2[BB*CC];

// ===================== f32x2 helpers ========================================
__device__ __forceinline__ ull pack2(float a){
    ull r; unsigned ai=__float_as_uint(a);
    asm("mov.b64 %0, {%1, %2};" : "=l"(r) : "r"(ai), "r"(ai));
    return r;
}
__device__ __forceinline__ void fma2(ull &d, ull a, ull b){
    asm("fma.rn.f32x2 %0, %1, %2, %0;" : "+l"(d) : "l"(a), "l"(b));
}
__device__ __forceinline__ float2 unp(ull v){ union{ull u; float2 f;}c; c.u=v; return c.f; }

__device__ __forceinline__ uint32 smem_u32(const void* p){
    uint32 a;
    asm("{ .reg .u64 t; cvta.to.shared.u64 t, %1; cvt.u32.u64 %0, t; }" : "=r"(a) : "l"(p));
    return a;
}
__device__ __forceinline__ void cpa16(uint32 dst, const void* src){
    asm volatile("cp.async.ca.shared.global [%0], [%1], 16;" :: "r"(dst), "l"(src));
}
#define CP_COMMIT() asm volatile("cp.async.commit_group;" ::: "memory")
#define CP_WAIT0()  asm volatile("cp.async.wait_group 0;" ::: "memory")

#define INS1(tv, tix, val, jg) do{ \
  if ((val)>(tv)[8] || ((val)==(tv)[8] && (jg)<(tix)[8])){ \
    (tv)[8]=(val); (tix)[8]=(jg); \
    _Pragma("unroll") for (int p_=8;p_>0;--p_){ \
      bool sw_=((tv)[p_]>(tv)[p_-1])||((tv)[p_]==(tv)[p_-1]&&(tix)[p_]<(tix)[p_-1]); \
      if (sw_){ float fv_=(tv)[p_];(tv)[p_]=(tv)[p_-1];(tv)[p_-1]=fv_; \
               int iv_=(tix)[p_];(tix)[p_]=(tix)[p_-1];(tix)[p_-1]=iv_; } } } }while(0)

// ===================== weight prep ==========================================
__global__ void prep_kernel(const float* __restrict__ wl1, const float* __restrict__ wl2){
    for (int i = blockIdx.x*256 + threadIdx.x; i < 4*CC*CC; i += gridDim.x*256){
        int slot=i>>14, rem=i&16383, o=rem>>7, c=rem&127;
        float v;
        if (slot==0){
            v=0.f;
#pragma unroll
            for (int w=0;w<3;w++) v += wl1[(o*256+c)*3+w] + wl1[(o*256+128+c)*3+w];
        } else v = wl1[(o*256+128+c)*3+(slot-1)];
        g_W4[i]=v;
    }
    for (int i = blockIdx.x*256 + threadIdx.x; i < CC*3*CC; i += gridDim.x*256){
        int p=i/384, k=i%384, w=k>>7, o=k&127;
        g_Wl2[i] = wl2[(p*128+o)*3+w];
    }
}

// ===================== pointwise conv (128 o x 64 n tiles) ==================
__global__ void __launch_bounds__(256) pw_gemm(const float* __restrict__ X,
        const float* __restrict__ W, const float* __restrict__ bias,
        const float* __restrict__ sc, const float* __restrict__ tr_,
        float* __restrict__ out){
    __shared__ float As[16*TW], Bs[16*68];
    int b=blockIdx.y, n0=blockIdx.x*64, tid=threadIdx.x;
    const float* Xb = X + (size_t)b*CC*NNp;
    int tr=tid>>4, tc=tid&15, r0=tr*4, c0=tc*2;
    ull acc[8][2];
#pragma unroll
    for(int i=0;i<8;i++){ acc[i][0]=0ULL; acc[i][1]=0ULL; }
    for (int kk=0; kk<128; kk+=16){
        for (int i=tid;i<512;i+=256){               // W[o][c] -> As[c][o]
            int m=i>>2, k4=(i&3)*4;
            float4 v = *(const float4*)(W + m*128 + kk + k4);
            As[(k4+0)*TW+m]=v.x; As[(k4+1)*TW+m]=v.y; As[(k4+2)*TW+m]=v.z; As[(k4+3)*TW+m]=v.w;
        }
        {
            int i=tid;                               // X[c][n] -> Bs[c][n] (16x64)
            int k=i>>4, n4=(i&15)*4;
            *(float4*)&Bs[k*68+n4] = *(const float4*)(Xb + (size_t)(kk+k)*NNp + n0 + n4);
        }
        __syncthreads();
#pragma unroll
        for (int k=0;k<16;k++){
            const float* ar = As + k*TW; const float* br = Bs + k*68;
            float4 a0 = *(const float4*)(ar+r0);
            float4 a1 = *(const float4*)(ar+r0+64);
            ull b0 = *(const ull*)(br+c0);
            ull b1 = *(const ull*)(br+c0+32);
            ull av[8]={pack2(a0.x),pack2(a0.y),pack2(a0.z),pack2(a0.w),
                       pack2(a1.x),pack2(a1.y),pack2(a1.z),pack2(a1.w)};
#pragma unroll
            for (int i=0;i<8;i++){ fma2(acc[i][0],av[i],b0); fma2(acc[i][1],av[i],b1); }
        }
        __syncthreads();
    }
#pragma unroll
    for (int i=0;i<8;i++){
        int row = (i<4)? r0+i : r0+60+i;
        float bb=bias[row], ss=sc[row], tt=tr_[row];
        float* orow = out + ((size_t)b*CC+row)*NNp + n0;
#pragma unroll
        for (int j=0;j<2;j++){
            int cj = c0 + j*32;
            float2 v=unp(acc[i][j]);
            float2 o; o.x=fmaxf(ss*(v.x+bb)+tt,0.f); o.y=fmaxf(ss*(v.y+bb)+tt,0.f);
            *(float2*)(orow+cj)=o;
        }
    }
}

__global__ void sq_kernel(const float* __restrict__ XF, float* __restrict__ SQ){
    int n=blockIdx.x*256+threadIdx.x, b=blockIdx.y;
    const float* p = XF + (size_t)b*CC*NNp + n;
    float s=0.f;
#pragma unroll 8
    for (int c=0;c<128;c++){ float v=p[(size_t)c*NNp]; s+=v*v; }
    SQ[b*NNp+n]=s;
}

// ===================== symmetric Gram -> gmem dot matrix ====================
extern __shared__ float ksm[];
__global__ void __launch_bounds__(512,1) knn_sym(const float* __restrict__ XF,
        float* __restrict__ G){
    int ti=blockIdx.x, tj=blockIdx.y, b=blockIdx.z;
    if (tj < ti) return;
    float* As = ksm;
    float* Bs = ksm + 128*KS_TW;
    uint32 smb = smem_u32(ksm);
    int tid = threadIdx.x;
    const float* Xb = XF + (size_t)b*CC*NNp;

    uint32 aB = smb, bB = smb + 128*KS_TW*4;
#pragma unroll
    for (int j=0;j<8;j++){
        int idx = tid + 512*j;
        int c = idx>>5, q4 = idx&31;
        uint32 off = (uint32)(c*KS_TW + q4*4)*4u;
        cpa16(aB + off, Xb + (size_t)c*NNp + ti*128 + q4*4);
        cpa16(bB + off, Xb + (size_t)c*NNp + tj*128 + q4*4);
    }
    CP_COMMIT(); CP_WAIT0();
    __syncthreads();

    int r0 = (tid>>4)*4, c0 = (tid&15)*4;
    ull acc[4][4];
#pragma unroll
    for (int i=0;i<4;i++)
#pragma unroll
        for (int j=0;j<4;j++) acc[i][j]=0ULL;
#pragma unroll 4
    for (int k=0;k<128;k++){
        const float* ar = As + k*KS_TW;
        const float* br = Bs + k*KS_TW;
        float4 a = *(const float4*)(ar + r0);
        ulonglong2 b0 = *(const ulonglong2*)(br + c0);
        ulonglong2 b1 = *(const ulonglong2*)(br + c0 + 64);
        ull av[4] = {pack2(a.x),pack2(a.y),pack2(a.z),pack2(a.w)};
        ull bv[4] = {b0.x,b0.y,b1.x,b1.y};
#pragma unroll
        for (int i=0;i<4;i++)
#pragma unroll
            for (int j=0;j<4;j++) fma2(acc[i][j], av[i], bv[j]);
    }

    float vals[4][8];
#pragma unroll
    for (int i=0;i<4;i++){
        float2 v0=unp(acc[i][0]), v1=unp(acc[i][1]);
        float2 v2=unp(acc[i][2]), v3=unp(acc[i][3]);
        vals[i][0]=v0.x; vals[i][1]=v0.y; vals[i][2]=v1.x; vals[i][3]=v1.y;
        vals[i][4]=v2.x; vals[i][5]=v2.y; vals[i][6]=v3.x; vals[i][7]=v3.y;
    }

    // row stores (coalesced): G[b][ti*128+r][tj*128+c]
    float* Grow = G + ((size_t)b*NNp + (size_t)ti*128)*NNp + (size_t)tj*128;
#pragma unroll
    for (int i=0;i<4;i++){
        float* p = Grow + (size_t)(r0+i)*NNp;
        *(float4*)(p + c0)      = make_float4(vals[i][0],vals[i][1],vals[i][2],vals[i][3]);
        *(float4*)(p + c0 + 64) = make_float4(vals[i][4],vals[i][5],vals[i][6],vals[i][7]);
    }

    // transposed stores: G[b][tj*128+c][ti*128+r0..r0+3]
    if (ti != tj){
        float* Gcol = G + ((size_t)b*NNp + (size_t)tj*128)*NNp + (size_t)ti*128;
#pragma unroll
        for (int cl=0; cl<8; cl++){
            int c = (cl<4)? (c0+cl) : (c0+60+cl);
            float4 t = make_float4(vals[0][cl], vals[1][cl], vals[2][cl], vals[3][cl]);
            *(float4*)(Gcol + (size_t)c*NNp + r0) = t;
        }
    }
}

// ===================== streaming top-9 selection ============================
// dynamic smem: sqs[4096] | LV[512*9] | LI[512*9]  = 53248 B
extern __shared__ float sel_sm[];
__global__ void __launch_bounds__(512,1) knn_select(const float* __restrict__ G,
        const float* __restrict__ SQ, int* __restrict__ IDX){
    float* sqs = sel_sm;
    float* LV  = sel_sm + NNp;
    int*   LI  = (int*)(sel_sm + NNp + 512*9);
    int b = blockIdx.y, q0 = blockIdx.x*128, tid = threadIdx.x;
    for (int i=tid; i<NNp/4; i+=512)
        ((float4*)sqs)[i] = ((const float4*)(SQ + (size_t)b*NNp))[i];
    __syncthreads();

    int qloc = tid>>2, sub = tid&3;
    const float* gq = G + ((size_t)b*NNp + q0 + qloc)*NNp;
    const float NEGINF = __int_as_float(0xff800000);
    float tv[9]; int tix[9];
#pragma unroll
    for (int k=0;k<9;k++){ tv[k]=NEGINF; tix[k]=0x7fffffff; }

    for (int ct=0; ct<32; ct++){
        int cb = ct*128 + sub*32;
        const float4* gp = (const float4*)(gq + cb);
        const float4* sp = (const float4*)(sqs + cb);
#pragma unroll
        for (int i=0;i<8;i++){
            float4 g = gp[i]; float4 s = sp[i];
            int jg = cb + i*4;
            float k0 = fmaf(g.x, 2.f, -s.x);
            float k1 = fmaf(g.y, 2.f, -s.y);
            float k2 = fmaf(g.z, 2.f, -s.z);
            float k3 = fmaf(g.w, 2.f, -s.w);
            INS1(tv, tix, k0, jg);
            INS1(tv, tix, k1, jg+1);
            INS1(tv, tix, k2, jg+2);
            INS1(tv, tix, k3, jg+3);
        }
    }
#pragma unroll
    for (int k=0;k<9;k++){ LV[tid*9+k]=tv[k]; LI[tid*9+k]=tix[k]; }
    __syncthreads();
    if (tid < 128){
        int h[4]={0,0,0,0};
        const float* lv = LV + (size_t)(tid*4)*9;
        const int*   li = LI + (size_t)(tid*4)*9;
        int* dst = IDX + ((size_t)b*NNp + q0 + tid)*9;
#pragma unroll
        for (int k=0;k<9;k++){
            float bv=NEGINF; int bi=0x7fffffff; int bs=0;
#pragma unroll
            for (int s=0;s<4;s++){
                float v=lv[s*9+h[s]]; int ix=li[s*9+h[s]];
                if (v>bv || (v==bv && ix<bi)){ bv=v; bi=ix; bs=s; }
            }
#pragma unroll
            for (int s=0;s<4;s++) if (s==bs) h[s]++;
            dst[k]=bi;
        }
    }
}

// ===================== per-tap GEMMs (2 blocks/SM) ==========================
__global__ void __launch_bounds__(256,2) pc_gemm(const float* __restrict__ X,
        const float* __restrict__ W4, float* __restrict__ out){
    __shared__ float As[16*TW], Bs[16*TW];
    int slot=blockIdx.z, b=blockIdx.y, n0=blockIdx.x*128, tid=threadIdx.x;
    const float* Xb = X + (size_t)b*CC*NNp;
    const float* Wd = W4 + (size_t)slot*CC*CC;
    int tr=tid>>4, tc=tid&15, r0=tr*4, c0=tc*4;
    ull acc[8][4];
#pragma unroll
    for(int i=0;i<8;i++)
#pragma unroll
        for(int j=0;j<4;j++) acc[i][j]=0ULL;
    for (int kk=0; kk<128; kk+=16){
        for (int i=tid;i<512;i+=256){
            int k=i>>5, n4=(i&31)*4;
            *(float4*)&As[k*TW+n4] = *(const float4*)(Xb + (size_t)(kk+k)*NNp + n0 + n4);
        }
        for (int i=tid;i<512;i+=256){
            int m=i>>2, k4=(i&3)*4;
            float4 v = *(const float4*)(Wd + m*128 + kk + k4);
            Bs[(k4+0)*TW+m]=v.x; Bs[(k4+1)*TW+m]=v.y; Bs[(k4+2)*TW+m]=v.z; Bs[(k4+3)*TW+m]=v.w;
        }
        __syncthreads();
#pragma unroll
        for (int k=0;k<16;k++){
            const float* ar = As + k*TW; const float* br = Bs + k*TW;
            float4 a0 = *(const float4*)(ar+r0);
            float4 a1 = *(const float4*)(ar+r0+64);
            ulonglong2 b0 = *(const ulonglong2*)(br+c0);
            ulonglong2 b1 = *(const ulonglong2*)(br+c0+64);
            ull av[8]={pack2(a0.x),pack2(a0.y),pack2(a0.z),pack2(a0.w),
                       pack2(a1.x),pack2(a1.y),pack2(a1.z),pack2(a1.w)};
            ull bv[4]={b0.x,b0.y,b1.x,b1.y};
#pragma unroll
            for (int i=0;i<8;i++)
#pragma unroll
                for (int j=0;j<4;j++) fma2(acc[i][j], av[i], bv[j]);
        }
        __syncthreads();
    }
    float* obase = out + (((size_t)slot*BB+b)*NNp + n0)*128;
#pragma unroll
    for (int i=0;i<8;i++){
        int row=(i<4)? r0+i : r0+60+i;
#pragma unroll
        for (int j=0;j<4;j++){
            int cj=(j<2)? c0+2*j : c0+60+2*j;
            *(float2*)(obase + (size_t)row*128 + cj) = unp(acc[i][j]);
        }
    }
}

// ===================== gather + edge-conv epilogue ==========================
__global__ void __launch_bounds__(256) gather_kernel(const float* __restrict__ PC,
        const int* __restrict__ IDX, const float* __restrict__ b_l1,
        const float* __restrict__ s_l1, const float* __restrict__ t_l1,
        float* __restrict__ H){
    int b=blockIdx.y;
    int o=threadIdx.x&127, sub=threadIdx.x>>7;
    float bb=b_l1[o], ss=s_l1[o], tt=t_l1[o];
    const float* P0 = PC + ((size_t)0*BB+b)*NNp*128;
    const float* P1 = PC + ((size_t)1*BB+b)*NNp*128;
    const float* P2 = PC + ((size_t)2*BB+b)*NNp*128;
    const float* P3 = PC + ((size_t)3*BB+b)*NNp*128;
    for (int it=0; it<4; it++){
        int n = blockIdx.x*8 + it*2 + sub;
        const int* id = IDX + ((size_t)b*NNp+n)*9;
        float c0v = P0[(size_t)n*128+o];
#pragma unroll
        for (int j=0;j<3;j++){
            int i0=id[3*j], i1=id[3*j+1], i2=id[3*j+2];
            float v = c0v - P1[(size_t)i0*128+o] - P2[(size_t)i1*128+o] - P3[(size_t)i2*128+o];
            H[(((size_t)b*NNp+n)*3+j)*128+o] = fmaxf(ss*(v+bb)+tt,0.f);
        }
    }
}

// ===================== global branch ========================================
__global__ void mean_kernel(const float* __restrict__ x1, float* __restrict__ g0){
    int c=blockIdx.x, b=blockIdx.y;
    const float* p = x1 + ((size_t)b*CC+c)*NNp;
    float s=0.f;
    for (int i=threadIdx.x;i<NNp;i+=256) s+=p[i];
    __shared__ float sm[8];
    for (int o=16;o;o>>=1) s+=__shfl_down_sync(~0u,s,o);
    if ((threadIdx.x&31)==0) sm[threadIdx.x>>5]=s;
    __syncthreads();
    if (threadIdx.x<8){
        s=sm[threadIdx.x];
        for (int o=4;o;o>>=1) s+=__shfl_down_sync(0xffu,s,o);
        if (threadIdx.x==0) g0[b*CC+c]=s*(1.f/NNp);
    }
}
__global__ void glob_kernel(const float* __restrict__ g0,
        const float* __restrict__ wg1,const float* __restrict__ bg1,
        const float* __restrict__ sg1,const float* __restrict__ tg1,
        const float* __restrict__ wg2,const float* __restrict__ bg2,
        const float* __restrict__ sg2,const float* __restrict__ tg2,
        float* __restrict__ g2){
    __shared__ float s0[128], s1[32];
    int b=blockIdx.x, t=threadIdx.x;
    s0[t]=g0[b*128+t]; __syncthreads();
    if (t<32){
        float a=0.f;
        for (int c=0;c<128;c++) a+=s0[c]*wg1[t*128+c];
        s1[t]=fmaxf(sg1[t]*(a+bg1[t])+tg1[t],0.f);
    }
    __syncthreads();
    float a=0.f;
    for (int i=0;i<32;i++) a+=s1[i]*wg2[t*32+i];
    g2[b*128+t]=sg2[t]*(a+bg2[t])+tg2[t];
}

// ===================== h2 GEMM (128 p x 64 n tiles, K=384) + sigmoid ========
__global__ void __launch_bounds__(256) h2_gemm(const float* __restrict__ H,
        const float* __restrict__ Wl2, const float* __restrict__ bl2,
        const float* __restrict__ sl2, const float* __restrict__ tl2,
        const float* __restrict__ g2, float* __restrict__ out){
    __shared__ float As[16*TW], Bs[16*68];
    int b=blockIdx.y, n0=blockIdx.x*64, tid=threadIdx.x;
    const float* Hb = H + ((size_t)b*NNp+n0)*384;
    int tr=tid>>4, tc=tid&15, r0=tr*4, c0=tc*2;
    ull acc[8][2];
#pragma unroll
    for(int i=0;i<8;i++){ acc[i][0]=0ULL; acc[i][1]=0ULL; }
    for (int kk=0; kk<384; kk+=16){
        for (int i=tid;i<512;i+=256){               // Wl2[p][k] -> As[k][p]
            int m=i>>2, k4=(i&3)*4;
            float4 v = *(const float4*)(Wl2 + m*384 + kk + k4);
            As[(k4+0)*TW+m]=v.x; As[(k4+1)*TW+m]=v.y; As[(k4+2)*TW+m]=v.z; As[(k4+3)*TW+m]=v.w;
        }
        {
            int i=tid;                               // H[n][k] -> Bs[k][n] (16x64)
            int n=i>>2, k4=(i&3)*4;
            float4 v = *(const float4*)(Hb + (size_t)n*384 + kk + k4);
            Bs[(k4+0)*68+n]=v.x; Bs[(k4+1)*68+n]=v.y; Bs[(k4+2)*68+n]=v.z; Bs[(k4+3)*68+n]=v.w;
        }
        __syncthreads();
#pragma unroll
        for (int k=0;k<16;k++){
            const float* ar = As + k*TW; const float* br = Bs + k*68;
            float4 a0 = *(const float4*)(ar+r0);
            float4 a1 = *(const float4*)(ar+r0+64);
            ull b0 = *(const ull*)(br+c0);
            ull b1 = *(const ull*)(br+c0+32);
            ull av[8]={pack2(a0.x),pack2(a0.y),pack2(a0.z),pack2(a0.w),
                       pack2(a1.x),pack2(a1.y),pack2(a1.z),pack2(a1.w)};
#pragma unroll
            for (int i=0;i<8;i++){ fma2(acc[i][0],av[i],b0); fma2(acc[i][1],av[i],b1); }
        }
        __syncthreads();
    }
#pragma unroll
    for (int i=0;i<8;i++){
        int p=(i<4)? r0+i : r0+60+i;
        float bb=bl2[p], ss=sl2[p], tt=tl2[p], gg=g2[b*128+p];
        float* orow = out + ((size_t)b*CC+p)*NNp + n0;
#pragma unroll
        for (int j=0;j<2;j++){
            int cj=c0+j*32;
            float2 v=unp(acc[i][j]);
            float l0=fmaxf(ss*(v.x+bb)+tt,0.f);
            float l1=fmaxf(ss*(v.y+bb)+tt,0.f);
            float2 o;
            o.x = 1.f/(1.f+__expf(-(gg+l0)));
            o.y = 1.f/(1.f+__expf(-(gg+l1)));
            *(float2*)(orow+cj)=o;
        }
    }
}

extern "C" void kernel_launch(void* const* d_in, const int* in_sizes, int n_in,
                              void* d_out, int out_size){
    const float* x    = (const float*)d_in[0];
    const float* w_be = (const float*)d_in[1];
    const float* b_be = (const float*)d_in[2];
    const float* s_be = (const float*)d_in[3];
    const float* t_be = (const float*)d_in[4];
    const float* w_kn = (const float*)d_in[5];
    const float* b_kn = (const float*)d_in[6];
    const float* s_kn = (const float*)d_in[7];
    const float* t_kn = (const float*)d_in[8];
    const float* w_g1 = (const float*)d_in[9];
    const float* b_g1 = (const float*)d_in[10];
    const float* s_g1 = (const float*)d_in[11];
    const float* t_g1 = (const float*)d_in[12];
    const float* w_g2 = (const float*)d_in[13];
    const float* b_g2 = (const float*)d_in[14];
    const float* s_g2 = (const float*)d_in[15];
    const float* t_g2 = (const float*)d_in[16];
    const float* w_l1 = (const float*)d_in[17];
    const float* b_l1 = (const float*)d_in[18];
    const float* s_l1 = (const float*)d_in[19];
    const float* t_l1 = (const float*)d_in[20];
    const float* w_l2 = (const float*)d_in[21];
    const float* b_l2 = (const float*)d_in[22];
    const float* s_l2 = (const float*)d_in[23];
    const float* t_l2 = (const float*)d_in[24];
    float* out = (float*)d_out;

    float *x1, *xf, *sq, *G, *PC, *H, *g0, *g2, *W4, *Wl2; int *idx;
    cudaGetSymbolAddress((void**)&x1, g_x1);
    cudaGetSymbolAddress((void**)&xf, g_xf);
    cudaGetSymbolAddress((void**)&sq, g_sq);
    cudaGetSymbolAddress((void**)&idx, g_idx);
    cudaGetSymbolAddress((void**)&G, g_G);
    cudaGetSymbolAddress((void**)&PC, g_PC);
    cudaGetSymbolAddress((void**)&H, g_h);
    cudaGetSymbolAddress((void**)&W4, g_W4);
    cudaGetSymbolAddress((void**)&Wl2, g_Wl2);
    cudaGetSymbolAddress((void**)&g0, g_g0);
    cudaGetSymbolAddress((void**)&g2, g_g2);

    const int ks_smem = 2*128*KS_TW*4;              // 135168 B
    cudaFuncSetAttribute(knn_sym, cudaFuncAttributeMaxDynamicSharedMemorySize, ks_smem);
    const int sel_smem = (NNp + 512*9)*4 + 512*9*4; // 53248 B
    cudaFuncSetAttribute(knn_select, cudaFuncAttributeMaxDynamicSharedMemorySize, sel_smem);

    prep_kernel<<<256,256>>>(w_l1, w_l2);
    pw_gemm<<<dim3(64,BB),256>>>(x,  w_be, b_be, s_be, t_be, x1);
    pw_gemm<<<dim3(64,BB),256>>>(x1, w_kn, b_kn, s_kn, t_kn, xf);
    knn_sym<<<dim3(32,32,BB),512,ks_smem>>>(xf, G);   // 4th launch -> ncu
    sq_kernel<<<dim3(16,BB),256>>>(xf, sq);
    knn_select<<<dim3(32,BB),512,sel_smem>>>(G, sq, idx);
    pc_gemm<<<dim3(32,BB,4),256>>>(xf, W4, PC);
    gather_kernel<<<dim3(512,BB),256>>>(PC, idx, b_l1, s_l1, t_l1, H);
    mean_kernel<<<dim3(128,BB),256>>>(x1, g0);
    glob_kernel<<<BB,128>>>(g0, w_g1,b_g1,s_g1,t_g1, w_g2,b_g2,s_g2,t_g2, g2);
    h2_gemm<<<dim3(64,BB),256>>>(H, Wl2, b_l2, s_l2, t_l2, g2, out);
}

// round 10
// speedup vs baseline: 2.2381x; 1.2182x over previous
#include <cuda_runtime.h>
#include <math.h>
#include <cstdint>

#define BB 4
#define CC 128
#define NNp 4096
#define TW 132
#define KS_TW 132
typedef unsigned long long ull;
typedef unsigned int uint32;

__device__ float g_x1[BB*CC*NNp];
__device__ float g_xf[BB*CC*NNp];
__device__ float g_sq[BB*NNp];
__device__ int   g_idx[BB*NNp*9];
__device__ float g_G[(size_t)BB*NNp*NNp];   // 256 MB raw dot products
__device__ float g_PC[4*BB*NNp*CC];
__device__ float g_h[BB*NNp*3*CC];
__device__ float g_W4[4*CC*CC];
__device__ float g_Wl2[CC*3*CC];
__device__ float g_g0[BB*CC];
__device__ float g_g2[BB*CC];

// ===================== f32x2 helpers ========================================
__device__ __forceinline__ ull pack2(float a){
    ull r; unsigned ai=__float_as_uint(a);
    asm("mov.b64 %0, {%1, %2};" : "=l"(r) : "r"(ai), "r"(ai));
    return r;
}
__device__ __forceinline__ void fma2(ull &d, ull a, ull b){
    asm("fma.rn.f32x2 %0, %1, %2, %0;" : "+l"(d) : "l"(a), "l"(b));
}
__device__ __forceinline__ float2 unp(ull v){ union{ull u; float2 f;}c; c.u=v; return c.f; }

__device__ __forceinline__ uint32 smem_u32(const void* p){
    uint32 a;
    asm("{ .reg .u64 t; cvta.to.shared.u64 t, %1; cvt.u32.u64 %0, t; }" : "=r"(a) : "l"(p));
    return a;
}
__device__ __forceinline__ void cpa16(uint32 dst, const void* src){
    asm volatile("cp.async.ca.shared.global [%0], [%1], 16;" :: "r"(dst), "l"(src));
}
#define CP_COMMIT() asm volatile("cp.async.commit_group;" ::: "memory")
#define CP_WAIT0()  asm volatile("cp.async.wait_group 0;" ::: "memory")

#define INS1(tv, tix, val, jg) do{ \
  if ((val)>(tv)[8] || ((val)==(tv)[8] && (jg)<(tix)[8])){ \
    (tv)[8]=(val); (tix)[8]=(jg); \
    _Pragma("unroll") for (int p_=8;p_>0;--p_){ \
      bool sw_=((tv)[p_]>(tv)[p_-1])||((tv)[p_]==(tv)[p_-1]&&(tix)[p_]<(tix)[p_-1]); \
      if (sw_){ float fv_=(tv)[p_];(tv)[p_]=(tv)[p_-1];(tv)[p_-1]=fv_; \
               int iv_=(tix)[p_];(tix)[p_]=(tix)[p_-1];(tix)[p_-1]=iv_; } } } }while(0)

// ===================== weight prep ==========================================
__global__ void prep_kernel(const float* __restrict__ wl1, const float* __restrict__ wl2){
    for (int i = blockIdx.x*256 + threadIdx.x; i < 4*CC*CC; i += gridDim.x*256){
        int slot=i>>14, rem=i&16383, o=rem>>7, c=rem&127;
        float v;
        if (slot==0){
            v=0.f;
#pragma unroll
            for (int w=0;w<3;w++) v += wl1[(o*256+c)*3+w] + wl1[(o*256+128+c)*3+w];
        } else v = wl1[(o*256+128+c)*3+(slot-1)];
        g_W4[i]=v;
    }
    for (int i = blockIdx.x*256 + threadIdx.x; i < CC*3*CC; i += gridDim.x*256){
        int p=i/384, k=i%384, w=k>>7, o=k&127;
        g_Wl2[i] = wl2[(p*128+o)*3+w];
    }
}

// ===================== pointwise conv (+ optional fused sq) =================
__global__ void __launch_bounds__(256) pw_gemm(const float* __restrict__ X,
        const float* __restrict__ W, const float* __restrict__ bias,
        const float* __restrict__ sc, const float* __restrict__ tr_,
        float* __restrict__ out, float* __restrict__ sqOut){
    __shared__ float As[16*TW], Bs[16*68];
    int b=blockIdx.y, n0=blockIdx.x*64, tid=threadIdx.x;
    const float* Xb = X + (size_t)b*CC*NNp;
    int tr=tid>>4, tc=tid&15, r0=tr*4, c0=tc*2;
    ull acc[8][2];
#pragma unroll
    for(int i=0;i<8;i++){ acc[i][0]=0ULL; acc[i][1]=0ULL; }
    for (int kk=0; kk<128; kk+=16){
        for (int i=tid;i<512;i+=256){               // W[o][c] -> As[c][o]
            int m=i>>2, k4=(i&3)*4;
            float4 v = *(const float4*)(W + m*128 + kk + k4);
            As[(k4+0)*TW+m]=v.x; As[(k4+1)*TW+m]=v.y; As[(k4+2)*TW+m]=v.z; As[(k4+3)*TW+m]=v.w;
        }
        {
            int i=tid;                               // X[c][n] -> Bs[c][n] (16x64)
            int k=i>>4, n4=(i&15)*4;
            *(float4*)&Bs[k*68+n4] = *(const float4*)(Xb + (size_t)(kk+k)*NNp + n0 + n4);
        }
        __syncthreads();
#pragma unroll
        for (int k=0;k<16;k++){
            const float* ar = As + k*TW; const float* br = Bs + k*68;
            float4 a0 = *(const float4*)(ar+r0);
            float4 a1 = *(const float4*)(ar+r0+64);
            ull b0 = *(const ull*)(br+c0);
            ull b1 = *(const ull*)(br+c0+32);
            ull av[8]={pack2(a0.x),pack2(a0.y),pack2(a0.z),pack2(a0.w),
                       pack2(a1.x),pack2(a1.y),pack2(a1.z),pack2(a1.w)};
#pragma unroll
            for (int i=0;i<8;i++){ fma2(acc[i][0],av[i],b0); fma2(acc[i][1],av[i],b1); }
        }
        __syncthreads();
    }
    float s0=0.f, s1=0.f, s2=0.f, s3=0.f;
#pragma unroll
    for (int i=0;i<8;i++){
        int row = (i<4)? r0+i : r0+60+i;
        float bb=bias[row], ss=sc[row], tt=tr_[row];
        float* orow = out + ((size_t)b*CC+row)*NNp + n0;
        float2 v0=unp(acc[i][0]), v1=unp(acc[i][1]);
        float o0=fmaxf(ss*(v0.x+bb)+tt,0.f);
        float o1=fmaxf(ss*(v0.y+bb)+tt,0.f);
        float o2=fmaxf(ss*(v1.x+bb)+tt,0.f);
        float o3=fmaxf(ss*(v1.y+bb)+tt,0.f);
        *(float2*)(orow+c0)    = make_float2(o0,o1);
        *(float2*)(orow+c0+32) = make_float2(o2,o3);
        s0=fmaf(o0,o0,s0); s1=fmaf(o1,o1,s1); s2=fmaf(o2,o2,s2); s3=fmaf(o3,o3,s3);
    }
    if (sqOut){
        // reduce over tr (16) via smem (reuse As)
        float* red = As;             // 16*64 floats
        red[tr*64 + c0]      = s0;
        red[tr*64 + c0 + 1]  = s1;
        red[tr*64 + c0 + 32] = s2;
        red[tr*64 + c0 + 33] = s3;
        __syncthreads();
        if (tid < 64){
            float s=0.f;
#pragma unroll
            for (int t=0;t<16;t++) s += red[t*64 + tid];
            sqOut[(size_t)b*NNp + n0 + tid] = s;
        }
    }
}

// ===================== symmetric Gram -> gmem dot matrix ====================
extern __shared__ float ksm[];
__global__ void __launch_bounds__(512,1) knn_sym(const float* __restrict__ XF,
        float* __restrict__ G){
    int ti=blockIdx.x, tj=blockIdx.y, b=blockIdx.z;
    if (tj < ti) return;
    float* As = ksm;
    float* Bs = ksm + 128*KS_TW;
    uint32 smb = smem_u32(ksm);
    int tid = threadIdx.x;
    const float* Xb = XF + (size_t)b*CC*NNp;

    uint32 aB = smb, bB = smb + 128*KS_TW*4;
#pragma unroll
    for (int j=0;j<8;j++){
        int idx = tid + 512*j;
        int c = idx>>5, q4 = idx&31;
        uint32 off = (uint32)(c*KS_TW + q4*4)*4u;
        cpa16(aB + off, Xb + (size_t)c*NNp + ti*128 + q4*4);
        cpa16(bB + off, Xb + (size_t)c*NNp + tj*128 + q4*4);
    }
    CP_COMMIT(); CP_WAIT0();
    __syncthreads();

    int r0 = (tid>>4)*4, c0 = (tid&15)*4;
    ull acc[4][4];
#pragma unroll
    for (int i=0;i<4;i++)
#pragma unroll
        for (int j=0;j<4;j++) acc[i][j]=0ULL;
#pragma unroll 4
    for (int k=0;k<128;k++){
        const float* ar = As + k*KS_TW;
        const float* br = Bs + k*KS_TW;
        float4 a = *(const float4*)(ar + r0);
        ulonglong2 b0 = *(const ulonglong2*)(br + c0);
        ulonglong2 b1 = *(const ulonglong2*)(br + c0 + 64);
        ull av[4] = {pack2(a.x),pack2(a.y),pack2(a.z),pack2(a.w)};
        ull bv[4] = {b0.x,b0.y,b1.x,b1.y};
#pragma unroll
        for (int i=0;i<4;i++)
#pragma unroll
            for (int j=0;j<4;j++) fma2(acc[i][j], av[i], bv[j]);
    }

    float vals[4][8];
#pragma unroll
    for (int i=0;i<4;i++){
        float2 v0=unp(acc[i][0]), v1=unp(acc[i][1]);
        float2 v2=unp(acc[i][2]), v3=unp(acc[i][3]);
        vals[i][0]=v0.x; vals[i][1]=v0.y; vals[i][2]=v1.x; vals[i][3]=v1.y;
        vals[i][4]=v2.x; vals[i][5]=v2.y; vals[i][6]=v3.x; vals[i][7]=v3.y;
    }

    float* Grow = G + ((size_t)b*NNp + (size_t)ti*128)*NNp + (size_t)tj*128;
#pragma unroll
    for (int i=0;i<4;i++){
        float* p = Grow + (size_t)(r0+i)*NNp;
        *(float4*)(p + c0)      = make_float4(vals[i][0],vals[i][1],vals[i][2],vals[i][3]);
        *(float4*)(p + c0 + 64) = make_float4(vals[i][4],vals[i][5],vals[i][6],vals[i][7]);
    }

    if (ti != tj){
        float* Gcol = G + ((size_t)b*NNp + (size_t)tj*128)*NNp + (size_t)ti*128;
#pragma unroll
        for (int cl=0; cl<8; cl++){
            int c = (cl<4)? (c0+cl) : (c0+60+cl);
            float4 t = make_float4(vals[0][cl], vals[1][cl], vals[2][cl], vals[3][cl]);
            *(float4*)(Gcol + (size_t)c*NNp + r0) = t;
        }
    }
}

// ===================== streaming top-9 selection ============================
// 64 queries/block, 8 threads/query. dyn smem: sqs[4096] | LV[512*9] | LI[512*9]
extern __shared__ float sel_sm[];
__global__ void __launch_bounds__(512,1) knn_select(const float* __restrict__ G,
        const float* __restrict__ SQ, int* __restrict__ IDX){
    float* sqs = sel_sm;
    float* LV  = sel_sm + NNp;
    int*   LI  = (int*)(sel_sm + NNp + 512*9);
    int b = blockIdx.y, q0 = blockIdx.x*64, tid = threadIdx.x;
    for (int i=tid; i<NNp/4; i+=512)
        ((float4*)sqs)[i] = ((const float4*)(SQ + (size_t)b*NNp))[i];
    __syncthreads();

    int qloc = tid>>3, sub = tid&7;
    const float* gq = G + ((size_t)b*NNp + q0 + qloc)*NNp;
    const float NEGINF = __int_as_float(0xff800000);
    float tv[9]; int tix[9];
#pragma unroll
    for (int k=0;k<9;k++){ tv[k]=NEGINF; tix[k]=0x7fffffff; }

    for (int ct=0; ct<32; ct++){
        int cb = ct*128 + sub*16;
        const float4* gp = (const float4*)(gq + cb);
        const float4* sp = (const float4*)(sqs + cb);
#pragma unroll
        for (int i=0;i<4;i++){
            float4 g = __ldcs(gp + i);
            float4 s = sp[i];
            int jg = cb + i*4;
            float k0 = fmaf(g.x, 2.f, -s.x);
            float k1 = fmaf(g.y, 2.f, -s.y);
            float k2 = fmaf(g.z, 2.f, -s.z);
            float k3 = fmaf(g.w, 2.f, -s.w);
            INS1(tv, tix, k0, jg);
            INS1(tv, tix, k1, jg+1);
            INS1(tv, tix, k2, jg+2);
            INS1(tv, tix, k3, jg+3);
        }
    }
#pragma unroll
    for (int k=0;k<9;k++){ LV[tid*9+k]=tv[k]; LI[tid*9+k]=tix[k]; }
    __syncthreads();
    if (tid < 64){
        int h[8]={0,0,0,0,0,0,0,0};
        const float* lv = LV + (size_t)(tid*8)*9;
        const int*   li = LI + (size_t)(tid*8)*9;
        int* dst = IDX + ((size_t)b*NNp + q0 + tid)*9;
#pragma unroll
        for (int k=0;k<9;k++){
            float bv=NEGINF; int bi=0x7fffffff; int bs=0;
#pragma unroll
            for (int s=0;s<8;s++){
                float v=lv[s*9+h[s]]; int ix=li[s*9+h[s]];
                if (v>bv || (v==bv && ix<bi)){ bv=v; bi=ix; bs=s; }
            }
#pragma unroll
            for (int s=0;s<8;s++) if (s==bs) h[s]++;
            dst[k]=bi;
        }
    }
}

// ===================== per-tap GEMMs (2 blocks/SM) ==========================
__global__ void __launch_bounds__(256,2) pc_gemm(const float* __restrict__ X,
        const float* __restrict__ W4, float* __restrict__ out){
    __shared__ float As[16*TW], Bs[16*TW];
    int slot=blockIdx.z, b=blockIdx.y, n0=blockIdx.x*128, tid=threadIdx.x;
    const float* Xb = X + (size_t)b*CC*NNp;
    const float* Wd = W4 + (size_t)slot*CC*CC;
    int tr=tid>>4, tc=tid&15, r0=tr*4, c0=tc*4;
    ull acc[8][4];
#pragma unroll
    for(int i=0;i<8;i++)
#pragma unroll
        for(int j=0;j<4;j++) acc[i][j]=0ULL;
    for (int kk=0; kk<128; kk+=16){
        for (int i=tid;i<512;i+=256){
            int k=i>>5, n4=(i&31)*4;
            *(float4*)&As[k*TW+n4] = *(const float4*)(Xb + (size_t)(kk+k)*NNp + n0 + n4);
        }
        for (int i=tid;i<512;i+=256){
            int m=i>>2, k4=(i&3)*4;
            float4 v = *(const float4*)(Wd + m*128 + kk + k4);
            Bs[(k4+0)*TW+m]=v.x; Bs[(k4+1)*TW+m]=v.y; Bs[(k4+2)*TW+m]=v.z; Bs[(k4+3)*TW+m]=v.w;
        }
        __syncthreads();
#pragma unroll
        for (int k=0;k<16;k++){
            const float* ar = As + k*TW; const float* br = Bs + k*TW;
            float4 a0 = *(const float4*)(ar+r0);
            float4 a1 = *(const float4*)(ar+r0+64);
            ulonglong2 b0 = *(const ulonglong2*)(br+c0);
            ulonglong2 b1 = *(const ulonglong2*)(br+c0+64);
            ull av[8]={pack2(a0.x),pack2(a0.y),pack2(a0.z),pack2(a0.w),
                       pack2(a1.x),pack2(a1.y),pack2(a1.z),pack2(a1.w)};
            ull bv[4]={b0.x,b0.y,b1.x,b1.y};
#pragma unroll
            for (int i=0;i<8;i++)
#pragma unroll
                for (int j=0;j<4;j++) fma2(acc[i][j], av[i], bv[j]);
        }
        __syncthreads();
    }
    float* obase = out + (((size_t)slot*BB+b)*NNp + n0)*128;
#pragma unroll
    for (int i=0;i<8;i++){
        int row=(i<4)? r0+i : r0+60+i;
#pragma unroll
        for (int j=0;j<4;j++){
            int cj=(j<2)? c0+2*j : c0+60+2*j;
            *(float2*)(obase + (size_t)row*128 + cj) = unp(acc[i][j]);
        }
    }
}

// ===================== gather + edge-conv epilogue ==========================
__global__ void __launch_bounds__(256) gather_kernel(const float* __restrict__ PC,
        const int* __restrict__ IDX, const float* __restrict__ b_l1,
        const float* __restrict__ s_l1, const float* __restrict__ t_l1,
        float* __restrict__ H){
    int b=blockIdx.y;
    int o=threadIdx.x&127, sub=threadIdx.x>>7;
    float bb=b_l1[o], ss=s_l1[o], tt=t_l1[o];
    const float* P0 = PC + ((size_t)0*BB+b)*NNp*128;
    const float* P1 = PC + ((size_t)1*BB+b)*NNp*128;
    const float* P2 = PC + ((size_t)2*BB+b)*NNp*128;
    const float* P3 = PC + ((size_t)3*BB+b)*NNp*128;
    for (int it=0; it<4; it++){
        int n = blockIdx.x*8 + it*2 + sub;
        const int* id = IDX + ((size_t)b*NNp+n)*9;
        float c0v = P0[(size_t)n*128+o];
#pragma unroll
        for (int j=0;j<3;j++){
            int i0=id[3*j], i1=id[3*j+1], i2=id[3*j+2];
            float v = c0v - P1[(size_t)i0*128+o] - P2[(size_t)i1*128+o] - P3[(size_t)i2*128+o];
            H[(((size_t)b*NNp+n)*3+j)*128+o] = fmaxf(ss*(v+bb)+tt,0.f);
        }
    }
}

// ===================== global branch ========================================
__global__ void mean_kernel(const float* __restrict__ x1, float* __restrict__ g0){
    int c=blockIdx.x, b=blockIdx.y;
    const float* p = x1 + ((size_t)b*CC+c)*NNp;
    float s=0.f;
    for (int i=threadIdx.x;i<NNp;i+=256) s+=p[i];
    __shared__ float sm[8];
    for (int o=16;o;o>>=1) s+=__shfl_down_sync(~0u,s,o);
    if ((threadIdx.x&31)==0) sm[threadIdx.x>>5]=s;
    __syncthreads();
    if (threadIdx.x<8){
        s=sm[threadIdx.x];
        for (int o=4;o;o>>=1) s+=__shfl_down_sync(0xffu,s,o);
        if (threadIdx.x==0) g0[b*CC+c]=s*(1.f/NNp);
    }
}
__global__ void glob_kernel(const float* __restrict__ g0,
        const float* __restrict__ wg1,const float* __restrict__ bg1,
        const float* __restrict__ sg1,const float* __restrict__ tg1,
        const float* __restrict__ wg2,const float* __restrict__ bg2,
        const float* __restrict__ sg2,const float* __restrict__ tg2,
        float* __restrict__ g2){
    __shared__ float s0[128], s1[32];
    int b=blockIdx.x, t=threadIdx.x;
    s0[t]=g0[b*128+t]; __syncthreads();
    if (t<32){
        float a=0.f;
        for (int c=0;c<128;c++) a+=s0[c]*wg1[t*128+c];
        s1[t]=fmaxf(sg1[t]*(a+bg1[t])+tg1[t],0.f);
    }
    __syncthreads();
    float a=0.f;
    for (int i=0;i<32;i++) a+=s1[i]*wg2[t*32+i];
    g2[b*128+t]=sg2[t]*(a+bg2[t])+tg2[t];
}

// ===================== h2 GEMM (K=384) + sigmoid ============================
__global__ void __launch_bounds__(256) h2_gemm(const float* __restrict__ H,
        const float* __restrict__ Wl2, const float* __restrict__ bl2,
        const float* __restrict__ sl2, const float* __restrict__ tl2,
        const float* __restrict__ g2, float* __restrict__ out){
    __shared__ float As[16*TW], Bs[16*68];
    int b=blockIdx.y, n0=blockIdx.x*64, tid=threadIdx.x;
    const float* Hb = H + ((size_t)b*NNp+n0)*384;
    int tr=tid>>4, tc=tid&15, r0=tr*4, c0=tc*2;
    ull acc[8][2];
#pragma unroll
    for(int i=0;i<8;i++){ acc[i][0]=0ULL; acc[i][1]=0ULL; }
    for (int kk=0; kk<384; kk+=16){
        for (int i=tid;i<512;i+=256){
            int m=i>>2, k4=(i&3)*4;
            float4 v = *(const float4*)(Wl2 + m*384 + kk + k4);
            As[(k4+0)*TW+m]=v.x; As[(k4+1)*TW+m]=v.y; As[(k4+2)*TW+m]=v.z; As[(k4+3)*TW+m]=v.w;
        }
        {
            int i=tid;
            int n=i>>2, k4=(i&3)*4;
            float4 v = *(const float4*)(Hb + (size_t)n*384 + kk + k4);
            Bs[(k4+0)*68+n]=v.x; Bs[(k4+1)*68+n]=v.y; Bs[(k4+2)*68+n]=v.z; Bs[(k4+3)*68+n]=v.w;
        }
        __syncthreads();
#pragma unroll
        for (int k=0;k<16;k++){
            const float* ar = As + k*TW; const float* br = Bs + k*68;
            float4 a0 = *(const float4*)(ar+r0);
            float4 a1 = *(const float4*)(ar+r0+64);
            ull b0 = *(const ull*)(br+c0);
            ull b1 = *(const ull*)(br+c0+32);
            ull av[8]={pack2(a0.x),pack2(a0.y),pack2(a0.z),pack2(a0.w),
                       pack2(a1.x),pack2(a1.y),pack2(a1.z),pack2(a1.w)};
#pragma unroll
            for (int i=0;i<8;i++){ fma2(acc[i][0],av[i],b0); fma2(acc[i][1],av[i],b1); }
        }
        __syncthreads();
    }
#pragma unroll
    for (int i=0;i<8;i++){
        int p=(i<4)? r0+i : r0+60+i;
        float bb=bl2[p], ss=sl2[p], tt=tl2[p], gg=g2[b*128+p];
        float* orow = out + ((size_t)b*CC+p)*NNp + n0;
#pragma unroll
        for (int j=0;j<2;j++){
            int cj=c0+j*32;
            float2 v=unp(acc[i][j]);
            float l0=fmaxf(ss*(v.x+bb)+tt,0.f);
            float l1=fmaxf(ss*(v.y+bb)+tt,0.f);
            float2 o;
            o.x = 1.f/(1.f+__expf(-(gg+l0)));
            o.y = 1.f/(1.f+__expf(-(gg+l1)));
            *(float2*)(orow+cj)=o;
        }
    }
}

extern "C" void kernel_launch(void* const* d_in, const int* in_sizes, int n_in,
                              void* d_out, int out_size){
    const float* x    = (const float*)d_in[0];
    const float* w_be = (const float*)d_in[1];
    const float* b_be = (const float*)d_in[2];
    const float* s_be = (const float*)d_in[3];
    const float* t_be = (const float*)d_in[4];
    const float* w_kn = (const float*)d_in[5];
    const float* b_kn = (const float*)d_in[6];
    const float* s_kn = (const float*)d_in[7];
    const float* t_kn = (const float*)d_in[8];
    const float* w_g1 = (const float*)d_in[9];
    const float* b_g1 = (const float*)d_in[10];
    const float* s_g1 = (const float*)d_in[11];
    const float* t_g1 = (const float*)d_in[12];
    const float* w_g2 = (const float*)d_in[13];
    const float* b_g2 = (const float*)d_in[14];
    const float* s_g2 = (const float*)d_in[15];
    const float* t_g2 = (const float*)d_in[16];
    const float* w_l1 = (const float*)d_in[17];
    const float* b_l1 = (const float*)d_in[18];
    const float* s_l1 = (const float*)d_in[19];
    const float* t_l1 = (const float*)d_in[20];
    const float* w_l2 = (const float*)d_in[21];
    const float* b_l2 = (const float*)d_in[22];
    const float* s_l2 = (const float*)d_in[23];
    const float* t_l2 = (const float*)d_in[24];
    float* out = (float*)d_out;

    float *x1, *xf, *sq, *G, *PC, *H, *g0, *g2, *W4, *Wl2; int *idx;
    cudaGetSymbolAddress((void**)&x1, g_x1);
    cudaGetSymbolAddress((void**)&xf, g_xf);
    cudaGetSymbolAddress((void**)&sq, g_sq);
    cudaGetSymbolAddress((void**)&idx, g_idx);
    cudaGetSymbolAddress((void**)&G, g_G);
    cudaGetSymbolAddress((void**)&PC, g_PC);
    cudaGetSymbolAddress((void**)&H, g_h);
    cudaGetSymbolAddress((void**)&W4, g_W4);
    cudaGetSymbolAddress((void**)&Wl2, g_Wl2);
    cudaGetSymbolAddress((void**)&g0, g_g0);
    cudaGetSymbolAddress((void**)&g2, g_g2);

    const int ks_smem = 2*128*KS_TW*4;              // 135168 B
    cudaFuncSetAttribute(knn_sym, cudaFuncAttributeMaxDynamicSharedMemorySize, ks_smem);
    const int sel_smem = (NNp + 512*9)*4 + 512*9*4; // 53248 B
    cudaFuncSetAttribute(knn_select, cudaFuncAttributeMaxDynamicSharedMemorySize, sel_smem);

    pw_gemm<<<dim3(64,BB),256>>>(x,  w_be, b_be, s_be, t_be, x1, nullptr);
    pw_gemm<<<dim3(64,BB),256>>>(x1, w_kn, b_kn, s_kn, t_kn, xf, sq);
    knn_sym<<<dim3(32,32,BB),512,ks_smem>>>(xf, G);
    knn_select<<<dim3(64,BB),512,sel_smem>>>(G, sq, idx);  // 4th launch -> ncu
    prep_kernel<<<256,256>>>(w_l1, w_l2);
    pc_gemm<<<dim3(32,BB,4),256>>>(xf, W4, PC);
    gather_kernel<<<dim3(512,BB),256>>>(PC, idx, b_l1, s_l1, t_l1, H);
    mean_kernel<<<dim3(128,BB),256>>>(x1, g0);
    glob_kernel<<<BB,128>>>(g0, w_g1,b_g1,s_g1,t_g1, w_g2,b_g2,s_g2,t_g2, g2);
    h2_gemm<<<dim3(64,BB),256>>>(H, Wl2, b_l2, s_l2, t_l2, g2, out);
}

// round 11
// speedup vs baseline: 2.2771x; 1.0174x over previous
#include <cuda_runtime.h>
#include <math.h>
#include <cstdint>

#define BB 4
#define CC 128
#define NNp 4096
#define TW 132
#define KS_TW 132
typedef unsigned long long ull;
typedef unsigned int uint32;

__device__ float g_x1[BB*CC*NNp];
__device__ float g_xf[BB*CC*NNp];
__device__ float g_sq[BB*NNp];
__device__ int   g_idx[BB*NNp*9];
__device__ float g_G[(size_t)BB*NNp*NNp];   // 256 MB: selection keys 2*dot - sq_j
__device__ float g_PC[4*BB*NNp*CC];
__device__ float g_h[BB*NNp*3*CC];
__device__ float g_W4[4*CC*CC];
__device__ float g_Wl2[CC*3*CC];
__device__ float g_g0[BB*CC];
__device__ float g_g2[BB*CC];

// ===================== f32x2 helpers ========================================
__device__ __forceinline__ ull pack2(float a){
    ull r; unsigned ai=__float_as_uint(a);
    asm("mov.b64 %0, {%1, %2};" : "=l"(r) : "r"(ai), "r"(ai));
    return r;
}
__device__ __forceinline__ void fma2(ull &d, ull a, ull b){
    asm("fma.rn.f32x2 %0, %1, %2, %0;" : "+l"(d) : "l"(a), "l"(b));
}
__device__ __forceinline__ float2 unp(ull v){ union{ull u; float2 f;}c; c.u=v; return c.f; }

__device__ __forceinline__ uint32 smem_u32(const void* p){
    uint32 a;
    asm("{ .reg .u64 t; cvta.to.shared.u64 t, %1; cvt.u32.u64 %0, t; }" : "=r"(a) : "l"(p));
    return a;
}
__device__ __forceinline__ void cpa16(uint32 dst, const void* src){
    asm volatile("cp.async.ca.shared.global [%0], [%1], 16;" :: "r"(dst), "l"(src));
}
#define CP_COMMIT() asm volatile("cp.async.commit_group;" ::: "memory")
#define CP_WAIT0()  asm volatile("cp.async.wait_group 0;" ::: "memory")

#define INS1(tv, tix, val, jg) do{ \
  if ((val)>(tv)[8] || ((val)==(tv)[8] && (jg)<(tix)[8])){ \
    (tv)[8]=(val); (tix)[8]=(jg); \
    _Pragma("unroll") for (int p_=8;p_>0;--p_){ \
      bool sw_=((tv)[p_]>(tv)[p_-1])||((tv)[p_]==(tv)[p_-1]&&(tix)[p_]<(tix)[p_-1]); \
      if (sw_){ float fv_=(tv)[p_];(tv)[p_]=(tv)[p_-1];(tv)[p_-1]=fv_; \
               int iv_=(tix)[p_];(tix)[p_]=(tix)[p_-1];(tix)[p_-1]=iv_; } } } }while(0)

// ===================== weight prep ==========================================
__global__ void prep_kernel(const float* __restrict__ wl1, const float* __restrict__ wl2){
    for (int i = blockIdx.x*256 + threadIdx.x; i < 4*CC*CC; i += gridDim.x*256){
        int slot=i>>14, rem=i&16383, o=rem>>7, c=rem&127;
        float v;
        if (slot==0){
            v=0.f;
#pragma unroll
            for (int w=0;w<3;w++) v += wl1[(o*256+c)*3+w] + wl1[(o*256+128+c)*3+w];
        } else v = wl1[(o*256+128+c)*3+(slot-1)];
        g_W4[i]=v;
    }
    for (int i = blockIdx.x*256 + threadIdx.x; i < CC*3*CC; i += gridDim.x*256){
        int p=i/384, k=i%384, w=k>>7, o=k&127;
        g_Wl2[i] = wl2[(p*128+o)*3+w];
    }
}

// ===================== pointwise conv (+ optional fused sq) =================
__global__ void __launch_bounds__(256) pw_gemm(const float* __restrict__ X,
        const float* __restrict__ W, const float* __restrict__ bias,
        const float* __restrict__ sc, const float* __restrict__ tr_,
        float* __restrict__ out, float* __restrict__ sqOut){
    __shared__ float As[16*TW], Bs[16*68];
    int b=blockIdx.y, n0=blockIdx.x*64, tid=threadIdx.x;
    const float* Xb = X + (size_t)b*CC*NNp;
    int tr=tid>>4, tc=tid&15, r0=tr*4, c0=tc*2;
    ull acc[8][2];
#pragma unroll
    for(int i=0;i<8;i++){ acc[i][0]=0ULL; acc[i][1]=0ULL; }
    for (int kk=0; kk<128; kk+=16){
        for (int i=tid;i<512;i+=256){
            int m=i>>2, k4=(i&3)*4;
            float4 v = *(const float4*)(W + m*128 + kk + k4);
            As[(k4+0)*TW+m]=v.x; As[(k4+1)*TW+m]=v.y; As[(k4+2)*TW+m]=v.z; As[(k4+3)*TW+m]=v.w;
        }
        {
            int i=tid;
            int k=i>>4, n4=(i&15)*4;
            *(float4*)&Bs[k*68+n4] = *(const float4*)(Xb + (size_t)(kk+k)*NNp + n0 + n4);
        }
        __syncthreads();
#pragma unroll
        for (int k=0;k<16;k++){
            const float* ar = As + k*TW; const float* br = Bs + k*68;
            float4 a0 = *(const float4*)(ar+r0);
            float4 a1 = *(const float4*)(ar+r0+64);
            ull b0 = *(const ull*)(br+c0);
            ull b1 = *(const ull*)(br+c0+32);
            ull av[8]={pack2(a0.x),pack2(a0.y),pack2(a0.z),pack2(a0.w),
                       pack2(a1.x),pack2(a1.y),pack2(a1.z),pack2(a1.w)};
#pragma unroll
            for (int i=0;i<8;i++){ fma2(acc[i][0],av[i],b0); fma2(acc[i][1],av[i],b1); }
        }
        __syncthreads();
    }
    float s0=0.f, s1=0.f, s2=0.f, s3=0.f;
#pragma unroll
    for (int i=0;i<8;i++){
        int row = (i<4)? r0+i : r0+60+i;
        float bb=bias[row], ss=sc[row], tt=tr_[row];
        float* orow = out + ((size_t)b*CC+row)*NNp + n0;
        float2 v0=unp(acc[i][0]), v1=unp(acc[i][1]);
        float o0=fmaxf(ss*(v0.x+bb)+tt,0.f);
        float o1=fmaxf(ss*(v0.y+bb)+tt,0.f);
        float o2=fmaxf(ss*(v1.x+bb)+tt,0.f);
        float o3=fmaxf(ss*(v1.y+bb)+tt,0.f);
        *(float2*)(orow+c0)    = make_float2(o0,o1);
        *(float2*)(orow+c0+32) = make_float2(o2,o3);
        s0=fmaf(o0,o0,s0); s1=fmaf(o1,o1,s1); s2=fmaf(o2,o2,s2); s3=fmaf(o3,o3,s3);
    }
    if (sqOut){
        float* red = As;
        red[tr*64 + c0]      = s0;
        red[tr*64 + c0 + 1]  = s1;
        red[tr*64 + c0 + 32] = s2;
        red[tr*64 + c0 + 33] = s3;
        __syncthreads();
        if (tid < 64){
            float s=0.f;
#pragma unroll
            for (int t=0;t<16;t++) s += red[t*64 + tid];
            sqOut[(size_t)b*NNp + n0 + tid] = s;
        }
    }
}

// ===================== symmetric Gram -> gmem KEY matrix ====================
extern __shared__ float ksm[];
__global__ void __launch_bounds__(512,1) knn_sym(const float* __restrict__ XF,
        const float* __restrict__ SQ, float* __restrict__ G){
    int ti=blockIdx.x, tj=blockIdx.y, b=blockIdx.z;
    if (tj < ti) return;
    float* As = ksm;
    float* Bs = ksm + 128*KS_TW;
    uint32 smb = smem_u32(ksm);
    int tid = threadIdx.x;
    const float* Xb = XF + (size_t)b*CC*NNp;

    uint32 aB = smb, bB = smb + 128*KS_TW*4;
#pragma unroll
    for (int j=0;j<8;j++){
        int idx = tid + 512*j;
        int c = idx>>5, q4 = idx&31;
        uint32 off = (uint32)(c*KS_TW + q4*4)*4u;
        cpa16(aB + off, Xb + (size_t)c*NNp + ti*128 + q4*4);
        cpa16(bB + off, Xb + (size_t)c*NNp + tj*128 + q4*4);
    }
    CP_COMMIT(); CP_WAIT0();
    __syncthreads();

    int r0 = (tid>>4)*4, c0 = (tid&15)*4;
    ull acc[4][4];
#pragma unroll
    for (int i=0;i<4;i++)
#pragma unroll
        for (int j=0;j<4;j++) acc[i][j]=0ULL;
#pragma unroll 4
    for (int k=0;k<128;k++){
        const float* ar = As + k*KS_TW;
        const float* br = Bs + k*KS_TW;
        float4 a = *(const float4*)(ar + r0);
        ulonglong2 b0 = *(const ulonglong2*)(br + c0);
        ulonglong2 b1 = *(const ulonglong2*)(br + c0 + 64);
        ull av[4] = {pack2(a.x),pack2(a.y),pack2(a.z),pack2(a.w)};
        ull bv[4] = {b0.x,b0.y,b1.x,b1.y};
#pragma unroll
        for (int i=0;i<4;i++)
#pragma unroll
            for (int j=0;j<4;j++) fma2(acc[i][j], av[i], bv[j]);
    }

    float vals[4][8];
#pragma unroll
    for (int i=0;i<4;i++){
        float2 v0=unp(acc[i][0]), v1=unp(acc[i][1]);
        float2 v2=unp(acc[i][2]), v3=unp(acc[i][3]);
        vals[i][0]=v0.x; vals[i][1]=v0.y; vals[i][2]=v1.x; vals[i][3]=v1.y;
        vals[i][4]=v2.x; vals[i][5]=v2.y; vals[i][6]=v3.x; vals[i][7]=v3.y;
    }

    const float* SQb = SQ + (size_t)b*NNp;
    float4 sqj_lo = *(const float4*)(SQb + tj*128 + c0);
    float4 sqj_hi = *(const float4*)(SQb + tj*128 + c0 + 64);
    float4 sqi4   = *(const float4*)(SQb + ti*128 + r0);

    // row stores: key[q=i][cand=j] = fmaf(dot, 2, -sq_j)
    float* Grow = G + ((size_t)b*NNp + (size_t)ti*128)*NNp + (size_t)tj*128;
#pragma unroll
    for (int i=0;i<4;i++){
        float* p = Grow + (size_t)(r0+i)*NNp;
        *(float4*)(p + c0)      = make_float4(
            fmaf(vals[i][0],2.f,-sqj_lo.x), fmaf(vals[i][1],2.f,-sqj_lo.y),
            fmaf(vals[i][2],2.f,-sqj_lo.z), fmaf(vals[i][3],2.f,-sqj_lo.w));
        *(float4*)(p + c0 + 64) = make_float4(
            fmaf(vals[i][4],2.f,-sqj_hi.x), fmaf(vals[i][5],2.f,-sqj_hi.y),
            fmaf(vals[i][6],2.f,-sqj_hi.z), fmaf(vals[i][7],2.f,-sqj_hi.w));
    }

    // transposed stores: key[q=j][cand=i] = fmaf(dot, 2, -sq_i)
    if (ti != tj){
        float* Gcol = G + ((size_t)b*NNp + (size_t)tj*128)*NNp + (size_t)ti*128;
#pragma unroll
        for (int cl=0; cl<8; cl++){
            int c = (cl<4)? (c0+cl) : (c0+60+cl);
            float4 t = make_float4(
                fmaf(vals[0][cl],2.f,-sqi4.x), fmaf(vals[1][cl],2.f,-sqi4.y),
                fmaf(vals[2][cl],2.f,-sqi4.z), fmaf(vals[3][cl],2.f,-sqi4.w));
            *(float4*)(Gcol + (size_t)c*NNp + r0) = t;
        }
    }
}

// ===================== filtered streaming top-9 selection ===================
__global__ void __launch_bounds__(512,1) knn_select(const float* __restrict__ G,
        int* __restrict__ IDX){
    __shared__ float LV[512*9];
    __shared__ int   LI[512*9];
    int b = blockIdx.y, q0 = blockIdx.x*64, tid = threadIdx.x;
    int qloc = tid>>3, sub = tid&7;
    const float* gq = G + ((size_t)b*NNp + q0 + qloc)*NNp;
    const float NEGINF = __int_as_float(0xff800000);
    float tv[9]; int tix[9];
#pragma unroll
    for (int k=0;k<9;k++){ tv[k]=NEGINF; tix[k]=0x7fffffff; }

    for (int ct=0; ct<32; ct++){
        int cb = ct*128 + sub*16;
        const float4* gp = (const float4*)(gq + cb);
#pragma unroll
        for (int i=0;i<4;i++){
            float4 g = __ldcs(gp + i);
            float m = fmaxf(fmaxf(g.x,g.y), fmaxf(g.z,g.w));
            if (m > tv[8]){
                int jg = cb + i*4;
                INS1(tv, tix, g.x, jg);
                INS1(tv, tix, g.y, jg+1);
                INS1(tv, tix, g.z, jg+2);
                INS1(tv, tix, g.w, jg+3);
            }
        }
    }
#pragma unroll
    for (int k=0;k<9;k++){ LV[tid*9+k]=tv[k]; LI[tid*9+k]=tix[k]; }
    __syncthreads();
    if (tid < 64){
        int h[8]={0,0,0,0,0,0,0,0};
        const float* lv = LV + (size_t)(tid*8)*9;
        const int*   li = LI + (size_t)(tid*8)*9;
        int* dst = IDX + ((size_t)b*NNp + q0 + tid)*9;
#pragma unroll
        for (int k=0;k<9;k++){
            float bv=NEGINF; int bi=0x7fffffff; int bs=0;
#pragma unroll
            for (int s=0;s<8;s++){
                float v=lv[s*9+h[s]]; int ix=li[s*9+h[s]];
                if (v>bv || (v==bv && ix<bi)){ bv=v; bi=ix; bs=s; }
            }
#pragma unroll
            for (int s=0;s<8;s++) if (s==bs) h[s]++;
            dst[k]=bi;
        }
    }
}

// ===================== per-tap GEMMs (2 blocks/SM) ==========================
__global__ void __launch_bounds__(256,2) pc_gemm(const float* __restrict__ X,
        const float* __restrict__ W4, float* __restrict__ out){
    __shared__ float As[16*TW], Bs[16*TW];
    int slot=blockIdx.z, b=blockIdx.y, n0=blockIdx.x*128, tid=threadIdx.x;
    const float* Xb = X + (size_t)b*CC*NNp;
    const float* Wd = W4 + (size_t)slot*CC*CC;
    int tr=tid>>4, tc=tid&15, r0=tr*4, c0=tc*4;
    ull acc[8][4];
#pragma unroll
    for(int i=0;i<8;i++)
#pragma unroll
        for(int j=0;j<4;j++) acc[i][j]=0ULL;
    for (int kk=0; kk<128; kk+=16){
        for (int i=tid;i<512;i+=256){
            int k=i>>5, n4=(i&31)*4;
            *(float4*)&As[k*TW+n4] = *(const float4*)(Xb + (size_t)(kk+k)*NNp + n0 + n4);
        }
        for (int i=tid;i<512;i+=256){
            int m=i>>2, k4=(i&3)*4;
            float4 v = *(const float4*)(Wd + m*128 + kk + k4);
            Bs[(k4+0)*TW+m]=v.x; Bs[(k4+1)*TW+m]=v.y; Bs[(k4+2)*TW+m]=v.z; Bs[(k4+3)*TW+m]=v.w;
        }
        __syncthreads();
#pragma unroll
        for (int k=0;k<16;k++){
            const float* ar = As + k*TW; const float* br = Bs + k*TW;
            float4 a0 = *(const float4*)(ar+r0);
            float4 a1 = *(const float4*)(ar+r0+64);
            ulonglong2 b0 = *(const ulonglong2*)(br+c0);
            ulonglong2 b1 = *(const ulonglong2*)(br+c0+64);
            ull av[8]={pack2(a0.x),pack2(a0.y),pack2(a0.z),pack2(a0.w),
                       pack2(a1.x),pack2(a1.y),pack2(a1.z),pack2(a1.w)};
            ull bv[4]={b0.x,b0.y,b1.x,b1.y};
#pragma unroll
            for (int i=0;i<8;i++)
#pragma unroll
                for (int j=0;j<4;j++) fma2(acc[i][j], av[i], bv[j]);
        }
        __syncthreads();
    }
    float* obase = out + (((size_t)slot*BB+b)*NNp + n0)*128;
#pragma unroll
    for (int i=0;i<8;i++){
        int row=(i<4)? r0+i : r0+60+i;
#pragma unroll
        for (int j=0;j<4;j++){
            int cj=(j<2)? c0+2*j : c0+60+2*j;
            *(float2*)(obase + (size_t)row*128 + cj) = unp(acc[i][j]);
        }
    }
}

// ===================== gather + edge-conv epilogue ==========================
__global__ void __launch_bounds__(256) gather_kernel(const float* __restrict__ PC,
        const int* __restrict__ IDX, const float* __restrict__ b_l1,
        const float* __restrict__ s_l1, const float* __restrict__ t_l1,
        float* __restrict__ H){
    int b=blockIdx.y;
    int o=threadIdx.x&127, sub=threadIdx.x>>7;
    float bb=b_l1[o], ss=s_l1[o], tt=t_l1[o];
    const float* P0 = PC + ((size_t)0*BB+b)*NNp*128;
    const float* P1 = PC + ((size_t)1*BB+b)*NNp*128;
    const float* P2 = PC + ((size_t)2*BB+b)*NNp*128;
    const float* P3 = PC + ((size_t)3*BB+b)*NNp*128;
    for (int it=0; it<4; it++){
        int n = blockIdx.x*8 + it*2 + sub;
        const int* id = IDX + ((size_t)b*NNp+n)*9;
        float c0v = P0[(size_t)n*128+o];
#pragma unroll
        for (int j=0;j<3;j++){
            int i0=id[3*j], i1=id[3*j+1], i2=id[3*j+2];
            float v = c0v - P1[(size_t)i0*128+o] - P2[(size_t)i1*128+o] - P3[(size_t)i2*128+o];
            H[(((size_t)b*NNp+n)*3+j)*128+o] = fmaxf(ss*(v+bb)+tt,0.f);
        }
    }
}

// ===================== global branch ========================================
__global__ void mean_kernel(const float* __restrict__ x1, float* __restrict__ g0){
    int c=blockIdx.x, b=blockIdx.y;
    const float* p = x1 + ((size_t)b*CC+c)*NNp;
    float s=0.f;
    for (int i=threadIdx.x;i<NNp;i+=256) s+=p[i];
    __shared__ float sm[8];
    for (int o=16;o;o>>=1) s+=__shfl_down_sync(~0u,s,o);
    if ((threadIdx.x&31)==0) sm[threadIdx.x>>5]=s;
    __syncthreads();
    if (threadIdx.x<8){
        s=sm[threadIdx.x];
        for (int o=4;o;o>>=1) s+=__shfl_down_sync(0xffu,s,o);
        if (threadIdx.x==0) g0[b*CC+c]=s*(1.f/NNp);
    }
}
__global__ void glob_kernel(const float* __restrict__ g0,
        const float* __restrict__ wg1,const float* __restrict__ bg1,
        const float* __restrict__ sg1,const float* __restrict__ tg1,
        const float* __restrict__ wg2,const float* __restrict__ bg2,
        const float* __restrict__ sg2,const float* __restrict__ tg2,
        float* __restrict__ g2){
    __shared__ float s0[128], s1[32];
    int b=blockIdx.x, t=threadIdx.x;
    s0[t]=g0[b*128+t]; __syncthreads();
    if (t<32){
        float a=0.f;
        for (int c=0;c<128;c++) a+=s0[c]*wg1[t*128+c];
        s1[t]=fmaxf(sg1[t]*(a+bg1[t])+tg1[t],0.f);
    }
    __syncthreads();
    float a=0.f;
    for (int i=0;i<32;i++) a+=s1[i]*wg2[t*32+i];
    g2[b*128+t]=sg2[t]*(a+bg2[t])+tg2[t];
}

// ===================== h2 GEMM (K=384) + sigmoid ============================
__global__ void __launch_bounds__(256) h2_gemm(const float* __restrict__ H,
        const float* __restrict__ Wl2, const float* __restrict__ bl2,
        const float* __restrict__ sl2, const float* __restrict__ tl2,
        const float* __restrict__ g2, float* __restrict__ out){
    __shared__ float As[16*TW], Bs[16*68];
    int b=blockIdx.y, n0=blockIdx.x*64, tid=threadIdx.x;
    const float* Hb = H + ((size_t)b*NNp+n0)*384;
    int tr=tid>>4, tc=tid&15, r0=tr*4, c0=tc*2;
    ull acc[8][2];
#pragma unroll
    for(int i=0;i<8;i++){ acc[i][0]=0ULL; acc[i][1]=0ULL; }
    for (int kk=0; kk<384; kk+=16){
        for (int i=tid;i<512;i+=256){
            int m=i>>2, k4=(i&3)*4;
            float4 v = *(const float4*)(Wl2 + m*384 + kk + k4);
            As[(k4+0)*TW+m]=v.x; As[(k4+1)*TW+m]=v.y; As[(k4+2)*TW+m]=v.z; As[(k4+3)*TW+m]=v.w;
        }
        {
            int i=tid;
            int n=i>>2, k4=(i&3)*4;
            float4 v = *(const float4*)(Hb + (size_t)n*384 + kk + k4);
            Bs[(k4+0)*68+n]=v.x; Bs[(k4+1)*68+n]=v.y; Bs[(k4+2)*68+n]=v.z; Bs[(k4+3)*68+n]=v.w;
        }
        __syncthreads();
#pragma unroll
        for (int k=0;k<16;k++){
            const float* ar = As + k*TW; const float* br = Bs + k*68;
            float4 a0 = *(const float4*)(ar+r0);
            float4 a1 = *(const float4*)(ar+r0+64);
            ull b0 = *(const ull*)(br+c0);
            ull b1 = *(const ull*)(br+c0+32);
            ull av[8]={pack2(a0.x),pack2(a0.y),pack2(a0.z),pack2(a0.w),
                       pack2(a1.x),pack2(a1.y),pack2(a1.z),pack2(a1.w)};
#pragma unroll
            for (int i=0;i<8;i++){ fma2(acc[i][0],av[i],b0); fma2(acc[i][1],av[i],b1); }
        }
        __syncthreads();
    }
#pragma unroll
    for (int i=0;i<8;i++){
        int p=(i<4)? r0+i : r0+60+i;
        float bb=bl2[p], ss=sl2[p], tt=tl2[p], gg=g2[b*128+p];
        float* orow = out + ((size_t)b*CC+p)*NNp + n0;
#pragma unroll
        for (int j=0;j<2;j++){
            int cj=c0+j*32;
            float2 v=unp(acc[i][j]);
            float l0=fmaxf(ss*(v.x+bb)+tt,0.f);
            float l1=fmaxf(ss*(v.y+bb)+tt,0.f);
            float2 o;
            o.x = 1.f/(1.f+__expf(-(gg+l0)));
            o.y = 1.f/(1.f+__expf(-(gg+l1)));
            *(float2*)(orow+cj)=o;
        }
    }
}

extern "C" void kernel_launch(void* const* d_in, const int* in_sizes, int n_in,
                              void* d_out, int out_size){
    const float* x    = (const float*)d_in[0];
    const float* w_be = (const float*)d_in[1];
    const float* b_be = (const float*)d_in[2];
    const float* s_be = (const float*)d_in[3];
    const float* t_be = (const float*)d_in[4];
    const float* w_kn = (const float*)d_in[5];
    const float* b_kn = (const float*)d_in[6];
    const float* s_kn = (const float*)d_in[7];
    const float* t_kn = (const float*)d_in[8];
    const float* w_g1 = (const float*)d_in[9];
    const float* b_g1 = (const float*)d_in[10];
    const float* s_g1 = (const float*)d_in[11];
    const float* t_g1 = (const float*)d_in[12];
    const float* w_g2 = (const float*)d_in[13];
    const float* b_g2 = (const float*)d_in[14];
    const float* s_g2 = (const float*)d_in[15];
    const float* t_g2 = (const float*)d_in[16];
    const float* w_l1 = (const float*)d_in[17];
    const float* b_l1 = (const float*)d_in[18];
    const float* s_l1 = (const float*)d_in[19];
    const float* t_l1 = (const float*)d_in[20];
    const float* w_l2 = (const float*)d_in[21];
    const float* b_l2 = (const float*)d_in[22];
    const float* s_l2 = (const float*)d_in[23];
    const float* t_l2 = (const float*)d_in[24];
    float* out = (float*)d_out;

    float *x1, *xf, *sq, *G, *PC, *H, *g0, *g2, *W4, *Wl2; int *idx;
    cudaGetSymbolAddress((void**)&x1, g_x1);
    cudaGetSymbolAddress((void**)&xf, g_xf);
    cudaGetSymbolAddress((void**)&sq, g_sq);
    cudaGetSymbolAddress((void**)&idx, g_idx);
    cudaGetSymbolAddress((void**)&G, g_G);
    cudaGetSymbolAddress((void**)&PC, g_PC);
    cudaGetSymbolAddress((void**)&H, g_h);
    cudaGetSymbolAddress((void**)&W4, g_W4);
    cudaGetSymbolAddress((void**)&Wl2, g_Wl2);
    cudaGetSymbolAddress((void**)&g0, g_g0);
    cudaGetSymbolAddress((void**)&g2, g_g2);

    const int ks_smem = 2*128*KS_TW*4;              // 135168 B
    cudaFuncSetAttribute(knn_sym, cudaFuncAttributeMaxDynamicSharedMemorySize, ks_smem);

    pw_gemm<<<dim3(64,BB),256>>>(x,  w_be, b_be, s_be, t_be, x1, nullptr);
    pw_gemm<<<dim3(64,BB),256>>>(x1, w_kn, b_kn, s_kn, t_kn, xf, sq);
    knn_sym<<<dim3(32,32,BB),512,ks_smem>>>(xf, sq, G);
    knn_select<<<dim3(64,BB),512>>>(G, idx);        // 4th launch -> ncu
    prep_kernel<<<256,256>>>(w_l1, w_l2);
    pc_gemm<<<dim3(32,BB,4),256>>>(xf, W4, PC);
    gather_kernel<<<dim3(512,BB),256>>>(PC, idx, b_l1, s_l1, t_l1, H);
    mean_kernel<<<dim3(128,BB),256>>>(x1, g0);
    glob_kernel<<<BB,128>>>(g0, w_g1,b_g1,s_g1,t_g1, w_g2,b_g2,s_g2,t_g2, g2);
    h2_gemm<<<dim3(64,BB),256>>>(H, Wl2, b_l2, s_l2, t_l2, g2, out);
}

// round 12
// speedup vs baseline: 2.9350x; 1.2889x over previous
#include <cuda_runtime.h>
#include <math.h>
#include <cstdint>

#define BB 4
#define CC 128
#define NNp 4096
#define TW 132
#define KS_TW 132
typedef unsigned long long ull;
typedef unsigned int uint32;

__device__ float g_x1[BB*CC*NNp];
__device__ float g_xf[BB*CC*NNp];
__device__ float g_sq[BB*NNp];
__device__ int   g_idx[BB*NNp*9];
__device__ float g_G[(size_t)BB*NNp*NNp];   // 256 MB: selection keys 2*dot - sq_j
__device__ float g_PC[4*BB*NNp*CC];
__device__ float g_h[BB*NNp*3*CC];
__device__ float g_W4[4*CC*CC];
__device__ float g_Wl2[CC*3*CC];
__device__ float g_g0[BB*CC];
__device__ float g_g2[BB*CC];

// ===================== f32x2 helpers ========================================
__device__ __forceinline__ ull pack2(float a){
    ull r; unsigned ai=__float_as_uint(a);
    asm("mov.b64 %0, {%1, %2};" : "=l"(r) : "r"(ai), "r"(ai));
    return r;
}
__device__ __forceinline__ void fma2(ull &d, ull a, ull b){
    asm("fma.rn.f32x2 %0, %1, %2, %0;" : "+l"(d) : "l"(a), "l"(b));
}
__device__ __forceinline__ float2 unp(ull v){ union{ull u; float2 f;}c; c.u=v; return c.f; }

__device__ __forceinline__ uint32 smem_u32(const void* p){
    uint32 a;
    asm("{ .reg .u64 t; cvta.to.shared.u64 t, %1; cvt.u32.u64 %0, t; }" : "=r"(a) : "l"(p));
    return a;
}
__device__ __forceinline__ void cpa16(uint32 dst, const void* src){
    asm volatile("cp.async.ca.shared.global [%0], [%1], 16;" :: "r"(dst), "l"(src));
}
#define CP_COMMIT() asm volatile("cp.async.commit_group;" ::: "memory")
#define CP_WAIT0()  asm volatile("cp.async.wait_group 0;" ::: "memory")

// monotone float -> uint encoding (order-preserving)
__device__ __forceinline__ uint32 fenc(float f){
    uint32 u = __float_as_uint(f);
    return ((int)u < 0) ? ~u : (u | 0x80000000u);
}

// ===================== weight prep ==========================================
__global__ void prep_kernel(const float* __restrict__ wl1, const float* __restrict__ wl2){
    for (int i = blockIdx.x*256 + threadIdx.x; i < 4*CC*CC; i += gridDim.x*256){
        int slot=i>>14, rem=i&16383, o=rem>>7, c=rem&127;
        float v;
        if (slot==0){
            v=0.f;
#pragma unroll
            for (int w=0;w<3;w++) v += wl1[(o*256+c)*3+w] + wl1[(o*256+128+c)*3+w];
        } else v = wl1[(o*256+128+c)*3+(slot-1)];
        g_W4[i]=v;
    }
    for (int i = blockIdx.x*256 + threadIdx.x; i < CC*3*CC; i += gridDim.x*256){
        int p=i/384, k=i%384, w=k>>7, o=k&127;
        g_Wl2[i] = wl2[(p*128+o)*3+w];
    }
}

// ===================== pointwise conv (+ optional fused sq) =================
__global__ void __launch_bounds__(256) pw_gemm(const float* __restrict__ X,
        const float* __restrict__ W, const float* __restrict__ bias,
        const float* __restrict__ sc, const float* __restrict__ tr_,
        float* __restrict__ out, float* __restrict__ sqOut){
    __shared__ float As[16*TW], Bs[16*68];
    int b=blockIdx.y, n0=blockIdx.x*64, tid=threadIdx.x;
    const float* Xb = X + (size_t)b*CC*NNp;
    int tr=tid>>4, tc=tid&15, r0=tr*4, c0=tc*2;
    ull acc[8][2];
#pragma unroll
    for(int i=0;i<8;i++){ acc[i][0]=0ULL; acc[i][1]=0ULL; }
    for (int kk=0; kk<128; kk+=16){
        for (int i=tid;i<512;i+=256){
            int m=i>>2, k4=(i&3)*4;
            float4 v = *(const float4*)(W + m*128 + kk + k4);
            As[(k4+0)*TW+m]=v.x; As[(k4+1)*TW+m]=v.y; As[(k4+2)*TW+m]=v.z; As[(k4+3)*TW+m]=v.w;
        }
        {
            int i=tid;
            int k=i>>4, n4=(i&15)*4;
            *(float4*)&Bs[k*68+n4] = *(const float4*)(Xb + (size_t)(kk+k)*NNp + n0 + n4);
        }
        __syncthreads();
#pragma unroll
        for (int k=0;k<16;k++){
            const float* ar = As + k*TW; const float* br = Bs + k*68;
            float4 a0 = *(const float4*)(ar+r0);
            float4 a1 = *(const float4*)(ar+r0+64);
            ull b0 = *(const ull*)(br+c0);
            ull b1 = *(const ull*)(br+c0+32);
            ull av[8]={pack2(a0.x),pack2(a0.y),pack2(a0.z),pack2(a0.w),
                       pack2(a1.x),pack2(a1.y),pack2(a1.z),pack2(a1.w)};
#pragma unroll
            for (int i=0;i<8;i++){ fma2(acc[i][0],av[i],b0); fma2(acc[i][1],av[i],b1); }
        }
        __syncthreads();
    }
    float s0=0.f, s1=0.f, s2=0.f, s3=0.f;
#pragma unroll
    for (int i=0;i<8;i++){
        int row = (i<4)? r0+i : r0+60+i;
        float bb=bias[row], ss=sc[row], tt=tr_[row];
        float* orow = out + ((size_t)b*CC+row)*NNp + n0;
        float2 v0=unp(acc[i][0]), v1=unp(acc[i][1]);
        float o0=fmaxf(ss*(v0.x+bb)+tt,0.f);
        float o1=fmaxf(ss*(v0.y+bb)+tt,0.f);
        float o2=fmaxf(ss*(v1.x+bb)+tt,0.f);
        float o3=fmaxf(ss*(v1.y+bb)+tt,0.f);
        *(float2*)(orow+c0)    = make_float2(o0,o1);
        *(float2*)(orow+c0+32) = make_float2(o2,o3);
        s0=fmaf(o0,o0,s0); s1=fmaf(o1,o1,s1); s2=fmaf(o2,o2,s2); s3=fmaf(o3,o3,s3);
    }
    if (sqOut){
        float* red = As;
        red[tr*64 + c0]      = s0;
        red[tr*64 + c0 + 1]  = s1;
        red[tr*64 + c0 + 32] = s2;
        red[tr*64 + c0 + 33] = s3;
        __syncthreads();
        if (tid < 64){
            float s=0.f;
#pragma unroll
            for (int t=0;t<16;t++) s += red[t*64 + tid];
            sqOut[(size_t)b*NNp + n0 + tid] = s;
        }
    }
}

// ===================== symmetric Gram -> gmem KEY matrix ====================
extern __shared__ float ksm[];
__global__ void __launch_bounds__(512,1) knn_sym(const float* __restrict__ XF,
        const float* __restrict__ SQ, float* __restrict__ G){
    int ti=blockIdx.x, tj=blockIdx.y, b=blockIdx.z;
    if (tj < ti) return;
    float* As = ksm;
    float* Bs = ksm + 128*KS_TW;
    uint32 smb = smem_u32(ksm);
    int tid = threadIdx.x;
    const float* Xb = XF + (size_t)b*CC*NNp;

    uint32 aB = smb, bB = smb + 128*KS_TW*4;
#pragma unroll
    for (int j=0;j<8;j++){
        int idx = tid + 512*j;
        int c = idx>>5, q4 = idx&31;
        uint32 off = (uint32)(c*KS_TW + q4*4)*4u;
        cpa16(aB + off, Xb + (size_t)c*NNp + ti*128 + q4*4);
        cpa16(bB + off, Xb + (size_t)c*NNp + tj*128 + q4*4);
    }
    CP_COMMIT(); CP_WAIT0();
    __syncthreads();

    int r0 = (tid>>4)*4, c0 = (tid&15)*4;
    ull acc[4][4];
#pragma unroll
    for (int i=0;i<4;i++)
#pragma unroll
        for (int j=0;j<4;j++) acc[i][j]=0ULL;
#pragma unroll 4
    for (int k=0;k<128;k++){
        const float* ar = As + k*KS_TW;
        const float* br = Bs + k*KS_TW;
        float4 a = *(const float4*)(ar + r0);
        ulonglong2 b0 = *(const ulonglong2*)(br + c0);
        ulonglong2 b1 = *(const ulonglong2*)(br + c0 + 64);
        ull av[4] = {pack2(a.x),pack2(a.y),pack2(a.z),pack2(a.w)};
        ull bv[4] = {b0.x,b0.y,b1.x,b1.y};
#pragma unroll
        for (int i=0;i<4;i++)
#pragma unroll
            for (int j=0;j<4;j++) fma2(acc[i][j], av[i], bv[j]);
    }

    float vals[4][8];
#pragma unroll
    for (int i=0;i<4;i++){
        float2 v0=unp(acc[i][0]), v1=unp(acc[i][1]);
        float2 v2=unp(acc[i][2]), v3=unp(acc[i][3]);
        vals[i][0]=v0.x; vals[i][1]=v0.y; vals[i][2]=v1.x; vals[i][3]=v1.y;
        vals[i][4]=v2.x; vals[i][5]=v2.y; vals[i][6]=v3.x; vals[i][7]=v3.y;
    }

    const float* SQb = SQ + (size_t)b*NNp;
    float4 sqj_lo = *(const float4*)(SQb + tj*128 + c0);
    float4 sqj_hi = *(const float4*)(SQb + tj*128 + c0 + 64);
    float4 sqi4   = *(const float4*)(SQb + ti*128 + r0);

    float* Grow = G + ((size_t)b*NNp + (size_t)ti*128)*NNp + (size_t)tj*128;
#pragma unroll
    for (int i=0;i<4;i++){
        float* p = Grow + (size_t)(r0+i)*NNp;
        *(float4*)(p + c0)      = make_float4(
            fmaf(vals[i][0],2.f,-sqj_lo.x), fmaf(vals[i][1],2.f,-sqj_lo.y),
            fmaf(vals[i][2],2.f,-sqj_lo.z), fmaf(vals[i][3],2.f,-sqj_lo.w));
        *(float4*)(p + c0 + 64) = make_float4(
            fmaf(vals[i][4],2.f,-sqj_hi.x), fmaf(vals[i][5],2.f,-sqj_hi.y),
            fmaf(vals[i][6],2.f,-sqj_hi.z), fmaf(vals[i][7],2.f,-sqj_hi.w));
    }

    if (ti != tj){
        float* Gcol = G + ((size_t)b*NNp + (size_t)tj*128)*NNp + (size_t)ti*128;
#pragma unroll
        for (int cl=0; cl<8; cl++){
            int c = (cl<4)? (c0+cl) : (c0+60+cl);
            float4 t = make_float4(
                fmaf(vals[0][cl],2.f,-sqi4.x), fmaf(vals[1][cl],2.f,-sqi4.y),
                fmaf(vals[2][cl],2.f,-sqi4.z), fmaf(vals[3][cl],2.f,-sqi4.w));
            *(float4*)(Gcol + (size_t)c*NNp + r0) = t;
        }
    }
}

// ===================== tournament top-9 selection ===========================
// 1 warp/query, 16 queries per 512-thread block.
__global__ void __launch_bounds__(512,1) knn_select(const float* __restrict__ G,
        int* __restrict__ IDX){
    int b = blockIdx.y, q = blockIdx.x*16 + (threadIdx.x>>5);
    int lane = threadIdx.x & 31;
    const float* gq = G + ((size_t)b*NNp + q)*NNp;
    const float NEGINF = __int_as_float(0xff800000);

    // Phase A: 16 groups per lane, group id = g*32+lane, 8 cands each (aligned)
    float gv[16]; int gi[16];
#pragma unroll
    for (int g=0; g<16; g++){
        int base = (g*32 + lane)*8;
        float4 a = __ldcs((const float4*)(gq + base));
        float4 c = __ldcs((const float4*)(gq + base + 4));
        float bv = a.x; int bi = base;
        if (a.y > bv){ bv=a.y; bi=base+1; }
        if (a.z > bv){ bv=a.z; bi=base+2; }
        if (a.w > bv){ bv=a.w; bi=base+3; }
        if (c.x > bv){ bv=c.x; bi=base+4; }
        if (c.y > bv){ bv=c.y; bi=base+5; }
        if (c.z > bv){ bv=c.z; bi=base+6; }
        if (c.w > bv){ bv=c.w; bi=base+7; }
        gv[g]=bv; gi[g]=bi;
    }

    // Phase B: 9 warp-argmax rounds over 512 group keys -> my group base (lanes 0..8)
    int mybase = -1;
#pragma unroll
    for (int r=0; r<9; r++){
        float bv=NEGINF; int bi=0x7fffffff; int bs=0;
#pragma unroll
        for (int g=0; g<16; g++){
            bool t = (gv[g]>bv) || (gv[g]==bv && gi[g]<bi);
            if (t){ bv=gv[g]; bi=gi[g]; bs=g; }
        }
        uint32 enc = fenc(bv);
        uint32 me  = __reduce_max_sync(0xffffffffu, enc);
        uint32 cand = (enc==me) ? (uint32)bi : 0xffffffffu;
        uint32 mi  = __reduce_min_sync(0xffffffffu, cand);
        if (lane == r) mybase = (int)(mi & ~7u);
        if (enc==me && (uint32)bi==mi){ gv[bs]=NEGINF; gi[bs]=0x7fffffff; }
    }

    // Phase C: lanes 0..8 hold their winning group's 8 candidates; 9 argmax rounds
    float cv[8]; int cbase;
    if (mybase >= 0){
        float4 a = *(const float4*)(gq + mybase);
        float4 c = *(const float4*)(gq + mybase + 4);
        cv[0]=a.x; cv[1]=a.y; cv[2]=a.z; cv[3]=a.w;
        cv[4]=c.x; cv[5]=c.y; cv[6]=c.z; cv[7]=c.w;
        cbase = mybase;
    } else {
#pragma unroll
        for (int k=0;k<8;k++) cv[k]=NEGINF;
        cbase = 0x7ffffff0;
    }
    int* dst = IDX + ((size_t)b*NNp + q)*9;
#pragma unroll
    for (int r=0; r<9; r++){
        float bv=NEGINF; int bi=0x7fffffff; int bs=0;
#pragma unroll
        for (int k=0;k<8;k++){
            bool t = (cv[k]>bv) || (cv[k]==bv && (cbase+k)<bi);
            if (t){ bv=cv[k]; bi=cbase+k; bs=k; }
        }
        uint32 enc = fenc(bv);
        uint32 me  = __reduce_max_sync(0xffffffffu, enc);
        uint32 cand = (enc==me) ? (uint32)bi : 0xffffffffu;
        uint32 mi  = __reduce_min_sync(0xffffffffu, cand);
        if (lane == 0) dst[r] = (int)mi;
        if (enc==me && (uint32)bi==mi) cv[bs]=NEGINF;
    }
}

// ===================== per-tap GEMMs (2 blocks/SM) ==========================
__global__ void __launch_bounds__(256,2) pc_gemm(const float* __restrict__ X,
        const float* __restrict__ W4, float* __restrict__ out){
    __shared__ float As[16*TW], Bs[16*TW];
    int slot=blockIdx.z, b=blockIdx.y, n0=blockIdx.x*128, tid=threadIdx.x;
    const float* Xb = X + (size_t)b*CC*NNp;
    const float* Wd = W4 + (size_t)slot*CC*CC;
    int tr=tid>>4, tc=tid&15, r0=tr*4, c0=tc*4;
    ull acc[8][4];
#pragma unroll
    for(int i=0;i<8;i++)
#pragma unroll
        for(int j=0;j<4;j++) acc[i][j]=0ULL;
    for (int kk=0; kk<128; kk+=16){
        for (int i=tid;i<512;i+=256){
            int k=i>>5, n4=(i&31)*4;
            *(float4*)&As[k*TW+n4] = *(const float4*)(Xb + (size_t)(kk+k)*NNp + n0 + n4);
        }
        for (int i=tid;i<512;i+=256){
            int m=i>>2, k4=(i&3)*4;
            float4 v = *(const float4*)(Wd + m*128 + kk + k4);
            Bs[(k4+0)*TW+m]=v.x; Bs[(k4+1)*TW+m]=v.y; Bs[(k4+2)*TW+m]=v.z; Bs[(k4+3)*TW+m]=v.w;
        }
        __syncthreads();
#pragma unroll
        for (int k=0;k<16;k++){
            const float* ar = As + k*TW; const float* br = Bs + k*TW;
            float4 a0 = *(const float4*)(ar+r0);
            float4 a1 = *(const float4*)(ar+r0+64);
            ulonglong2 b0 = *(const ulonglong2*)(br+c0);
            ulonglong2 b1 = *(const ulonglong2*)(br+c0+64);
            ull av[8]={pack2(a0.x),pack2(a0.y),pack2(a0.z),pack2(a0.w),
                       pack2(a1.x),pack2(a1.y),pack2(a1.z),pack2(a1.w)};
            ull bv[4]={b0.x,b0.y,b1.x,b1.y};
#pragma unroll
            for (int i=0;i<8;i++)
#pragma unroll
                for (int j=0;j<4;j++) fma2(acc[i][j], av[i], bv[j]);
        }
        __syncthreads();
    }
    float* obase = out + (((size_t)slot*BB+b)*NNp + n0)*128;
#pragma unroll
    for (int i=0;i<8;i++){
        int row=(i<4)? r0+i : r0+60+i;
#pragma unroll
        for (int j=0;j<4;j++){
            int cj=(j<2)? c0+2*j : c0+60+2*j;
            *(float2*)(obase + (size_t)row*128 + cj) = unp(acc[i][j]);
        }
    }
}

// ===================== gather + edge-conv epilogue ==========================
__global__ void __launch_bounds__(256) gather_kernel(const float* __restrict__ PC,
        const int* __restrict__ IDX, const float* __restrict__ b_l1,
        const float* __restrict__ s_l1, const float* __restrict__ t_l1,
        float* __restrict__ H){
    int b=blockIdx.y;
    int o=threadIdx.x&127, sub=threadIdx.x>>7;
    float bb=b_l1[o], ss=s_l1[o], tt=t_l1[o];
    const float* P0 = PC + ((size_t)0*BB+b)*NNp*128;
    const float* P1 = PC + ((size_t)1*BB+b)*NNp*128;
    const float* P2 = PC + ((size_t)2*BB+b)*NNp*128;
    const float* P3 = PC + ((size_t)3*BB+b)*NNp*128;
    for (int it=0; it<4; it++){
        int n = blockIdx.x*8 + it*2 + sub;
        const int* id = IDX + ((size_t)b*NNp+n)*9;
        float c0v = P0[(size_t)n*128+o];
#pragma unroll
        for (int j=0;j<3;j++){
            int i0=id[3*j], i1=id[3*j+1], i2=id[3*j+2];
            float v = c0v - P1[(size_t)i0*128+o] - P2[(size_t)i1*128+o] - P3[(size_t)i2*128+o];
            H[(((size_t)b*NNp+n)*3+j)*128+o] = fmaxf(ss*(v+bb)+tt,0.f);
        }
    }
}

// ===================== global branch ========================================
__global__ void mean_kernel(const float* __restrict__ x1, float* __restrict__ g0){
    int c=blockIdx.x, b=blockIdx.y;
    const float* p = x1 + ((size_t)b*CC+c)*NNp;
    float s=0.f;
    for (int i=threadIdx.x;i<NNp;i+=256) s+=p[i];
    __shared__ float sm[8];
    for (int o=16;o;o>>=1) s+=__shfl_down_sync(~0u,s,o);
    if ((threadIdx.x&31)==0) sm[threadIdx.x>>5]=s;
    __syncthreads();
    if (threadIdx.x<8){
        s=sm[threadIdx.x];
        for (int o=4;o;o>>=1) s+=__shfl_down_sync(0xffu,s,o);
        if (threadIdx.x==0) g0[b*CC+c]=s*(1.f/NNp);
    }
}
__global__ void glob_kernel(const float* __restrict__ g0,
        const float* __restrict__ wg1,const float* __restrict__ bg1,
        const float* __restrict__ sg1,const float* __restrict__ tg1,
        const float* __restrict__ wg2,const float* __restrict__ bg2,
        const float* __restrict__ sg2,const float* __restrict__ tg2,
        float* __restrict__ g2){
    __shared__ float s0[128], s1[32];
    int b=blockIdx.x, t=threadIdx.x;
    s0[t]=g0[b*128+t]; __syncthreads();
    if (t<32){
        float a=0.f;
        for (int c=0;c<128;c++) a+=s0[c]*wg1[t*128+c];
        s1[t]=fmaxf(sg1[t]*(a+bg1[t])+tg1[t],0.f);
    }
    __syncthreads();
    float a=0.f;
    for (int i=0;i<32;i++) a+=s1[i]*wg2[t*32+i];
    g2[b*128+t]=sg2[t]*(a+bg2[t])+tg2[t];
}

// ===================== h2 GEMM (K=384) + sigmoid ============================
__global__ void __launch_bounds__(256) h2_gemm(const float* __restrict__ H,
        const float* __restrict__ Wl2, const float* __restrict__ bl2,
        const float* __restrict__ sl2, const float* __restrict__ tl2,
        const float* __restrict__ g2, float* __restrict__ out){
    __shared__ float As[16*TW], Bs[16*68];
    int b=blockIdx.y, n0=blockIdx.x*64, tid=threadIdx.x;
    const float* Hb = H + ((size_t)b*NNp+n0)*384;
    int tr=tid>>4, tc=tid&15, r0=tr*4, c0=tc*2;
    ull acc[8][2];
#pragma unroll
    for(int i=0;i<8;i++){ acc[i][0]=0ULL; acc[i][1]=0ULL; }
    for (int kk=0; kk<384; kk+=16){
        for (int i=tid;i<512;i+=256){
            int m=i>>2, k4=(i&3)*4;
            float4 v = *(const float4*)(Wl2 + m*384 + kk + k4);
            As[(k4+0)*TW+m]=v.x; As[(k4+1)*TW+m]=v.y; As[(k4+2)*TW+m]=v.z; As[(k4+3)*TW+m]=v.w;
        }
        {
            int i=tid;
            int n=i>>2, k4=(i&3)*4;
            float4 v = *(const float4*)(Hb + (size_t)n*384 + kk + k4);
            Bs[(k4+0)*68+n]=v.x; Bs[(k4+1)*68+n]=v.y; Bs[(k4+2)*68+n]=v.z; Bs[(k4+3)*68+n]=v.w;
        }
        __syncthreads();
#pragma unroll
        for (int k=0;k<16;k++){
            const float* ar = As + k*TW; const float* br = Bs + k*68;
            float4 a0 = *(const float4*)(ar+r0);
            float4 a1 = *(const float4*)(ar+r0+64);
            ull b0 = *(const ull*)(br+c0);
            ull b1 = *(const ull*)(br+c0+32);
            ull av[8]={pack2(a0.x),pack2(a0.y),pack2(a0.z),pack2(a0.w),
                       pack2(a1.x),pack2(a1.y),pack2(a1.z),pack2(a1.w)};
#pragma unroll
            for (int i=0;i<8;i++){ fma2(acc[i][0],av[i],b0); fma2(acc[i][1],av[i],b1); }
        }
        __syncthreads();
    }
#pragma unroll
    for (int i=0;i<8;i++){
        int p=(i<4)? r0+i : r0+60+i;
        float bb=bl2[p], ss=sl2[p], tt=tl2[p], gg=g2[b*128+p];
        float* orow = out + ((size_t)b*CC+p)*NNp + n0;
#pragma unroll
        for (int j=0;j<2;j++){
            int cj=c0+j*32;
            float2 v=unp(acc[i][j]);
            float l0=fmaxf(ss*(v.x+bb)+tt,0.f);
            float l1=fmaxf(ss*(v.y+bb)+tt,0.f);
            float2 o;
            o.x = 1.f/(1.f+__expf(-(gg+l0)));
            o.y = 1.f/(1.f+__expf(-(gg+l1)));
            *(float2*)(orow+cj)=o;
        }
    }
}

extern "C" void kernel_launch(void* const* d_in, const int* in_sizes, int n_in,
                              void* d_out, int out_size){
    const float* x    = (const float*)d_in[0];
    const float* w_be = (const float*)d_in[1];
    const float* b_be = (const float*)d_in[2];
    const float* s_be = (const float*)d_in[3];
    const float* t_be = (const float*)d_in[4];
    const float* w_kn = (const float*)d_in[5];
    const float* b_kn = (const float*)d_in[6];
    const float* s_kn = (const float*)d_in[7];
    const float* t_kn = (const float*)d_in[8];
    const float* w_g1 = (const float*)d_in[9];
    const float* b_g1 = (const float*)d_in[10];
    const float* s_g1 = (const float*)d_in[11];
    const float* t_g1 = (const float*)d_in[12];
    const float* w_g2 = (const float*)d_in[13];
    const float* b_g2 = (const float*)d_in[14];
    const float* s_g2 = (const float*)d_in[15];
    const float* t_g2 = (const float*)d_in[16];
    const float* w_l1 = (const float*)d_in[17];
    const float* b_l1 = (const float*)d_in[18];
    const float* s_l1 = (const float*)d_in[19];
    const float* t_l1 = (const float*)d_in[20];
    const float* w_l2 = (const float*)d_in[21];
    const float* b_l2 = (const float*)d_in[22];
    const float* s_l2 = (const float*)d_in[23];
    const float* t_l2 = (const float*)d_in[24];
    float* out = (float*)d_out;

    float *x1, *xf, *sq, *G, *PC, *H, *g0, *g2, *W4, *Wl2; int *idx;
    cudaGetSymbolAddress((void**)&x1, g_x1);
    cudaGetSymbolAddress((void**)&xf, g_xf);
    cudaGetSymbolAddress((void**)&sq, g_sq);
    cudaGetSymbolAddress((void**)&idx, g_idx);
    cudaGetSymbolAddress((void**)&G, g_G);
    cudaGetSymbolAddress((void**)&PC, g_PC);
    cudaGetSymbolAddress((void**)&H, g_h);
    cudaGetSymbolAddress((void**)&W4, g_W4);
    cudaGetSymbolAddress((void**)&Wl2, g_Wl2);
    cudaGetSymbolAddress((void**)&g0, g_g0);
    cudaGetSymbolAddress((void**)&g2, g_g2);

    const int ks_smem = 2*128*KS_TW*4;              // 135168 B
    cudaFuncSetAttribute(knn_sym, cudaFuncAttributeMaxDynamicSharedMemorySize, ks_smem);

    pw_gemm<<<dim3(64,BB),256>>>(x,  w_be, b_be, s_be, t_be, x1, nullptr);
    pw_gemm<<<dim3(64,BB),256>>>(x1, w_kn, b_kn, s_kn, t_kn, xf, sq);
    knn_sym<<<dim3(32,32,BB),512,ks_smem>>>(xf, sq, G);
    knn_select<<<dim3(256,BB),512>>>(G, idx);       // 4th launch -> ncu
    prep_kernel<<<256,256>>>(w_l1, w_l2);
    pc_gemm<<<dim3(32,BB,4),256>>>(xf, W4, PC);
    gather_kernel<<<dim3(512,BB),256>>>(PC, idx, b_l1, s_l1, t_l1, H);
    mean_kernel<<<dim3(128,BB),256>>>(x1, g0);
    glob_kernel<<<BB,128>>>(g0, w_g1,b_g1,s_g1,t_g1, w_g2,b_g2,s_g2,t_g2, g2);
    h2_gemm<<<dim3(64,BB),256>>>(H, Wl2, b_l2, s_l2, t_l2, g2, out);
}

// round 13
// speedup vs baseline: 3.3266x; 1.1335x over previous
#include <cuda_runtime.h>
#include <math.h>
#include <cstdint>

#define BB 4
#define CC 128
#define NNp 4096
#define TW 132
#define KS_TW 132
typedef unsigned long long ull;
typedef unsigned int uint32;

__device__ float g_x1[BB*CC*NNp];
__device__ float g_xf[BB*CC*NNp];
__device__ float g_sq[BB*NNp];
__device__ int   g_idx[BB*NNp*9];
__device__ float g_G[(size_t)BB*NNp*NNp];   // 256 MB: selection keys 2*dot - sq_j
__device__ float g_PC[4*BB*NNp*CC];
__device__ float g_h[BB*NNp*3*CC];
__device__ float g_W4[4*CC*CC];
__device__ float g_Wl2[CC*3*CC];
__device__ float g_g0[BB*CC];
__device__ float g_g2[BB*CC];

// stream/event plumbing created once at load time (before harness checkpoints)
static cudaStream_t g_s2;
static cudaEvent_t  g_ef, g_es;
struct StreamInit {
    StreamInit(){
        cudaStreamCreateWithFlags(&g_s2, cudaStreamNonBlocking);
        cudaEventCreateWithFlags(&g_ef, cudaEventDisableTiming);
        cudaEventCreateWithFlags(&g_es, cudaEventDisableTiming);
    }
};
static StreamInit g_si;

// ===================== f32x2 helpers ========================================
__device__ __forceinline__ ull pack2(float a){
    ull r; unsigned ai=__float_as_uint(a);
    asm("mov.b64 %0, {%1, %2};" : "=l"(r) : "r"(ai), "r"(ai));
    return r;
}
__device__ __forceinline__ void fma2(ull &d, ull a, ull b){
    asm("fma.rn.f32x2 %0, %1, %2, %0;" : "+l"(d) : "l"(a), "l"(b));
}
__device__ __forceinline__ float2 unp(ull v){ union{ull u; float2 f;}c; c.u=v; return c.f; }

__device__ __forceinline__ uint32 smem_u32(const void* p){
    uint32 a;
    asm("{ .reg .u64 t; cvta.to.shared.u64 t, %1; cvt.u32.u64 %0, t; }" : "=r"(a) : "l"(p));
    return a;
}
__device__ __forceinline__ void cpa16(uint32 dst, const void* src){
    asm volatile("cp.async.ca.shared.global [%0], [%1], 16;" :: "r"(dst), "l"(src));
}
#define CP_COMMIT() asm volatile("cp.async.commit_group;" ::: "memory")
#define CP_WAIT0()  asm volatile("cp.async.wait_group 0;" ::: "memory")

// monotone float -> uint encoding (order-preserving)
__device__ __forceinline__ uint32 fenc(float f){
    uint32 u = __float_as_uint(f);
    return ((int)u < 0) ? ~u : (u | 0x80000000u);
}

// ===================== weight prep ==========================================
__global__ void prep_kernel(const float* __restrict__ wl1, const float* __restrict__ wl2){
    for (int i = blockIdx.x*256 + threadIdx.x; i < 4*CC*CC; i += gridDim.x*256){
        int slot=i>>14, rem=i&16383, o=rem>>7, c=rem&127;
        float v;
        if (slot==0){
            v=0.f;
#pragma unroll
            for (int w=0;w<3;w++) v += wl1[(o*256+c)*3+w] + wl1[(o*256+128+c)*3+w];
        } else v = wl1[(o*256+128+c)*3+(slot-1)];
        g_W4[i]=v;
    }
    for (int i = blockIdx.x*256 + threadIdx.x; i < CC*3*CC; i += gridDim.x*256){
        int p=i/384, k=i%384, w=k>>7, o=k&127;
        g_Wl2[i] = wl2[(p*128+o)*3+w];
    }
}

// ===================== pointwise conv (+ optional fused sq) =================
__global__ void __launch_bounds__(256) pw_gemm(const float* __restrict__ X,
        const float* __restrict__ W, const float* __restrict__ bias,
        const float* __restrict__ sc, const float* __restrict__ tr_,
        float* __restrict__ out, float* __restrict__ sqOut){
    __shared__ float As[16*TW], Bs[16*68];
    int b=blockIdx.y, n0=blockIdx.x*64, tid=threadIdx.x;
    const float* Xb = X + (size_t)b*CC*NNp;
    int tr=tid>>4, tc=tid&15, r0=tr*4, c0=tc*2;
    ull acc[8][2];
#pragma unroll
    for(int i=0;i<8;i++){ acc[i][0]=0ULL; acc[i][1]=0ULL; }
    for (int kk=0; kk<128; kk+=16){
        for (int i=tid;i<512;i+=256){
            int m=i>>2, k4=(i&3)*4;
            float4 v = *(const float4*)(W + m*128 + kk + k4);
            As[(k4+0)*TW+m]=v.x; As[(k4+1)*TW+m]=v.y; As[(k4+2)*TW+m]=v.z; As[(k4+3)*TW+m]=v.w;
        }
        {
            int i=tid;
            int k=i>>4, n4=(i&15)*4;
            *(float4*)&Bs[k*68+n4] = *(const float4*)(Xb + (size_t)(kk+k)*NNp + n0 + n4);
        }
        __syncthreads();
#pragma unroll
        for (int k=0;k<16;k++){
            const float* ar = As + k*TW; const float* br = Bs + k*68;
            float4 a0 = *(const float4*)(ar+r0);
            float4 a1 = *(const float4*)(ar+r0+64);
            ull b0 = *(const ull*)(br+c0);
            ull b1 = *(const ull*)(br+c0+32);
            ull av[8]={pack2(a0.x),pack2(a0.y),pack2(a0.z),pack2(a0.w),
                       pack2(a1.x),pack2(a1.y),pack2(a1.z),pack2(a1.w)};
#pragma unroll
            for (int i=0;i<8;i++){ fma2(acc[i][0],av[i],b0); fma2(acc[i][1],av[i],b1); }
        }
        __syncthreads();
    }
    float s0=0.f, s1=0.f, s2=0.f, s3=0.f;
#pragma unroll
    for (int i=0;i<8;i++){
        int row = (i<4)? r0+i : r0+60+i;
        float bb=bias[row], ss=sc[row], tt=tr_[row];
        float* orow = out + ((size_t)b*CC+row)*NNp + n0;
        float2 v0=unp(acc[i][0]), v1=unp(acc[i][1]);
        float o0=fmaxf(ss*(v0.x+bb)+tt,0.f);
        float o1=fmaxf(ss*(v0.y+bb)+tt,0.f);
        float o2=fmaxf(ss*(v1.x+bb)+tt,0.f);
        float o3=fmaxf(ss*(v1.y+bb)+tt,0.f);
        *(float2*)(orow+c0)    = make_float2(o0,o1);
        *(float2*)(orow+c0+32) = make_float2(o2,o3);
        s0=fmaf(o0,o0,s0); s1=fmaf(o1,o1,s1); s2=fmaf(o2,o2,s2); s3=fmaf(o3,o3,s3);
    }
    if (sqOut){
        float* red = As;
        red[tr*64 + c0]      = s0;
        red[tr*64 + c0 + 1]  = s1;
        red[tr*64 + c0 + 32] = s2;
        red[tr*64 + c0 + 33] = s3;
        __syncthreads();
        if (tid < 64){
            float s=0.f;
#pragma unroll
            for (int t=0;t<16;t++) s += red[t*64 + tid];
            sqOut[(size_t)b*NNp + n0 + tid] = s;
        }
    }
}

// ===================== symmetric Gram -> gmem KEY matrix ====================
extern __shared__ float ksm[];
__global__ void __launch_bounds__(512,1) knn_sym(const float* __restrict__ XF,
        const float* __restrict__ SQ, float* __restrict__ G){
    int ti=blockIdx.x, tj=blockIdx.y, b=blockIdx.z;
    if (tj < ti) return;
    float* As = ksm;
    float* Bs = ksm + 128*KS_TW;
    uint32 smb = smem_u32(ksm);
    int tid = threadIdx.x;
    const float* Xb = XF + (size_t)b*CC*NNp;

    uint32 aB = smb, bB = smb + 128*KS_TW*4;
#pragma unroll
    for (int j=0;j<8;j++){
        int idx = tid + 512*j;
        int c = idx>>5, q4 = idx&31;
        uint32 off = (uint32)(c*KS_TW + q4*4)*4u;
        cpa16(aB + off, Xb + (size_t)c*NNp + ti*128 + q4*4);
        cpa16(bB + off, Xb + (size_t)c*NNp + tj*128 + q4*4);
    }
    CP_COMMIT(); CP_WAIT0();
    __syncthreads();

    int r0 = (tid>>4)*4, c0 = (tid&15)*4;
    ull acc[4][4];
#pragma unroll
    for (int i=0;i<4;i++)
#pragma unroll
        for (int j=0;j<4;j++) acc[i][j]=0ULL;
#pragma unroll 4
    for (int k=0;k<128;k++){
        const float* ar = As + k*KS_TW;
        const float* br = Bs + k*KS_TW;
        float4 a = *(const float4*)(ar + r0);
        ulonglong2 b0 = *(const ulonglong2*)(br + c0);
        ulonglong2 b1 = *(const ulonglong2*)(br + c0 + 64);
        ull av[4] = {pack2(a.x),pack2(a.y),pack2(a.z),pack2(a.w)};
        ull bv[4] = {b0.x,b0.y,b1.x,b1.y};
#pragma unroll
        for (int i=0;i<4;i++)
#pragma unroll
            for (int j=0;j<4;j++) fma2(acc[i][j], av[i], bv[j]);
    }

    float vals[4][8];
#pragma unroll
    for (int i=0;i<4;i++){
        float2 v0=unp(acc[i][0]), v1=unp(acc[i][1]);
        float2 v2=unp(acc[i][2]), v3=unp(acc[i][3]);
        vals[i][0]=v0.x; vals[i][1]=v0.y; vals[i][2]=v1.x; vals[i][3]=v1.y;
        vals[i][4]=v2.x; vals[i][5]=v2.y; vals[i][6]=v3.x; vals[i][7]=v3.y;
    }

    const float* SQb = SQ + (size_t)b*NNp;
    float4 sqj_lo = *(const float4*)(SQb + tj*128 + c0);
    float4 sqj_hi = *(const float4*)(SQb + tj*128 + c0 + 64);
    float4 sqi4   = *(const float4*)(SQb + ti*128 + r0);

    float* Grow = G + ((size_t)b*NNp + (size_t)ti*128)*NNp + (size_t)tj*128;
#pragma unroll
    for (int i=0;i<4;i++){
        float* p = Grow + (size_t)(r0+i)*NNp;
        *(float4*)(p + c0)      = make_float4(
            fmaf(vals[i][0],2.f,-sqj_lo.x), fmaf(vals[i][1],2.f,-sqj_lo.y),
            fmaf(vals[i][2],2.f,-sqj_lo.z), fmaf(vals[i][3],2.f,-sqj_lo.w));
        *(float4*)(p + c0 + 64) = make_float4(
            fmaf(vals[i][4],2.f,-sqj_hi.x), fmaf(vals[i][5],2.f,-sqj_hi.y),
            fmaf(vals[i][6],2.f,-sqj_hi.z), fmaf(vals[i][7],2.f,-sqj_hi.w));
    }

    if (ti != tj){
        float* Gcol = G + ((size_t)b*NNp + (size_t)tj*128)*NNp + (size_t)ti*128;
#pragma unroll
        for (int cl=0; cl<8; cl++){
            int c = (cl<4)? (c0+cl) : (c0+60+cl);
            float4 t = make_float4(
                fmaf(vals[0][cl],2.f,-sqi4.x), fmaf(vals[1][cl],2.f,-sqi4.y),
                fmaf(vals[2][cl],2.f,-sqi4.z), fmaf(vals[3][cl],2.f,-sqi4.w));
            *(float4*)(Gcol + (size_t)c*NNp + r0) = t;
        }
    }
}

// ===================== tournament top-9 selection ===========================
// 1 warp/query, 16 queries per 512-thread block, 2 blocks/SM target.
__global__ void __launch_bounds__(512,2) knn_select(const float* __restrict__ G,
        int* __restrict__ IDX){
    int b = blockIdx.y, q = blockIdx.x*16 + (threadIdx.x>>5);
    int lane = threadIdx.x & 31;
    const float* gq = G + ((size_t)b*NNp + q)*NNp;
    const float NEGINF = __int_as_float(0xff800000);

    // Phase A: 16 groups per lane, group id = g*32+lane, 8 cands each (aligned)
    float gv[16]; int gi[16];
#pragma unroll
    for (int g=0; g<16; g++){
        int base = (g*32 + lane)*8;
        float4 a = __ldcs((const float4*)(gq + base));
        float4 c = __ldcs((const float4*)(gq + base + 4));
        float bv = a.x; int bi = base;
        if (a.y > bv){ bv=a.y; bi=base+1; }
        if (a.z > bv){ bv=a.z; bi=base+2; }
        if (a.w > bv){ bv=a.w; bi=base+3; }
        if (c.x > bv){ bv=c.x; bi=base+4; }
        if (c.y > bv){ bv=c.y; bi=base+5; }
        if (c.z > bv){ bv=c.z; bi=base+6; }
        if (c.w > bv){ bv=c.w; bi=base+7; }
        gv[g]=bv; gi[g]=bi;
    }

    // Phase B: 9 warp-argmax rounds over 512 group keys -> my group base (lanes 0..8)
    int mybase = -1;
#pragma unroll
    for (int r=0; r<9; r++){
        float bv=NEGINF; int bi=0x7fffffff; int bs=0;
#pragma unroll
        for (int g=0; g<16; g++){
            bool t = (gv[g]>bv) || (gv[g]==bv && gi[g]<bi);
            if (t){ bv=gv[g]; bi=gi[g]; bs=g; }
        }
        uint32 enc = fenc(bv);
        uint32 me  = __reduce_max_sync(0xffffffffu, enc);
        uint32 cand = (enc==me) ? (uint32)bi : 0xffffffffu;
        uint32 mi  = __reduce_min_sync(0xffffffffu, cand);
        if (lane == r) mybase = (int)(mi & ~7u);
        if (enc==me && (uint32)bi==mi){ gv[bs]=NEGINF; gi[bs]=0x7fffffff; }
    }

    // Phase C: lanes 0..8 hold their winning group's 8 candidates; 9 argmax rounds
    float cv[8]; int cbase;
    if (mybase >= 0){
        float4 a = *(const float4*)(gq + mybase);
        float4 c = *(const float4*)(gq + mybase + 4);
        cv[0]=a.x; cv[1]=a.y; cv[2]=a.z; cv[3]=a.w;
        cv[4]=c.x; cv[5]=c.y; cv[6]=c.z; cv[7]=c.w;
        cbase = mybase;
    } else {
#pragma unroll
        for (int k=0;k<8;k++) cv[k]=NEGINF;
        cbase = 0x7ffffff0;
    }
    int* dst = IDX + ((size_t)b*NNp + q)*9;
#pragma unroll
    for (int r=0; r<9; r++){
        float bv=NEGINF; int bi=0x7fffffff; int bs=0;
#pragma unroll
        for (int k=0;k<8;k++){
            bool t = (cv[k]>bv) || (cv[k]==bv && (cbase+k)<bi);
            if (t){ bv=cv[k]; bi=cbase+k; bs=k; }
        }
        uint32 enc = fenc(bv);
        uint32 me  = __reduce_max_sync(0xffffffffu, enc);
        uint32 cand = (enc==me) ? (uint32)bi : 0xffffffffu;
        uint32 mi  = __reduce_min_sync(0xffffffffu, cand);
        if (lane == 0) dst[r] = (int)mi;
        if (enc==me && (uint32)bi==mi) cv[bs]=NEGINF;
    }
}

// ===================== per-tap GEMMs (2 blocks/SM) ==========================
__global__ void __launch_bounds__(256,2) pc_gemm(const float* __restrict__ X,
        const float* __restrict__ W4, float* __restrict__ out){
    __shared__ float As[16*TW], Bs[16*TW];
    int slot=blockIdx.z, b=blockIdx.y, n0=blockIdx.x*128, tid=threadIdx.x;
    const float* Xb = X + (size_t)b*CC*NNp;
    const float* Wd = W4 + (size_t)slot*CC*CC;
    int tr=tid>>4, tc=tid&15, r0=tr*4, c0=tc*4;
    ull acc[8][4];
#pragma unroll
    for(int i=0;i<8;i++)
#pragma unroll
        for(int j=0;j<4;j++) acc[i][j]=0ULL;
    for (int kk=0; kk<128; kk+=16){
        for (int i=tid;i<512;i+=256){
            int k=i>>5, n4=(i&31)*4;
            *(float4*)&As[k*TW+n4] = *(const float4*)(Xb + (size_t)(kk+k)*NNp + n0 + n4);
        }
        for (int i=tid;i<512;i+=256){
            int m=i>>2, k4=(i&3)*4;
            float4 v = *(const float4*)(Wd + m*128 + kk + k4);
            Bs[(k4+0)*TW+m]=v.x; Bs[(k4+1)*TW+m]=v.y; Bs[(k4+2)*TW+m]=v.z; Bs[(k4+3)*TW+m]=v.w;
        }
        __syncthreads();
#pragma unroll
        for (int k=0;k<16;k++){
            const float* ar = As + k*TW; const float* br = Bs + k*TW;
            float4 a0 = *(const float4*)(ar+r0);
            float4 a1 = *(const float4*)(ar+r0+64);
            ulonglong2 b0 = *(const ulonglong2*)(br+c0);
            ulonglong2 b1 = *(const ulonglong2*)(br+c0+64);
            ull av[8]={pack2(a0.x),pack2(a0.y),pack2(a0.z),pack2(a0.w),
                       pack2(a1.x),pack2(a1.y),pack2(a1.z),pack2(a1.w)};
            ull bv[4]={b0.x,b0.y,b1.x,b1.y};
#pragma unroll
            for (int i=0;i<8;i++)
#pragma unroll
                for (int j=0;j<4;j++) fma2(acc[i][j], av[i], bv[j]);
        }
        __syncthreads();
    }
    float* obase = out + (((size_t)slot*BB+b)*NNp + n0)*128;
#pragma unroll
    for (int i=0;i<8;i++){
        int row=(i<4)? r0+i : r0+60+i;
#pragma unroll
        for (int j=0;j<4;j++){
            int cj=(j<2)? c0+2*j : c0+60+2*j;
            *(float2*)(obase + (size_t)row*128 + cj) = unp(acc[i][j]);
        }
    }
}

// ===================== gather + edge-conv epilogue ==========================
__global__ void __launch_bounds__(256) gather_kernel(const float* __restrict__ PC,
        const int* __restrict__ IDX, const float* __restrict__ b_l1,
        const float* __restrict__ s_l1, const float* __restrict__ t_l1,
        float* __restrict__ H){
    int b=blockIdx.y;
    int o=threadIdx.x&127, sub=threadIdx.x>>7;
    float bb=b_l1[o], ss=s_l1[o], tt=t_l1[o];
    const float* P0 = PC + ((size_t)0*BB+b)*NNp*128;
    const float* P1 = PC + ((size_t)1*BB+b)*NNp*128;
    const float* P2 = PC + ((size_t)2*BB+b)*NNp*128;
    const float* P3 = PC + ((size_t)3*BB+b)*NNp*128;
    for (int it=0; it<4; it++){
        int n = blockIdx.x*8 + it*2 + sub;
        const int* id = IDX + ((size_t)b*NNp+n)*9;
        float c0v = P0[(size_t)n*128+o];
#pragma unroll
        for (int j=0;j<3;j++){
            int i0=id[3*j], i1=id[3*j+1], i2=id[3*j+2];
            float v = c0v - P1[(size_t)i0*128+o] - P2[(size_t)i1*128+o] - P3[(size_t)i2*128+o];
            H[(((size_t)b*NNp+n)*3+j)*128+o] = fmaxf(ss*(v+bb)+tt,0.f);
        }
    }
}

// ===================== global branch ========================================
__global__ void mean_kernel(const float* __restrict__ x1, float* __restrict__ g0){
    int c=blockIdx.x, b=blockIdx.y;
    const float* p = x1 + ((size_t)b*CC+c)*NNp;
    float s=0.f;
    for (int i=threadIdx.x;i<NNp;i+=256) s+=p[i];
    __shared__ float sm[8];
    for (int o=16;o;o>>=1) s+=__shfl_down_sync(~0u,s,o);
    if ((threadIdx.x&31)==0) sm[threadIdx.x>>5]=s;
    __syncthreads();
    if (threadIdx.x<8){
        s=sm[threadIdx.x];
        for (int o=4;o;o>>=1) s+=__shfl_down_sync(0xffu,s,o);
        if (threadIdx.x==0) g0[b*CC+c]=s*(1.f/NNp);
    }
}
__global__ void glob_kernel(const float* __restrict__ g0,
        const float* __restrict__ wg1,const float* __restrict__ bg1,
        const float* __restrict__ sg1,const float* __restrict__ tg1,
        const float* __restrict__ wg2,const float* __restrict__ bg2,
        const float* __restrict__ sg2,const float* __restrict__ tg2,
        float* __restrict__ g2){
    __shared__ float s0[128], s1[32];
    int b=blockIdx.x, t=threadIdx.x;
    s0[t]=g0[b*128+t]; __syncthreads();
    if (t<32){
        float a=0.f;
        for (int c=0;c<128;c++) a+=s0[c]*wg1[t*128+c];
        s1[t]=fmaxf(sg1[t]*(a+bg1[t])+tg1[t],0.f);
    }
    __syncthreads();
    float a=0.f;
    for (int i=0;i<32;i++) a+=s1[i]*wg2[t*32+i];
    g2[b*128+t]=sg2[t]*(a+bg2[t])+tg2[t];
}

// ===================== h2 GEMM (K=384) + sigmoid ============================
__global__ void __launch_bounds__(256) h2_gemm(const float* __restrict__ H,
        const float* __restrict__ Wl2, const float* __restrict__ bl2,
        const float* __restrict__ sl2, const float* __restrict__ tl2,
        const float* __restrict__ g2, float* __restrict__ out){
    __shared__ float As[16*TW], Bs[16*68];
    int b=blockIdx.y, n0=blockIdx.x*64, tid=threadIdx.x;
    const float* Hb = H + ((size_t)b*NNp+n0)*384;
    int tr=tid>>4, tc=tid&15, r0=tr*4, c0=tc*2;
    ull acc[8][2];
#pragma unroll
    for(int i=0;i<8;i++){ acc[i][0]=0ULL; acc[i][1]=0ULL; }
    for (int kk=0; kk<384; kk+=16){
        for (int i=tid;i<512;i+=256){
            int m=i>>2, k4=(i&3)*4;
            float4 v = *(const float4*)(Wl2 + m*384 + kk + k4);
            As[(k4+0)*TW+m]=v.x; As[(k4+1)*TW+m]=v.y; As[(k4+2)*TW+m]=v.z; As[(k4+3)*TW+m]=v.w;
        }
        {
            int i=tid;
            int n=i>>2, k4=(i&3)*4;
            float4 v = *(const float4*)(Hb + (size_t)n*384 + kk + k4);
            Bs[(k4+0)*68+n]=v.x; Bs[(k4+1)*68+n]=v.y; Bs[(k4+2)*68+n]=v.z; Bs[(k4+3)*68+n]=v.w;
        }
        __syncthreads();
#pragma unroll
        for (int k=0;k<16;k++){
            const float* ar = As + k*TW; const float* br = Bs + k*68;
            float4 a0 = *(const float4*)(ar+r0);
            float4 a1 = *(const float4*)(ar+r0+64);
            ull b0 = *(const ull*)(br+c0);
            ull b1 = *(const ull*)(br+c0+32);
            ull av[8]={pack2(a0.x),pack2(a0.y),pack2(a0.z),pack2(a0.w),
                       pack2(a1.x),pack2(a1.y),pack2(a1.z),pack2(a1.w)};
#pragma unroll
            for (int i=0;i<8;i++){ fma2(acc[i][0],av[i],b0); fma2(acc[i][1],av[i],b1); }
        }
        __syncthreads();
    }
#pragma unroll
    for (int i=0;i<8;i++){
        int p=(i<4)? r0+i : r0+60+i;
        float bb=bl2[p], ss=sl2[p], tt=tl2[p], gg=g2[b*128+p];
        float* orow = out + ((size_t)b*CC+p)*NNp + n0;
#pragma unroll
        for (int j=0;j<2;j++){
            int cj=c0+j*32;
            float2 v=unp(acc[i][j]);
            float l0=fmaxf(ss*(v.x+bb)+tt,0.f);
            float l1=fmaxf(ss*(v.y+bb)+tt,0.f);
            float2 o;
            o.x = 1.f/(1.f+__expf(-(gg+l0)));
            o.y = 1.f/(1.f+__expf(-(gg+l1)));
            *(float2*)(orow+cj)=o;
        }
    }
}

extern "C" void kernel_launch(void* const* d_in, const int* in_sizes, int n_in,
                              void* d_out, int out_size){
    const float* x    = (const float*)d_in[0];
    const float* w_be = (const float*)d_in[1];
    const float* b_be = (const float*)d_in[2];
    const float* s_be = (const float*)d_in[3];
    const float* t_be = (const float*)d_in[4];
    const float* w_kn = (const float*)d_in[5];
    const float* b_kn = (const float*)d_in[6];
    const float* s_kn = (const float*)d_in[7];
    const float* t_kn = (const float*)d_in[8];
    const float* w_g1 = (const float*)d_in[9];
    const float* b_g1 = (const float*)d_in[10];
    const float* s_g1 = (const float*)d_in[11];
    const float* t_g1 = (const float*)d_in[12];
    const float* w_g2 = (const float*)d_in[13];
    const float* b_g2 = (const float*)d_in[14];
    const float* s_g2 = (const float*)d_in[15];
    const float* t_g2 = (const float*)d_in[16];
    const float* w_l1 = (const float*)d_in[17];
    const float* b_l1 = (const float*)d_in[18];
    const float* s_l1 = (const float*)d_in[19];
    const float* t_l1 = (const float*)d_in[20];
    const float* w_l2 = (const float*)d_in[21];
    const float* b_l2 = (const float*)d_in[22];
    const float* s_l2 = (const float*)d_in[23];
    const float* t_l2 = (const float*)d_in[24];
    float* out = (float*)d_out;

    float *x1, *xf, *sq, *G, *PC, *H, *g0, *g2, *W4, *Wl2; int *idx;
    cudaGetSymbolAddress((void**)&x1, g_x1);
    cudaGetSymbolAddress((void**)&xf, g_xf);
    cudaGetSymbolAddress((void**)&sq, g_sq);
    cudaGetSymbolAddress((void**)&idx, g_idx);
    cudaGetSymbolAddress((void**)&G, g_G);
    cudaGetSymbolAddress((void**)&PC, g_PC);
    cudaGetSymbolAddress((void**)&H, g_h);
    cudaGetSymbolAddress((void**)&W4, g_W4);
    cudaGetSymbolAddress((void**)&Wl2, g_Wl2);
    cudaGetSymbolAddress((void**)&g0, g_g0);
    cudaGetSymbolAddress((void**)&g2, g_g2);

    const int ks_smem = 2*128*KS_TW*4;              // 135168 B
    cudaFuncSetAttribute(knn_sym, cudaFuncAttributeMaxDynamicSharedMemorySize, ks_smem);

    // main stream: pw1, pw2(+sq), sym, select
    pw_gemm<<<dim3(64,BB),256>>>(x,  w_be, b_be, s_be, t_be, x1, nullptr);
    pw_gemm<<<dim3(64,BB),256>>>(x1, w_kn, b_kn, s_kn, t_kn, xf, sq);

    // fork side stream: prep, pc_gemm, mean, glob (independent of G/idx)
    cudaEventRecord(g_ef, 0);
    cudaStreamWaitEvent(g_s2, g_ef, 0);
    prep_kernel<<<256,256,0,g_s2>>>(w_l1, w_l2);
    pc_gemm<<<dim3(32,BB,4),256,0,g_s2>>>(xf, W4, PC);
    mean_kernel<<<dim3(128,BB),256,0,g_s2>>>(x1, g0);
    glob_kernel<<<BB,128,0,g_s2>>>(g0, w_g1,b_g1,s_g1,t_g1, w_g2,b_g2,s_g2,t_g2, g2);
    cudaEventRecord(g_es, g_s2);

    knn_sym<<<dim3(32,32,BB),512,ks_smem>>>(xf, sq, G);
    knn_select<<<dim3(256,BB),512>>>(G, idx);

    // join: gather needs idx (main) + PC (side); h2 needs H + g2 (side)
    cudaStreamWaitEvent(0, g_es, 0);
    gather_kernel<<<dim3(512,BB),256>>>(PC, idx, b_l1, s_l1, t_l1, H);
    h2_gemm<<<dim3(64,BB),256>>>(H, Wl2, b_l2, s_l2, t_l2, g2, out);
}